// round 11
// baseline (speedup 1.0000x reference)
#include <cuda_runtime.h>
#include <cuda_bf16.h>
#include <math.h>

#define TT    2048   // tokens (B*S)
#define DD    1024   // model dim
#define HH    16     // heads
#define HDIM  64     // head dim
#define NEXP  16     // experts
#define TOPK  2
#define EDIM  512    // expert dim
#define DSH   2048   // shared expert dim
#define QKV3  3072

// ---------------- scratch (device globals; no allocations) ----------------
constexpr size_t SZ_XN  = (size_t)TT * DD;
constexpr size_t OFF_XN  = 0;
constexpr size_t OFF_QKV = OFF_XN  + SZ_XN;
constexpr size_t OFF_AO  = OFF_QKV + (size_t)TT * QKV3;
constexpr size_t OFF_XFI = OFF_AO  + SZ_XN;
constexpr size_t OFF_XFN = OFF_XFI + SZ_XN;
constexpr size_t OFF_SC  = OFF_XFN + SZ_XN;
constexpr size_t OFF_G   = OFF_SC  + (size_t)TT * TOPK;
constexpr size_t OFF_YP  = OFF_G   + (size_t)TT * TOPK * EDIM;
constexpr size_t OFF_YC  = OFF_YP  + (size_t)TT * TOPK * DD;
constexpr size_t OFF_GT  = OFF_YC  + SZ_XN;
constexpr size_t OFF_YS  = OFF_GT  + (size_t)TT * DSH;
constexpr size_t TOTF    = OFF_YS  + SZ_XN;

__device__ float g_bufF[TOTF];

constexpr int IOFF_CNT  = 0;
constexpr int IOFF_OFFS = 16;
constexpr int IOFF_CUR  = 33;
constexpr int IOFF_PERM = 64;
constexpr int IOFF_SLOT = 64 + TT*TOPK;
constexpr int TOTI      = 64 + 2*TT*TOPK;
__device__ int g_bufI[TOTI];

// ---------------- tf32 mma helpers ----------------
__device__ __forceinline__ unsigned f2tf32(float x) {
    unsigned u; asm("cvt.rna.tf32.f32 %0, %1;" : "=r"(u) : "f"(x)); return u;
}
__device__ __forceinline__ void mma8(float* c, const unsigned* a, const unsigned* b) {
    asm volatile("mma.sync.aligned.m16n8k8.row.col.f32.tf32.tf32.f32 "
        "{%0,%1,%2,%3},{%4,%5,%6,%7},{%8,%9},{%0,%1,%2,%3};"
        : "+f"(c[0]), "+f"(c[1]), "+f"(c[2]), "+f"(c[3])
        : "r"(a[0]), "r"(a[1]), "r"(a[2]), "r"(a[3]), "r"(b[0]), "r"(b[1]));
}
// 16B cp.async with zero-fill when invalid
__device__ __forceinline__ void cpa16(float* dst, const float* src, bool v) {
    unsigned d = (unsigned)__cvta_generic_to_shared(dst);
    int sz = v ? 16 : 0;
    asm volatile("cp.async.cg.shared.global [%0], [%1], 16, %2;" :: "r"(d), "l"(src), "r"(sz));
}
#define CPA_COMMIT() asm volatile("cp.async.commit_group;")
#define CPA_WAIT1()  asm volatile("cp.async.wait_group 1;")
#define CPA_WAIT0()  asm volatile("cp.async.wait_group 0;")

// ---------------- rmsnorm ----------------
__global__ void rmsnorm_kernel(const float* __restrict__ x, const float* __restrict__ w,
                               float* __restrict__ o) {
    int t = blockIdx.x;
    const float* xr = x + (size_t)t * DD;
    float v[4]; float s = 0.f;
    #pragma unroll
    for (int i = 0; i < 4; i++) { v[i] = xr[threadIdx.x + i*256]; s += v[i]*v[i]; }
    __shared__ float red[8];
    #pragma unroll
    for (int off = 16; off > 0; off >>= 1) s += __shfl_xor_sync(0xffffffffu, s, off);
    if ((threadIdx.x & 31) == 0) red[threadIdx.x >> 5] = s;
    __syncthreads();
    if (threadIdx.x == 0) {
        float tot = 0.f;
        #pragma unroll
        for (int i = 0; i < 8; i++) tot += red[i];
        red[0] = tot;
    }
    __syncthreads();
    float sc = rsqrtf(red[0] / (float)DD + 1e-5f);
    #pragma unroll
    for (int i = 0; i < 4; i++) {
        int d = threadIdx.x + i*256;
        o[(size_t)t*DD + d] = v[i] * sc * w[d];
    }
}

// =============== tf32 NT GEMM (cp.async double-buffer) ===================
// C[M,N] = A[M,K] @ B[N,K]^T (+R). BM=128 BN=128 BK=32, 256 thr, 8 warps
// 2(M) x 4(N), warp tile 64x32. Smem holds raw fp32; tf32 cvt on frag load.
#define GTW (128*36)   // words per stage per operand

__device__ __forceinline__ void gemm_nt_body_ca(
        float* smx, const float* __restrict__ A, const float* __restrict__ B,
        const float* __restrict__ R, float* __restrict__ C,
        int M, int N, int K, int row0, int col0) {
    float* sA[2] = { smx, smx + GTW };
    float* sB[2] = { smx + 2*GTW, smx + 3*GTW };
    const int tid = threadIdx.x;
    const int lane = tid & 31, w = tid >> 5;
    const int g = lane >> 2, tg = lane & 3;
    const int wm = (w & 1) * 64, wn = (w >> 1) * 32;
    const int ar = tid >> 3, ac = (tid & 7) * 4;

    const float* Ap[4]; bool va[4];
    #pragma unroll
    for (int p = 0; p < 4; p++) {
        int r = row0 + p*32 + ar;
        va[p] = r < M;
        Ap[p] = A + (size_t)(va[p] ? r : 0) * K + ac;
    }
    const float* Bp[4];
    #pragma unroll
    for (int p = 0; p < 4; p++)
        Bp[p] = B + (size_t)(col0 + p*32 + ar) * K + ac;

    // stage 0
    #pragma unroll
    for (int p = 0; p < 4; p++) {
        cpa16(sA[0] + (p*32+ar)*36 + ac, Ap[p], va[p]);
        cpa16(sB[0] + (p*32+ar)*36 + ac, Bp[p], true);
    }
    CPA_COMMIT();

    float acc[4][4][4] = {};
    const int nk = K / 32;
    for (int kt = 0; kt < nk; kt++) {
        const int st = kt & 1;
        const bool nxt = (kt + 1) < nk;
        if (nxt) {
            const int k1 = (kt + 1) * 32;
            #pragma unroll
            for (int p = 0; p < 4; p++) {
                cpa16(sA[st^1] + (p*32+ar)*36 + ac, Ap[p] + k1, va[p]);
                cpa16(sB[st^1] + (p*32+ar)*36 + ac, Bp[p] + k1, true);
            }
            CPA_COMMIT();
            CPA_WAIT1();
        } else {
            CPA_WAIT0();
        }
        __syncthreads();
        const float* cA = sA[st];
        const float* cB = sB[st];
        #pragma unroll
        for (int ks = 0; ks < 4; ks++) {
            const int kb = ks*8;
            unsigned af[4][4], bf[4][2];
            #pragma unroll
            for (int i = 0; i < 4; i++) {
                af[i][0] = f2tf32(cA[(wm+i*16+g  )*36 + kb+tg]);
                af[i][1] = f2tf32(cA[(wm+i*16+8+g)*36 + kb+tg]);
                af[i][2] = f2tf32(cA[(wm+i*16+g  )*36 + kb+tg+4]);
                af[i][3] = f2tf32(cA[(wm+i*16+8+g)*36 + kb+tg+4]);
            }
            #pragma unroll
            for (int j = 0; j < 4; j++) {
                bf[j][0] = f2tf32(cB[(wn+j*8+g)*36 + kb+tg]);
                bf[j][1] = f2tf32(cB[(wn+j*8+g)*36 + kb+tg+4]);
            }
            #pragma unroll
            for (int i = 0; i < 4; i++)
                #pragma unroll
                for (int j = 0; j < 4; j++)
                    mma8(acc[i][j], af[i], bf[j]);
        }
        __syncthreads();
    }

    #pragma unroll
    for (int i = 0; i < 4; i++) {
        #pragma unroll
        for (int j = 0; j < 4; j++) {
            int r0 = row0 + wm + i*16 + g;
            int cc = col0 + wn + j*8 + tg*2;
            if (r0 < M) {
                size_t x = (size_t)r0*N + cc;
                float v0 = acc[i][j][0], v1 = acc[i][j][1];
                if (R) { v0 += R[x]; v1 += R[x+1]; }
                C[x] = v0; C[x+1] = v1;
            }
            int r1 = r0 + 8;
            if (r1 < M) {
                size_t x = (size_t)r1*N + cc;
                float v2 = acc[i][j][2], v3 = acc[i][j][3];
                if (R) { v2 += R[x]; v3 += R[x+1]; }
                C[x] = v2; C[x+1] = v3;
            }
        }
    }
}

constexpr int GEMM_SMEM = 4 * GTW * (int)sizeof(float);   // 73728 B

__global__ __launch_bounds__(256) void gemm_tf32_nt(
        const float* __restrict__ A, const float* __restrict__ B,
        const float* __restrict__ R, float* __restrict__ C, int M, int N, int K) {
    extern __shared__ float smx[];
    gemm_nt_body_ca(smx, A, B, R, C, M, N, K, blockIdx.y * 128, blockIdx.x * 128);
}

// =============== shared expert up + SiLU gate (dual-B, cp.async) ==========
// gt[T, DSH] = silu(x@B[0:DSH]^T) * (x@B[DSH:2DSH]^T). BM=128 BN=64 BK=32.
// 8 warps: 4(M) x 2(N), warp tile 32x32.
#define HBW (64*36)    // words per stage for each B operand
__global__ __launch_bounds__(256) void shared_up_gate_tf32(
        const float* __restrict__ A, const float* __restrict__ B,
        float* __restrict__ gt) {
    extern __shared__ float smx[];
    float* sA[2]  = { smx,           smx + GTW };
    float* sB1[2] = { smx + 2*GTW,          smx + 2*GTW + HBW };
    float* sB2[2] = { smx + 2*GTW + 2*HBW,  smx + 2*GTW + 3*HBW };
    const int row0 = blockIdx.y * 128, col0 = blockIdx.x * 64;
    const int tid = threadIdx.x;
    const int lane = tid & 31, w = tid >> 5;
    const int g = lane >> 2, tg = lane & 3;
    const int wm = (w & 3) * 32, wn = (w >> 2) * 32;
    const int ar = tid >> 3, ac = (tid & 7) * 4;

    const float* Ap[4];
    #pragma unroll
    for (int p = 0; p < 4; p++)
        Ap[p] = A + (size_t)(row0 + p*32 + ar) * DD + ac;
    const float* B1p[2]; const float* B2p[2];
    #pragma unroll
    for (int p = 0; p < 2; p++) {
        B1p[p] = B + (size_t)(col0 + p*32 + ar) * DD + ac;
        B2p[p] = B + (size_t)(DSH + col0 + p*32 + ar) * DD + ac;
    }

    #pragma unroll
    for (int p = 0; p < 4; p++) cpa16(sA[0] + (p*32+ar)*36 + ac, Ap[p], true);
    #pragma unroll
    for (int p = 0; p < 2; p++) {
        cpa16(sB1[0] + (p*32+ar)*36 + ac, B1p[p], true);
        cpa16(sB2[0] + (p*32+ar)*36 + ac, B2p[p], true);
    }
    CPA_COMMIT();

    float acc1[2][4][4] = {}, acc2[2][4][4] = {};
    const int nk = DD / 32;
    for (int kt = 0; kt < nk; kt++) {
        const int st = kt & 1;
        const bool nxt = (kt + 1) < nk;
        if (nxt) {
            const int k1 = (kt + 1) * 32;
            #pragma unroll
            for (int p = 0; p < 4; p++) cpa16(sA[st^1] + (p*32+ar)*36 + ac, Ap[p] + k1, true);
            #pragma unroll
            for (int p = 0; p < 2; p++) {
                cpa16(sB1[st^1] + (p*32+ar)*36 + ac, B1p[p] + k1, true);
                cpa16(sB2[st^1] + (p*32+ar)*36 + ac, B2p[p] + k1, true);
            }
            CPA_COMMIT();
            CPA_WAIT1();
        } else {
            CPA_WAIT0();
        }
        __syncthreads();
        const float* cA = sA[st];
        const float* c1 = sB1[st];
        const float* c2 = sB2[st];
        #pragma unroll
        for (int ks = 0; ks < 4; ks++) {
            const int kb = ks*8;
            unsigned af[2][4], bf1[4][2], bf2[4][2];
            #pragma unroll
            for (int i = 0; i < 2; i++) {
                af[i][0] = f2tf32(cA[(wm+i*16+g  )*36 + kb+tg]);
                af[i][1] = f2tf32(cA[(wm+i*16+8+g)*36 + kb+tg]);
                af[i][2] = f2tf32(cA[(wm+i*16+g  )*36 + kb+tg+4]);
                af[i][3] = f2tf32(cA[(wm+i*16+8+g)*36 + kb+tg+4]);
            }
            #pragma unroll
            for (int j = 0; j < 4; j++) {
                bf1[j][0] = f2tf32(c1[(wn+j*8+g)*36 + kb+tg]);
                bf1[j][1] = f2tf32(c1[(wn+j*8+g)*36 + kb+tg+4]);
                bf2[j][0] = f2tf32(c2[(wn+j*8+g)*36 + kb+tg]);
                bf2[j][1] = f2tf32(c2[(wn+j*8+g)*36 + kb+tg+4]);
            }
            #pragma unroll
            for (int i = 0; i < 2; i++)
                #pragma unroll
                for (int j = 0; j < 4; j++) {
                    mma8(acc1[i][j], af[i], bf1[j]);
                    mma8(acc2[i][j], af[i], bf2[j]);
                }
        }
        __syncthreads();
    }

    #pragma unroll
    for (int i = 0; i < 2; i++) {
        #pragma unroll
        for (int j = 0; j < 4; j++) {
            int r0 = row0 + wm + i*16 + g;
            int cc = col0 + wn + j*8 + tg*2;
            #pragma unroll
            for (int half = 0; half < 2; half++) {
                int r = r0 + half*8;
                float h1a = acc1[i][j][half*2+0], h2a = acc2[i][j][half*2+0];
                float h1b = acc1[i][j][half*2+1], h2b = acc2[i][j][half*2+1];
                float sa = 1.f / (1.f + __expf(-h1a));
                float sb = 1.f / (1.f + __expf(-h1b));
                size_t x = (size_t)r * DSH + cc;
                gt[x]   = h1a * sa * h2a;
                gt[x+1] = h1b * sb * h2b;
            }
        }
    }
}
constexpr int SUG_SMEM = (2*GTW + 4*HBW) * (int)sizeof(float);  // 73728 B

// ---------------- RoPE (in-place on q,k within qkv buffer) ----------------
__global__ void rope_kernel(float* __restrict__ qkv) {
    int idx = blockIdx.x * blockDim.x + threadIdx.x;
    const int total = 2 * TT * HH * 32;
    if (idx >= total) return;
    int which = idx / (TT * HH * 32);
    int rem   = idx % (TT * HH * 32);
    int t = rem / (HH * 32);
    int r2 = rem % (HH * 32);
    int h = r2 >> 5, i = r2 & 31;
    size_t base = (size_t)t * QKV3 + (size_t)which * DD + h * HDIM;
    float invf = (float)exp(-9.210340371976184 * ((double)i / 32.0));
    float fr = (float)t * invf;
    float c = (float)cos((double)fr);
    float s = (float)sin((double)fr);
    float x1 = qkv[base + i];
    float x2 = qkv[base + 32 + i];
    qkv[base + i]      =  x1 * c + x2 * s;
    qkv[base + 32 + i] = -x1 * s + x2 * c;
}

// =============== flash attention v3: 64q CTAs for occupancy ==============
// 64q x 64k tiles, 128 threads = 4 warps, warp w owns q rows [16w,16w+16).
// Register softmax; P stays in registers (quad-shuffle frag conversion).
#define KSTR 68
#define VSTR 72
__global__ __launch_bounds__(128) void attn_kernel(const float* __restrict__ qkv,
                                                   float* __restrict__ o) {
    __shared__ unsigned sm[64*KSTR + 64*VSTR];
    unsigned* Ks = sm;
    unsigned* Vs = sm + 64*KSTR;

    const int qb = gridDim.x - 1 - blockIdx.x;   // heavy blocks first
    const int h = blockIdx.y;
    const int tid = threadIdx.x;
    const int lane = tid & 31, w = tid >> 5;
    const int g = lane >> 2, tg = lane & 3;
    const bool odd = tg & 1;
    const int s0 = tg >> 1, s1 = 2 + (tg >> 1);

    { // stage Q tile [64][64] as tf32 into Ks area
        int qi = tid >> 1, d0 = (tid & 1) * 32;
        const float* src = qkv + (size_t)(qb*64 + qi) * QKV3 + h * HDIM + d0;
        #pragma unroll
        for (int c = 0; c < 32; c += 4) {
            float4 v = *(const float4*)(src + c);
            sm[qi*KSTR + d0+c+0] = f2tf32(v.x); sm[qi*KSTR + d0+c+1] = f2tf32(v.y);
            sm[qi*KSTR + d0+c+2] = f2tf32(v.z); sm[qi*KSTR + d0+c+3] = f2tf32(v.w);
        }
    }
    __syncthreads();
    unsigned aq[8][4];
    {
        int r0 = 16*w + g;
        #pragma unroll
        for (int kk = 0; kk < 8; kk++) {
            aq[kk][0] = sm[(r0  )*KSTR + 8*kk + tg];
            aq[kk][1] = sm[(r0+8)*KSTR + 8*kk + tg];
            aq[kk][2] = sm[(r0  )*KSTR + 8*kk + tg + 4];
            aq[kk][3] = sm[(r0+8)*KSTR + 8*kk + tg + 4];
        }
    }
    __syncthreads();

    float m0 = -INFINITY, m1 = -INFINITY, l0 = 0.f, l1 = 0.f;
    float acco[8][4] = {};
    const int qg0 = qb*64 + 16*w + g;
    const int qg1 = qg0 + 8;

    for (int kb = 0; kb <= qb; kb++) {
        { // load K,V tiles as tf32
            int ki = tid >> 1, d0 = (tid & 1) * 32;
            const float* kp = qkv + (size_t)(kb*64 + ki) * QKV3 + DD   + h*HDIM + d0;
            const float* vp = qkv + (size_t)(kb*64 + ki) * QKV3 + 2*DD + h*HDIM + d0;
            #pragma unroll
            for (int c = 0; c < 32; c += 4) {
                float4 kv = *(const float4*)(kp + c);
                Ks[ki*KSTR + d0+c+0]=f2tf32(kv.x); Ks[ki*KSTR + d0+c+1]=f2tf32(kv.y);
                Ks[ki*KSTR + d0+c+2]=f2tf32(kv.z); Ks[ki*KSTR + d0+c+3]=f2tf32(kv.w);
                float4 vv = *(const float4*)(vp + c);
                Vs[ki*VSTR + d0+c+0]=f2tf32(vv.x); Vs[ki*VSTR + d0+c+1]=f2tf32(vv.y);
                Vs[ki*VSTR + d0+c+2]=f2tf32(vv.z); Vs[ki*VSTR + d0+c+3]=f2tf32(vv.w);
            }
        }
        __syncthreads();

        // S = Q @ K^T : warp tile 16 rows x 64 cols
        float sf[8][4] = {};
        #pragma unroll
        for (int kk = 0; kk < 8; kk++) {
            #pragma unroll
            for (int j = 0; j < 8; j++) {
                unsigned b[2] = { Ks[(8*j+g)*KSTR + 8*kk + tg],
                                  Ks[(8*j+g)*KSTR + 8*kk + tg + 4] };
                mma8(sf[j], aq[kk], b);
            }
        }
        // scale + causal mask + register softmax
        float vmax0 = -1e30f, vmax1 = -1e30f;
        #pragma unroll
        for (int j = 0; j < 8; j++) {
            int kg = kb*64 + 8*j + 2*tg;
            sf[j][0] = (kg   > qg0) ? -1e30f : sf[j][0]*0.125f;
            sf[j][1] = (kg+1 > qg0) ? -1e30f : sf[j][1]*0.125f;
            sf[j][2] = (kg   > qg1) ? -1e30f : sf[j][2]*0.125f;
            sf[j][3] = (kg+1 > qg1) ? -1e30f : sf[j][3]*0.125f;
            vmax0 = fmaxf(vmax0, fmaxf(sf[j][0], sf[j][1]));
            vmax1 = fmaxf(vmax1, fmaxf(sf[j][2], sf[j][3]));
        }
        vmax0 = fmaxf(vmax0, __shfl_xor_sync(0xffffffffu, vmax0, 1));
        vmax0 = fmaxf(vmax0, __shfl_xor_sync(0xffffffffu, vmax0, 2));
        vmax1 = fmaxf(vmax1, __shfl_xor_sync(0xffffffffu, vmax1, 1));
        vmax1 = fmaxf(vmax1, __shfl_xor_sync(0xffffffffu, vmax1, 2));
        float mn0 = fmaxf(m0, vmax0), mn1 = fmaxf(m1, vmax1);
        float al0 = __expf(m0 - mn0), al1 = __expf(m1 - mn1);
        float ps0 = 0.f, ps1 = 0.f;
        #pragma unroll
        for (int j = 0; j < 8; j++) {
            sf[j][0] = __expf(sf[j][0] - mn0); ps0 += sf[j][0];
            sf[j][1] = __expf(sf[j][1] - mn0); ps0 += sf[j][1];
            sf[j][2] = __expf(sf[j][2] - mn1); ps1 += sf[j][2];
            sf[j][3] = __expf(sf[j][3] - mn1); ps1 += sf[j][3];
        }
        ps0 += __shfl_xor_sync(0xffffffffu, ps0, 1);
        ps0 += __shfl_xor_sync(0xffffffffu, ps0, 2);
        ps1 += __shfl_xor_sync(0xffffffffu, ps1, 1);
        ps1 += __shfl_xor_sync(0xffffffffu, ps1, 2);
        l0 = l0*al0 + ps0; l1 = l1*al1 + ps1;
        m0 = mn0; m1 = mn1;
        #pragma unroll
        for (int jd = 0; jd < 8; jd++) {
            acco[jd][0] *= al0; acco[jd][1] *= al0;
            acco[jd][2] *= al1; acco[jd][3] *= al1;
        }
        // O += P @ V : A-frags built from C-frags via quad shuffles
        #pragma unroll
        for (int j = 0; j < 8; j++) {
            float q00 = __shfl_sync(0xffffffffu, sf[j][0], s0, 4);
            float q01 = __shfl_sync(0xffffffffu, sf[j][1], s0, 4);
            float q10 = __shfl_sync(0xffffffffu, sf[j][2], s0, 4);
            float q11 = __shfl_sync(0xffffffffu, sf[j][3], s0, 4);
            float r00 = __shfl_sync(0xffffffffu, sf[j][0], s1, 4);
            float r01 = __shfl_sync(0xffffffffu, sf[j][1], s1, 4);
            float r10 = __shfl_sync(0xffffffffu, sf[j][2], s1, 4);
            float r11 = __shfl_sync(0xffffffffu, sf[j][3], s1, 4);
            unsigned a[4];
            a[0] = f2tf32(odd ? q01 : q00);
            a[1] = f2tf32(odd ? q11 : q10);
            a[2] = f2tf32(odd ? r01 : r00);
            a[3] = f2tf32(odd ? r11 : r10);
            #pragma unroll
            for (int jd = 0; jd < 8; jd++) {
                unsigned b[2] = { Vs[(8*j+tg  )*VSTR + 8*jd + g],
                                  Vs[(8*j+tg+4)*VSTR + 8*jd + g] };
                mma8(acco[jd], a, b);
            }
        }
        __syncthreads();
    }

    float i0 = 1.f / l0, i1 = 1.f / l1;
    #pragma unroll
    for (int jd = 0; jd < 8; jd++) {
        int col = h*HDIM + 8*jd + 2*tg;
        o[(size_t)qg0*DD + col  ] = acco[jd][0]*i0;
        o[(size_t)qg0*DD + col+1] = acco[jd][1]*i0;
        o[(size_t)qg1*DD + col  ] = acco[jd][2]*i1;
        o[(size_t)qg1*DD + col+1] = acco[jd][3]*i1;
    }
}

// ---------------- router ----------------
__global__ void router_kernel(const float* __restrict__ xffn, const float* __restrict__ mk,
                              const float* __restrict__ bias, const int* __restrict__ indices,
                              const float* __restrict__ values, float* __restrict__ scores) {
    int t = blockIdx.x;
    __shared__ float red[128 * NEXP];
    float partial[NEXP];
    #pragma unroll
    for (int e = 0; e < NEXP; e++) partial[e] = 0.f;
    for (int d = threadIdx.x; d < DD; d += 128) {
        float xv = xffn[(size_t)t*DD + d];
        const float* mrow = mk + (size_t)d * NEXP;
        #pragma unroll
        for (int e = 0; e < NEXP; e++) partial[e] += xv * mrow[e];
    }
    #pragma unroll
    for (int e = 0; e < NEXP; e++) red[threadIdx.x*NEXP + e] = partial[e];
    __syncthreads();
    for (int s = 64; s >= 1; s >>= 1) {
        if (threadIdx.x < s)
            #pragma unroll
            for (int e = 0; e < NEXP; e++)
                red[threadIdx.x*NEXP + e] += red[(threadIdx.x+s)*NEXP + e];
        __syncthreads();
    }
    if (threadIdx.x == 0) {
        int i0 = indices[t*2+0], i1 = indices[t*2+1];
        float v0 = values[t*2+0] + red[i0] + bias[i0];
        float v1 = values[t*2+1] + red[i1] + bias[i1];
        float m = fmaxf(v0, v1);
        float e0 = __expf(v0 - m), e1 = __expf(v1 - m);
        float inv = 1.f / (e0 + e1);
        scores[t*2+0] = e0 * inv;
        scores[t*2+1] = e1 * inv;
    }
}

// ---------------- routing build ----------------
__global__ void route_init(int* counts) { if (threadIdx.x < NEXP) counts[threadIdx.x] = 0; }
__global__ void route_count(const int* __restrict__ indices, int* counts) {
    int i = blockIdx.x * blockDim.x + threadIdx.x;
    if (i < TT*TOPK) atomicAdd(&counts[indices[i]], 1);
}
__global__ void route_scan(const int* __restrict__ counts, int* offsets, int* cursor) {
    if (threadIdx.x == 0) {
        int off = 0;
        for (int e = 0; e < NEXP; e++) { offsets[e] = off; cursor[e] = off; off += counts[e]; }
        offsets[NEXP] = off;
    }
}
__global__ void route_scatter(const int* __restrict__ indices, int* cursor,
                              int* __restrict__ perm, int* __restrict__ slotpos) {
    int i = blockIdx.x * blockDim.x + threadIdx.x;
    if (i < TT*TOPK) {
        int e = indices[i];
        int p = atomicAdd(&cursor[e], 1);
        perm[p] = i >> 1;
        slotpos[i] = p;
    }
}

// =============== expert up (tf32): g = silu(x@W1) * (x@W2), gathered A ====
__global__ __launch_bounds__(256) void expert_up_tf32(
        const float* __restrict__ xffn, const float* __restrict__ experts,
        const int* __restrict__ counts, const int* __restrict__ offsets,
        const int* __restrict__ perm, float* __restrict__ g_out) {
    const int e = blockIdx.z;
    const int M = counts[e];
    const int row0 = blockIdx.y * 64;
    if (row0 >= M) return;
    const int off = offsets[e];
    const float* B1 = experts + (size_t)e * DD * EDIM;
    const float* B2 = experts + ((size_t)NEXP + e) * DD * EDIM;
    const int col0 = blockIdx.x * 64;

    __shared__ unsigned As[64][36];
    __shared__ unsigned B1s[32][72];
    __shared__ unsigned B2s[32][72];

    const int tid = threadIdx.x;
    const int lane = tid & 31, w = tid >> 5;
    const int g = lane >> 2, tg = lane & 3;
    const int wm = (w & 1) * 32, wn = (w >> 1) * 16;
    const int ar = tid >> 3, ac = (tid & 7) * 4;
    const int bkr = tid >> 4, bnc = (tid & 15) * 4;

    const float* Ap[2]; bool va[2];
    #pragma unroll
    for (int p = 0; p < 2; p++) {
        int r = row0 + p*32 + ar;
        va[p] = r < M;
        int tok = va[p] ? perm[off + r] : 0;
        Ap[p] = xffn + (size_t)tok * DD + ac;
    }
    const float* B1p[2]; const float* B2p[2];
    #pragma unroll
    for (int p = 0; p < 2; p++) {
        B1p[p] = B1 + (size_t)(p*16 + bkr) * EDIM + col0 + bnc;
        B2p[p] = B2 + (size_t)(p*16 + bkr) * EDIM + col0 + bnc;
    }

    #pragma unroll
    for (int p = 0; p < 2; p++) {
        float4 v = va[p] ? *(const float4*)(Ap[p]) : make_float4(0,0,0,0);
        As[p*32+ar][ac+0]=f2tf32(v.x); As[p*32+ar][ac+1]=f2tf32(v.y);
        As[p*32+ar][ac+2]=f2tf32(v.z); As[p*32+ar][ac+3]=f2tf32(v.w);
    }
    #pragma unroll
    for (int p = 0; p < 2; p++) {
        float4 v1 = *(const float4*)(B1p[p]);
        float4 v2 = *(const float4*)(B2p[p]);
        B1s[p*16+bkr][bnc+0]=f2tf32(v1.x); B1s[p*16+bkr][bnc+1]=f2tf32(v1.y);
        B1s[p*16+bkr][bnc+2]=f2tf32(v1.z); B1s[p*16+bkr][bnc+3]=f2tf32(v1.w);
        B2s[p*16+bkr][bnc+0]=f2tf32(v2.x); B2s[p*16+bkr][bnc+1]=f2tf32(v2.y);
        B2s[p*16+bkr][bnc+2]=f2tf32(v2.z); B2s[p*16+bkr][bnc+3]=f2tf32(v2.w);
    }
    __syncthreads();

    float acc1[2][2][4] = {}, acc2[2][2][4] = {};
    float4 pa[2], pb1[2], pb2[2];
    for (int k0 = 0; k0 < DD; k0 += 32) {
        bool nxt = (k0 + 32) < DD;
        if (nxt) {
            #pragma unroll
            for (int p = 0; p < 2; p++)
                pa[p] = va[p] ? *(const float4*)(Ap[p] + k0 + 32) : make_float4(0,0,0,0);
            #pragma unroll
            for (int p = 0; p < 2; p++) {
                pb1[p] = *(const float4*)(B1p[p] + (size_t)(k0 + 32) * EDIM);
                pb2[p] = *(const float4*)(B2p[p] + (size_t)(k0 + 32) * EDIM);
            }
        }
        #pragma unroll
        for (int ks = 0; ks < 4; ks++) {
            const int kb = ks*8;
            unsigned af[2][4], bf1[2][2], bf2[2][2];
            #pragma unroll
            for (int i = 0; i < 2; i++) {
                af[i][0] = As[wm+i*16+g  ][kb+tg];
                af[i][1] = As[wm+i*16+8+g][kb+tg];
                af[i][2] = As[wm+i*16+g  ][kb+tg+4];
                af[i][3] = As[wm+i*16+8+g][kb+tg+4];
            }
            #pragma unroll
            for (int j = 0; j < 2; j++) {
                bf1[j][0] = B1s[kb+tg  ][wn+j*8+g];
                bf1[j][1] = B1s[kb+tg+4][wn+j*8+g];
                bf2[j][0] = B2s[kb+tg  ][wn+j*8+g];
                bf2[j][1] = B2s[kb+tg+4][wn+j*8+g];
            }
            #pragma unroll
            for (int i = 0; i < 2; i++)
                #pragma unroll
                for (int j = 0; j < 2; j++) {
                    mma8(acc1[i][j], af[i], bf1[j]);
                    mma8(acc2[i][j], af[i], bf2[j]);
                }
        }
        __syncthreads();
        if (nxt) {
            #pragma unroll
            for (int p = 0; p < 2; p++) {
                As[p*32+ar][ac+0]=f2tf32(pa[p].x); As[p*32+ar][ac+1]=f2tf32(pa[p].y);
                As[p*32+ar][ac+2]=f2tf32(pa[p].z); As[p*32+ar][ac+3]=f2tf32(pa[p].w);
            }
            #pragma unroll
            for (int p = 0; p < 2; p++) {
                B1s[p*16+bkr][bnc+0]=f2tf32(pb1[p].x); B1s[p*16+bkr][bnc+1]=f2tf32(pb1[p].y);
                B1s[p*16+bkr][bnc+2]=f2tf32(pb1[p].z); B1s[p*16+bkr][bnc+3]=f2tf32(pb1[p].w);
                B2s[p*16+bkr][bnc+0]=f2tf32(pb2[p].x); B2s[p*16+bkr][bnc+1]=f2tf32(pb2[p].y);
                B2s[p*16+bkr][bnc+2]=f2tf32(pb2[p].z); B2s[p*16+bkr][bnc+3]=f2tf32(pb2[p].w);
            }
            __syncthreads();
        }
    }

    #pragma unroll
    for (int i = 0; i < 2; i++) {
        #pragma unroll
        for (int j = 0; j < 2; j++) {
            int r0 = row0 + wm + i*16 + g;
            int cc = col0 + wn + j*8 + tg*2;
            #pragma unroll
            for (int half = 0; half < 2; half++) {
                int r = r0 + half*8;
                if (r < M) {
                    float h1a = acc1[i][j][half*2+0], h2a = acc2[i][j][half*2+0];
                    float h1b = acc1[i][j][half*2+1], h2b = acc2[i][j][half*2+1];
                    float sa = 1.f / (1.f + __expf(-h1a));
                    float sb = 1.f / (1.f + __expf(-h1b));
                    size_t x = (size_t)(off + r) * EDIM + cc;
                    g_out[x]   = h1a * sa * h2a;
                    g_out[x+1] = h1b * sb * h2b;
                }
            }
        }
    }
}

// =============== expert down (tf32 NT, cp.async): yp = g @ W3^T ===========
__global__ __launch_bounds__(256) void expert_down_tf32(
        const float* __restrict__ gbuf, const float* __restrict__ experts,
        const int* __restrict__ counts, const int* __restrict__ offsets,
        float* __restrict__ yp) {
    const int e = blockIdx.z;
    const int M = counts[e];
    const int row0 = blockIdx.y * 128;
    if (row0 >= M) return;
    const int off = offsets[e];
    extern __shared__ float smx[];
    gemm_nt_body_ca(smx,
                 gbuf + (size_t)off * EDIM,
                 experts + (2*(size_t)NEXP + e) * DD * EDIM,
                 nullptr,
                 yp + (size_t)off * DD,
                 M, DD, EDIM, row0, blockIdx.x * 128);
}

// ---------------- combine experts (scores * yp) * coeff -------------------
__global__ void combine_kernel(const float* __restrict__ yp, const float* __restrict__ scores,
                               const int* __restrict__ slotpos, const float* __restrict__ coeff,
                               float* __restrict__ ycomb) {
    int t = blockIdx.x;
    float s0 = scores[t*2+0], s1 = scores[t*2+1];
    int p0 = slotpos[t*2+0], p1 = slotpos[t*2+1];
    const float* r0 = yp + (size_t)p0 * DD;
    const float* r1 = yp + (size_t)p1 * DD;
    #pragma unroll
    for (int i = 0; i < 4; i++) {
        int d = threadIdx.x + i*256;
        ycomb[(size_t)t*DD + d] = (s0*r0[d] + s1*r1[d]) * coeff[d];
    }
}

// ---------------- final: out = ycomb + rmsnorm(ysh)*w + x_ffn_input ------
__global__ void final_kernel(const float* __restrict__ ycomb, const float* __restrict__ ysh,
                             const float* __restrict__ shw, const float* __restrict__ xfi,
                             float* __restrict__ out) {
    int t = blockIdx.x;
    const float* yr = ysh + (size_t)t * DD;
    float v[4]; float s = 0.f;
    #pragma unroll
    for (int i = 0; i < 4; i++) { v[i] = yr[threadIdx.x + i*256]; s += v[i]*v[i]; }
    __shared__ float red[8];
    #pragma unroll
    for (int off = 16; off > 0; off >>= 1) s += __shfl_xor_sync(0xffffffffu, s, off);
    if ((threadIdx.x & 31) == 0) red[threadIdx.x >> 5] = s;
    __syncthreads();
    if (threadIdx.x == 0) {
        float tot = 0.f;
        #pragma unroll
        for (int i = 0; i < 8; i++) tot += red[i];
        red[0] = tot;
    }
    __syncthreads();
    float sc = rsqrtf(red[0] / (float)DD + 1e-5f);
    #pragma unroll
    for (int i = 0; i < 4; i++) {
        int d = threadIdx.x + i*256;
        size_t idx = (size_t)t*DD + d;
        out[idx] = ycomb[idx] + v[i]*sc*shw[d] + xfi[idx];
    }
}

// ---------------- launch ----------------
extern "C" void kernel_launch(void* const* d_in, const int* in_sizes, int n_in,
                              void* d_out, int out_size) {
    const float* x_input     = (const float*)d_in[0];
    const int*   indices     = (const int*)  d_in[1];
    const float* values      = (const float*)d_in[2];
    const float* attn_w      = (const float*)d_in[3];
    const float* attn_o_w    = (const float*)d_in[4];
    const float* attn_norm_w = (const float*)d_in[5];
    const float* ffn_norm_w  = (const float*)d_in[6];
    const float* ffn_experts = (const float*)d_in[7];
    const float* main_keys   = (const float*)d_in[8];
    const float* main_bias   = (const float*)d_in[9];
    const float* out_coeff   = (const float*)d_in[10];
    const float* ffn_up_w    = (const float*)d_in[11];
    const float* ffn_down_w  = (const float*)d_in[12];
    const float* shared_nw   = (const float*)d_in[13];
    float* out = (float*)d_out;

    float* bufF = nullptr; int* bufI = nullptr;
    cudaGetSymbolAddress((void**)&bufF, g_bufF);
    cudaGetSymbolAddress((void**)&bufI, g_bufI);

    float* xn   = bufF + OFF_XN;
    float* qkv  = bufF + OFF_QKV;
    float* ao   = bufF + OFF_AO;
    float* xfi  = bufF + OFF_XFI;
    float* xfn  = bufF + OFF_XFN;
    float* sc   = bufF + OFF_SC;
    float* gbuf = bufF + OFF_G;
    float* yp   = bufF + OFF_YP;
    float* yc   = bufF + OFF_YC;
    float* gt   = bufF + OFF_GT;
    float* ys   = bufF + OFF_YS;

    int* cnt  = bufI + IOFF_CNT;
    int* offs = bufI + IOFF_OFFS;
    int* cur  = bufI + IOFF_CUR;
    int* perm = bufI + IOFF_PERM;
    int* slot = bufI + IOFF_SLOT;

    cudaFuncSetAttribute(gemm_tf32_nt, cudaFuncAttributeMaxDynamicSharedMemorySize, GEMM_SMEM);
    cudaFuncSetAttribute(expert_down_tf32, cudaFuncAttributeMaxDynamicSharedMemorySize, GEMM_SMEM);
    cudaFuncSetAttribute(shared_up_gate_tf32, cudaFuncAttributeMaxDynamicSharedMemorySize, SUG_SMEM);

    // 1. attention pre-norm
    rmsnorm_kernel<<<TT, 256>>>(x_input, attn_norm_w, xn);
    // 2. QKV (tf32 tensor, cp.async pipeline)
    gemm_tf32_nt<<<dim3(QKV3/128, TT/128), 256, GEMM_SMEM>>>(xn, attn_w, nullptr, qkv, TT, QKV3, DD);
    // 3. RoPE on q,k
    rope_kernel<<<(2*TT*HH*32 + 255)/256, 256>>>(qkv);
    // 4. attention (tf32 tensor, 64q CTAs, register softmax)
    attn_kernel<<<dim3(TT/64, HH), 128>>>(qkv, ao);
    // 5. O proj + residual (tf32)
    gemm_tf32_nt<<<dim3(DD/128, TT/128), 256, GEMM_SMEM>>>(ao, attn_o_w, x_input, xfi, TT, DD, DD);
    // 6. ffn pre-norm
    rmsnorm_kernel<<<TT, 256>>>(xfi, ffn_norm_w, xfn);
    // 7. router scores
    router_kernel<<<TT, 128>>>(xfn, main_keys, main_bias, indices, values, sc);
    // 8. routing permutation
    route_init<<<1, 32>>>(cnt);
    route_count<<<(TT*TOPK + 255)/256, 256>>>(indices, cnt);
    route_scan<<<1, 32>>>(cnt, offs, cur);
    route_scatter<<<(TT*TOPK + 255)/256, 256>>>(indices, cur, perm, slot);
    // 9. expert up (tf32 dual GEMM + SiLU)
    expert_up_tf32<<<dim3(EDIM/64, (TT*TOPK)/64, NEXP), 256>>>(xfn, ffn_experts, cnt, offs, perm, gbuf);
    // 10. expert down (tf32, cp.async)
    expert_down_tf32<<<dim3(DD/128, (TT*TOPK)/128, NEXP), 256, GEMM_SMEM>>>(gbuf, ffn_experts, cnt, offs, yp);
    // 11. combine
    combine_kernel<<<TT, 256>>>(yp, sc, slot, out_coeff, yc);
    // 12. shared expert up + gate (fused dual-B tf32, cp.async)
    shared_up_gate_tf32<<<dim3(DSH/64, TT/128), 256, SUG_SMEM>>>(xfn, ffn_up_w, gt);
    // 13. shared expert down (tf32)
    gemm_tf32_nt<<<dim3(DD/128, TT/128), 256, GEMM_SMEM>>>(gt, ffn_down_w, nullptr, ys, TT, DD, DSH);
    // 14. final combine
    final_kernel<<<TT, 256>>>(yc, ys, shared_nw, xfi, out);
}

// round 12
// speedup vs baseline: 1.1094x; 1.1094x over previous
#include <cuda_runtime.h>
#include <cuda_bf16.h>
#include <math.h>

#define TT    2048   // tokens (B*S)
#define DD    1024   // model dim
#define HH    16     // heads
#define HDIM  64     // head dim
#define NEXP  16     // experts
#define TOPK  2
#define EDIM  512    // expert dim
#define DSH   2048   // shared expert dim
#define QKV3  3072

// ---------------- scratch (device globals; no allocations) ----------------
constexpr size_t SZ_XN  = (size_t)TT * DD;
constexpr size_t OFF_XN  = 0;
constexpr size_t OFF_QKV = OFF_XN  + SZ_XN;
constexpr size_t OFF_AO  = OFF_QKV + (size_t)TT * QKV3;
constexpr size_t OFF_XFI = OFF_AO  + SZ_XN;
constexpr size_t OFF_XFN = OFF_XFI + SZ_XN;
constexpr size_t OFF_SC  = OFF_XFN + SZ_XN;
constexpr size_t OFF_G   = OFF_SC  + (size_t)TT * TOPK;
constexpr size_t OFF_YP  = OFF_G   + (size_t)TT * TOPK * EDIM;
constexpr size_t OFF_YC  = OFF_YP  + (size_t)TT * TOPK * DD;
constexpr size_t OFF_GT  = OFF_YC  + SZ_XN;
constexpr size_t OFF_YS  = OFF_GT  + (size_t)TT * DSH;
constexpr size_t TOTF    = OFF_YS  + SZ_XN;

__device__ float g_bufF[TOTF];

constexpr int IOFF_CNT  = 0;
constexpr int IOFF_OFFS = 16;
constexpr int IOFF_CUR  = 33;
constexpr int IOFF_PERM = 64;
constexpr int IOFF_SLOT = 64 + TT*TOPK;
constexpr int TOTI      = 64 + 2*TT*TOPK;
__device__ int g_bufI[TOTI];

// ---------------- tf32 mma helpers ----------------
__device__ __forceinline__ unsigned f2tf32(float x) {
    unsigned u; asm("cvt.rna.tf32.f32 %0, %1;" : "=r"(u) : "f"(x)); return u;
}
__device__ __forceinline__ void mma8(float* c, const unsigned* a, const unsigned* b) {
    asm volatile("mma.sync.aligned.m16n8k8.row.col.f32.tf32.tf32.f32 "
        "{%0,%1,%2,%3},{%4,%5,%6,%7},{%8,%9},{%0,%1,%2,%3};"
        : "+f"(c[0]), "+f"(c[1]), "+f"(c[2]), "+f"(c[3])
        : "r"(a[0]), "r"(a[1]), "r"(a[2]), "r"(a[3]), "r"(b[0]), "r"(b[1]));
}
// 16B cp.async with zero-fill when invalid
__device__ __forceinline__ void cpa16(float* dst, const float* src, bool v) {
    unsigned d = (unsigned)__cvta_generic_to_shared(dst);
    int sz = v ? 16 : 0;
    asm volatile("cp.async.cg.shared.global [%0], [%1], 16, %2;" :: "r"(d), "l"(src), "r"(sz));
}
#define CPA_COMMIT() asm volatile("cp.async.commit_group;")
#define CPA_WAIT1()  asm volatile("cp.async.wait_group 1;")
#define CPA_WAIT0()  asm volatile("cp.async.wait_group 0;")

// ---------------- rmsnorm ----------------
__global__ void rmsnorm_kernel(const float* __restrict__ x, const float* __restrict__ w,
                               float* __restrict__ o) {
    int t = blockIdx.x;
    const float* xr = x + (size_t)t * DD;
    float v[4]; float s = 0.f;
    #pragma unroll
    for (int i = 0; i < 4; i++) { v[i] = xr[threadIdx.x + i*256]; s += v[i]*v[i]; }
    __shared__ float red[8];
    #pragma unroll
    for (int off = 16; off > 0; off >>= 1) s += __shfl_xor_sync(0xffffffffu, s, off);
    if ((threadIdx.x & 31) == 0) red[threadIdx.x >> 5] = s;
    __syncthreads();
    if (threadIdx.x == 0) {
        float tot = 0.f;
        #pragma unroll
        for (int i = 0; i < 8; i++) tot += red[i];
        red[0] = tot;
    }
    __syncthreads();
    float sc = rsqrtf(red[0] / (float)DD + 1e-5f);
    #pragma unroll
    for (int i = 0; i < 4; i++) {
        int d = threadIdx.x + i*256;
        o[(size_t)t*DD + d] = v[i] * sc * w[d];
    }
}

// =============== tf32 NT GEMM: C[M,N] = A[M,K] @ B[N,K]^T (+R) ===========
// BM=128 BN=128 BK=32, 256 threads (8 warps: 2 along M x 4 along N,
// each warp computes a 64x32 tile). Register-prefetch double buffering.
struct SmemNT {
    unsigned As[128][36];
    unsigned Bs[128][36];
};

__device__ __forceinline__ void gemm_nt_body(
        SmemNT& s, const float* __restrict__ A, const float* __restrict__ B,
        const float* __restrict__ R, float* __restrict__ C,
        int M, int N, int K, int row0, int col0) {
    const int tid = threadIdx.x;
    const int lane = tid & 31, w = tid >> 5;
    const int g = lane >> 2, tg = lane & 3;
    const int wm = (w & 1) * 64, wn = (w >> 1) * 32;
    const int ar = tid >> 3, ac = (tid & 7) * 4;

    const float* Ap[4]; bool va[4];
    #pragma unroll
    for (int p = 0; p < 4; p++) {
        int r = row0 + p*32 + ar;
        va[p] = r < M;
        Ap[p] = A + (size_t)(va[p] ? r : 0) * K + ac;
    }
    const float* Bp[4];
    #pragma unroll
    for (int p = 0; p < 4; p++)
        Bp[p] = B + (size_t)(col0 + p*32 + ar) * K + ac;

    #pragma unroll
    for (int p = 0; p < 4; p++) {
        float4 v = va[p] ? *(const float4*)(Ap[p]) : make_float4(0,0,0,0);
        s.As[p*32+ar][ac+0]=f2tf32(v.x); s.As[p*32+ar][ac+1]=f2tf32(v.y);
        s.As[p*32+ar][ac+2]=f2tf32(v.z); s.As[p*32+ar][ac+3]=f2tf32(v.w);
        float4 b = *(const float4*)(Bp[p]);
        s.Bs[p*32+ar][ac+0]=f2tf32(b.x); s.Bs[p*32+ar][ac+1]=f2tf32(b.y);
        s.Bs[p*32+ar][ac+2]=f2tf32(b.z); s.Bs[p*32+ar][ac+3]=f2tf32(b.w);
    }
    __syncthreads();

    float acc[4][4][4] = {};
    float4 pa[4], pb[4];
    for (int k0 = 0; k0 < K; k0 += 32) {
        bool nxt = (k0 + 32) < K;
        if (nxt) {
            #pragma unroll
            for (int p = 0; p < 4; p++) {
                pa[p] = va[p] ? *(const float4*)(Ap[p] + k0 + 32) : make_float4(0,0,0,0);
                pb[p] = *(const float4*)(Bp[p] + k0 + 32);
            }
        }
        #pragma unroll
        for (int ks = 0; ks < 4; ks++) {
            const int kb = ks*8;
            unsigned af[4][4], bf[4][2];
            #pragma unroll
            for (int i = 0; i < 4; i++) {
                af[i][0] = s.As[wm+i*16+g  ][kb+tg];
                af[i][1] = s.As[wm+i*16+8+g][kb+tg];
                af[i][2] = s.As[wm+i*16+g  ][kb+tg+4];
                af[i][3] = s.As[wm+i*16+8+g][kb+tg+4];
            }
            #pragma unroll
            for (int j = 0; j < 4; j++) {
                bf[j][0] = s.Bs[wn+j*8+g][kb+tg];
                bf[j][1] = s.Bs[wn+j*8+g][kb+tg+4];
            }
            #pragma unroll
            for (int i = 0; i < 4; i++)
                #pragma unroll
                for (int j = 0; j < 4; j++)
                    mma8(acc[i][j], af[i], bf[j]);
        }
        __syncthreads();
        if (nxt) {
            #pragma unroll
            for (int p = 0; p < 4; p++) {
                s.As[p*32+ar][ac+0]=f2tf32(pa[p].x); s.As[p*32+ar][ac+1]=f2tf32(pa[p].y);
                s.As[p*32+ar][ac+2]=f2tf32(pa[p].z); s.As[p*32+ar][ac+3]=f2tf32(pa[p].w);
                s.Bs[p*32+ar][ac+0]=f2tf32(pb[p].x); s.Bs[p*32+ar][ac+1]=f2tf32(pb[p].y);
                s.Bs[p*32+ar][ac+2]=f2tf32(pb[p].z); s.Bs[p*32+ar][ac+3]=f2tf32(pb[p].w);
            }
            __syncthreads();
        }
    }

    #pragma unroll
    for (int i = 0; i < 4; i++) {
        #pragma unroll
        for (int j = 0; j < 4; j++) {
            int r0 = row0 + wm + i*16 + g;
            int cc = col0 + wn + j*8 + tg*2;
            if (r0 < M) {
                size_t x = (size_t)r0*N + cc;
                float v0 = acc[i][j][0], v1 = acc[i][j][1];
                if (R) { v0 += R[x]; v1 += R[x+1]; }
                C[x] = v0; C[x+1] = v1;
            }
            int r1 = r0 + 8;
            if (r1 < M) {
                size_t x = (size_t)r1*N + cc;
                float v2 = acc[i][j][2], v3 = acc[i][j][3];
                if (R) { v2 += R[x]; v3 += R[x+1]; }
                C[x] = v2; C[x+1] = v3;
            }
        }
    }
}

__global__ __launch_bounds__(256) void gemm_tf32_nt(
        const float* __restrict__ A, const float* __restrict__ B,
        const float* __restrict__ R, float* __restrict__ C, int M, int N, int K) {
    __shared__ SmemNT s;
    gemm_nt_body(s, A, B, R, C, M, N, K, blockIdx.y * 128, blockIdx.x * 128);
}

// =============== shared expert up + SiLU gate (dual-B tf32 NT) ============
// gt[T, DSH] = silu(x@B[0:DSH]^T) * (x@B[DSH:2DSH]^T). BM=128 BN=64 BK=32.
__global__ __launch_bounds__(256) void shared_up_gate_tf32(
        const float* __restrict__ A, const float* __restrict__ B,
        float* __restrict__ gt) {
    __shared__ unsigned As[128][36];
    __shared__ unsigned B1s[64][36];
    __shared__ unsigned B2s[64][36];
    const int row0 = blockIdx.y * 128, col0 = blockIdx.x * 64;
    const int tid = threadIdx.x;
    const int lane = tid & 31, w = tid >> 5;
    const int g = lane >> 2, tg = lane & 3;
    const int wm = (w & 3) * 32, wn = (w >> 2) * 32;
    const int ar = tid >> 3, ac = (tid & 7) * 4;

    const float* Ap[4];
    #pragma unroll
    for (int p = 0; p < 4; p++)
        Ap[p] = A + (size_t)(row0 + p*32 + ar) * DD + ac;
    const float* B1p[2]; const float* B2p[2];
    #pragma unroll
    for (int p = 0; p < 2; p++) {
        B1p[p] = B + (size_t)(col0 + p*32 + ar) * DD + ac;
        B2p[p] = B + (size_t)(DSH + col0 + p*32 + ar) * DD + ac;
    }

    #pragma unroll
    for (int p = 0; p < 4; p++) {
        float4 v = *(const float4*)(Ap[p]);
        As[p*32+ar][ac+0]=f2tf32(v.x); As[p*32+ar][ac+1]=f2tf32(v.y);
        As[p*32+ar][ac+2]=f2tf32(v.z); As[p*32+ar][ac+3]=f2tf32(v.w);
    }
    #pragma unroll
    for (int p = 0; p < 2; p++) {
        float4 v1 = *(const float4*)(B1p[p]);
        float4 v2 = *(const float4*)(B2p[p]);
        B1s[p*32+ar][ac+0]=f2tf32(v1.x); B1s[p*32+ar][ac+1]=f2tf32(v1.y);
        B1s[p*32+ar][ac+2]=f2tf32(v1.z); B1s[p*32+ar][ac+3]=f2tf32(v1.w);
        B2s[p*32+ar][ac+0]=f2tf32(v2.x); B2s[p*32+ar][ac+1]=f2tf32(v2.y);
        B2s[p*32+ar][ac+2]=f2tf32(v2.z); B2s[p*32+ar][ac+3]=f2tf32(v2.w);
    }
    __syncthreads();

    float acc1[2][4][4] = {}, acc2[2][4][4] = {};
    float4 pa[4], pb1[2], pb2[2];
    for (int k0 = 0; k0 < DD; k0 += 32) {
        bool nxt = (k0 + 32) < DD;
        if (nxt) {
            #pragma unroll
            for (int p = 0; p < 4; p++) pa[p] = *(const float4*)(Ap[p] + k0 + 32);
            #pragma unroll
            for (int p = 0; p < 2; p++) {
                pb1[p] = *(const float4*)(B1p[p] + k0 + 32);
                pb2[p] = *(const float4*)(B2p[p] + k0 + 32);
            }
        }
        #pragma unroll
        for (int ks = 0; ks < 4; ks++) {
            const int kb = ks*8;
            unsigned af[2][4], bf1[4][2], bf2[4][2];
            #pragma unroll
            for (int i = 0; i < 2; i++) {
                af[i][0] = As[wm+i*16+g  ][kb+tg];
                af[i][1] = As[wm+i*16+8+g][kb+tg];
                af[i][2] = As[wm+i*16+g  ][kb+tg+4];
                af[i][3] = As[wm+i*16+8+g][kb+tg+4];
            }
            #pragma unroll
            for (int j = 0; j < 4; j++) {
                bf1[j][0] = B1s[wn+j*8+g][kb+tg];
                bf1[j][1] = B1s[wn+j*8+g][kb+tg+4];
                bf2[j][0] = B2s[wn+j*8+g][kb+tg];
                bf2[j][1] = B2s[wn+j*8+g][kb+tg+4];
            }
            #pragma unroll
            for (int i = 0; i < 2; i++)
                #pragma unroll
                for (int j = 0; j < 4; j++) {
                    mma8(acc1[i][j], af[i], bf1[j]);
                    mma8(acc2[i][j], af[i], bf2[j]);
                }
        }
        __syncthreads();
        if (nxt) {
            #pragma unroll
            for (int p = 0; p < 4; p++) {
                As[p*32+ar][ac+0]=f2tf32(pa[p].x); As[p*32+ar][ac+1]=f2tf32(pa[p].y);
                As[p*32+ar][ac+2]=f2tf32(pa[p].z); As[p*32+ar][ac+3]=f2tf32(pa[p].w);
            }
            #pragma unroll
            for (int p = 0; p < 2; p++) {
                B1s[p*32+ar][ac+0]=f2tf32(pb1[p].x); B1s[p*32+ar][ac+1]=f2tf32(pb1[p].y);
                B1s[p*32+ar][ac+2]=f2tf32(pb1[p].z); B1s[p*32+ar][ac+3]=f2tf32(pb1[p].w);
                B2s[p*32+ar][ac+0]=f2tf32(pb2[p].x); B2s[p*32+ar][ac+1]=f2tf32(pb2[p].y);
                B2s[p*32+ar][ac+2]=f2tf32(pb2[p].z); B2s[p*32+ar][ac+3]=f2tf32(pb2[p].w);
            }
            __syncthreads();
        }
    }

    #pragma unroll
    for (int i = 0; i < 2; i++) {
        #pragma unroll
        for (int j = 0; j < 4; j++) {
            int r0 = row0 + wm + i*16 + g;
            int cc = col0 + wn + j*8 + tg*2;
            #pragma unroll
            for (int half = 0; half < 2; half++) {
                int r = r0 + half*8;
                float h1a = acc1[i][j][half*2+0], h2a = acc2[i][j][half*2+0];
                float h1b = acc1[i][j][half*2+1], h2b = acc2[i][j][half*2+1];
                float sa = 1.f / (1.f + __expf(-h1a));
                float sb = 1.f / (1.f + __expf(-h1b));
                size_t x = (size_t)r * DSH + cc;
                gt[x]   = h1a * sa * h2a;
                gt[x+1] = h1b * sb * h2b;
            }
        }
    }
}

// ---------------- RoPE (in-place on q,k within qkv buffer) ----------------
__global__ void rope_kernel(float* __restrict__ qkv) {
    int idx = blockIdx.x * blockDim.x + threadIdx.x;
    const int total = 2 * TT * HH * 32;
    if (idx >= total) return;
    int which = idx / (TT * HH * 32);
    int rem   = idx % (TT * HH * 32);
    int t = rem / (HH * 32);
    int r2 = rem % (HH * 32);
    int h = r2 >> 5, i = r2 & 31;
    size_t base = (size_t)t * QKV3 + (size_t)which * DD + h * HDIM;
    float invf = (float)exp(-9.210340371976184 * ((double)i / 32.0));
    float fr = (float)t * invf;
    float c = (float)cos((double)fr);
    float s = (float)sin((double)fr);
    float x1 = qkv[base + i];
    float x2 = qkv[base + 32 + i];
    qkv[base + i]      =  x1 * c + x2 * s;
    qkv[base + 32 + i] = -x1 * s + x2 * c;
}

// =============== flash attention v4: 128q, cp.async K/V double buffer =====
// 128q x 64k tiles, 256 threads = 8 warps, warp w owns q rows [16w,16w+16).
// Register softmax; P in registers (quad-shuffle frag conversion).
// K/V staged raw fp32 via cp.async, fed to mma.tf32 directly (HW truncation);
// attention's error contribution is negligible vs the GEMM chain.
#define KSTR 68   // K tile stride (words): QK b-frag loads conflict-free
#define VSTR 72   // V tile stride (words): PV b-frag loads conflict-free
constexpr int ATTN_STAGE = 64*KSTR + 64*VSTR;            // words per stage
constexpr int ATTN_SMEM  = 2 * ATTN_STAGE * (int)sizeof(float);  // 71680 B

__global__ __launch_bounds__(256) void attn_kernel(const float* __restrict__ qkv,
                                                   float* __restrict__ o) {
    extern __shared__ float smf[];

    const int qb = gridDim.x - 1 - blockIdx.x;   // heavy blocks first
    const int h = blockIdx.y;
    const int tid = threadIdx.x;
    const int lane = tid & 31, w = tid >> 5;
    const int g = lane >> 2, tg = lane & 3;
    const bool odd = tg & 1;
    const int s0 = tg >> 1, s1 = 2 + (tg >> 1);

    { // stage Q tile [128][64] raw fp32 (stride KSTR; 8704 words < 2*ATTN_STAGE)
        int qi = tid >> 1, d0 = (tid & 1) * 32;
        const float* src = qkv + (size_t)(qb*128 + qi) * QKV3 + h * HDIM + d0;
        #pragma unroll
        for (int c = 0; c < 32; c += 4) {
            float4 v = *(const float4*)(src + c);
            smf[qi*KSTR + d0+c+0] = v.x; smf[qi*KSTR + d0+c+1] = v.y;
            smf[qi*KSTR + d0+c+2] = v.z; smf[qi*KSTR + d0+c+3] = v.w;
        }
    }
    __syncthreads();
    unsigned aq[8][4];
    { // Q fragments to registers (RNA-converted once)
        int r0 = 16*w + g;
        #pragma unroll
        for (int kk = 0; kk < 8; kk++) {
            aq[kk][0] = f2tf32(smf[(r0  )*KSTR + 8*kk + tg]);
            aq[kk][1] = f2tf32(smf[(r0+8)*KSTR + 8*kk + tg]);
            aq[kk][2] = f2tf32(smf[(r0  )*KSTR + 8*kk + tg + 4]);
            aq[kk][3] = f2tf32(smf[(r0+8)*KSTR + 8*kk + tg + 4]);
        }
    }
    __syncthreads();

    const int kbmax = 2*qb + 1;
    const int lki = tid >> 2, ld0 = (tid & 3) * 16;   // K/V loader mapping

    { // preload stage 0 (kb = 0)
        float* Ks = smf;
        float* Vs = smf + 64*KSTR;
        const float* kp = qkv + (size_t)lki * QKV3 + DD   + h*HDIM + ld0;
        const float* vp = qkv + (size_t)lki * QKV3 + 2*DD + h*HDIM + ld0;
        #pragma unroll
        for (int c = 0; c < 16; c += 4) {
            cpa16(Ks + lki*KSTR + ld0 + c, kp + c, true);
            cpa16(Vs + lki*VSTR + ld0 + c, vp + c, true);
        }
        CPA_COMMIT();
    }

    float m0 = -INFINITY, m1 = -INFINITY, l0 = 0.f, l1 = 0.f;
    float acco[8][4] = {};
    const int qg0 = qb*128 + 16*w + g;
    const int qg1 = qg0 + 8;

    for (int kb = 0; kb <= kbmax; kb++) {
        const int st = kb & 1;
        const float* Ks = smf + st * ATTN_STAGE;
        const float* Vs = Ks + 64*KSTR;
        if (kb < kbmax) { // prefetch kb+1 into other stage
            float* Kn = smf + (st^1) * ATTN_STAGE;
            float* Vn = Kn + 64*KSTR;
            const float* kp = qkv + (size_t)((kb+1)*64 + lki) * QKV3 + DD   + h*HDIM + ld0;
            const float* vp = qkv + (size_t)((kb+1)*64 + lki) * QKV3 + 2*DD + h*HDIM + ld0;
            #pragma unroll
            for (int c = 0; c < 16; c += 4) {
                cpa16(Kn + lki*KSTR + ld0 + c, kp + c, true);
                cpa16(Vn + lki*VSTR + ld0 + c, vp + c, true);
            }
            CPA_COMMIT();
            CPA_WAIT1();
        } else {
            CPA_WAIT0();
        }
        __syncthreads();

        // S = Q @ K^T : warp tile 16 rows x 64 cols
        float sf[8][4] = {};
        #pragma unroll
        for (int kk = 0; kk < 8; kk++) {
            #pragma unroll
            for (int j = 0; j < 8; j++) {
                unsigned b[2] = { __float_as_uint(Ks[(8*j+g)*KSTR + 8*kk + tg]),
                                  __float_as_uint(Ks[(8*j+g)*KSTR + 8*kk + tg + 4]) };
                mma8(sf[j], aq[kk], b);
            }
        }
        // scale + causal mask + register softmax
        float vmax0 = -1e30f, vmax1 = -1e30f;
        #pragma unroll
        for (int j = 0; j < 8; j++) {
            int kg = kb*64 + 8*j + 2*tg;
            sf[j][0] = (kg   > qg0) ? -1e30f : sf[j][0]*0.125f;
            sf[j][1] = (kg+1 > qg0) ? -1e30f : sf[j][1]*0.125f;
            sf[j][2] = (kg   > qg1) ? -1e30f : sf[j][2]*0.125f;
            sf[j][3] = (kg+1 > qg1) ? -1e30f : sf[j][3]*0.125f;
            vmax0 = fmaxf(vmax0, fmaxf(sf[j][0], sf[j][1]));
            vmax1 = fmaxf(vmax1, fmaxf(sf[j][2], sf[j][3]));
        }
        vmax0 = fmaxf(vmax0, __shfl_xor_sync(0xffffffffu, vmax0, 1));
        vmax0 = fmaxf(vmax0, __shfl_xor_sync(0xffffffffu, vmax0, 2));
        vmax1 = fmaxf(vmax1, __shfl_xor_sync(0xffffffffu, vmax1, 1));
        vmax1 = fmaxf(vmax1, __shfl_xor_sync(0xffffffffu, vmax1, 2));
        float mn0 = fmaxf(m0, vmax0), mn1 = fmaxf(m1, vmax1);
        float al0 = __expf(m0 - mn0), al1 = __expf(m1 - mn1);
        float ps0 = 0.f, ps1 = 0.f;
        #pragma unroll
        for (int j = 0; j < 8; j++) {
            sf[j][0] = __expf(sf[j][0] - mn0); ps0 += sf[j][0];
            sf[j][1] = __expf(sf[j][1] - mn0); ps0 += sf[j][1];
            sf[j][2] = __expf(sf[j][2] - mn1); ps1 += sf[j][2];
            sf[j][3] = __expf(sf[j][3] - mn1); ps1 += sf[j][3];
        }
        ps0 += __shfl_xor_sync(0xffffffffu, ps0, 1);
        ps0 += __shfl_xor_sync(0xffffffffu, ps0, 2);
        ps1 += __shfl_xor_sync(0xffffffffu, ps1, 1);
        ps1 += __shfl_xor_sync(0xffffffffu, ps1, 2);
        l0 = l0*al0 + ps0; l1 = l1*al1 + ps1;
        m0 = mn0; m1 = mn1;
        #pragma unroll
        for (int jd = 0; jd < 8; jd++) {
            acco[jd][0] *= al0; acco[jd][1] *= al0;
            acco[jd][2] *= al1; acco[jd][3] *= al1;
        }
        // O += P @ V : A-frags built from C-frags via quad shuffles
        #pragma unroll
        for (int j = 0; j < 8; j++) {
            float q00 = __shfl_sync(0xffffffffu, sf[j][0], s0, 4);
            float q01 = __shfl_sync(0xffffffffu, sf[j][1], s0, 4);
            float q10 = __shfl_sync(0xffffffffu, sf[j][2], s0, 4);
            float q11 = __shfl_sync(0xffffffffu, sf[j][3], s0, 4);
            float r00 = __shfl_sync(0xffffffffu, sf[j][0], s1, 4);
            float r01 = __shfl_sync(0xffffffffu, sf[j][1], s1, 4);
            float r10 = __shfl_sync(0xffffffffu, sf[j][2], s1, 4);
            float r11 = __shfl_sync(0xffffffffu, sf[j][3], s1, 4);
            unsigned a[4];
            a[0] = f2tf32(odd ? q01 : q00);
            a[1] = f2tf32(odd ? q11 : q10);
            a[2] = f2tf32(odd ? r01 : r00);
            a[3] = f2tf32(odd ? r11 : r10);
            #pragma unroll
            for (int jd = 0; jd < 8; jd++) {
                unsigned b[2] = { __float_as_uint(Vs[(8*j+tg  )*VSTR + 8*jd + g]),
                                  __float_as_uint(Vs[(8*j+tg+4)*VSTR + 8*jd + g]) };
                mma8(acco[jd], a, b);
            }
        }
        __syncthreads();
    }

    float i0 = 1.f / l0, i1 = 1.f / l1;
    #pragma unroll
    for (int jd = 0; jd < 8; jd++) {
        int col = h*HDIM + 8*jd + 2*tg;
        o[(size_t)qg0*DD + col  ] = acco[jd][0]*i0;
        o[(size_t)qg0*DD + col+1] = acco[jd][1]*i0;
        o[(size_t)qg1*DD + col  ] = acco[jd][2]*i1;
        o[(size_t)qg1*DD + col+1] = acco[jd][3]*i1;
    }
}

// ---------------- router ----------------
__global__ void router_kernel(const float* __restrict__ xffn, const float* __restrict__ mk,
                              const float* __restrict__ bias, const int* __restrict__ indices,
                              const float* __restrict__ values, float* __restrict__ scores) {
    int t = blockIdx.x;
    __shared__ float red[128 * NEXP];
    float partial[NEXP];
    #pragma unroll
    for (int e = 0; e < NEXP; e++) partial[e] = 0.f;
    for (int d = threadIdx.x; d < DD; d += 128) {
        float xv = xffn[(size_t)t*DD + d];
        const float* mrow = mk + (size_t)d * NEXP;
        #pragma unroll
        for (int e = 0; e < NEXP; e++) partial[e] += xv * mrow[e];
    }
    #pragma unroll
    for (int e = 0; e < NEXP; e++) red[threadIdx.x*NEXP + e] = partial[e];
    __syncthreads();
    for (int s = 64; s >= 1; s >>= 1) {
        if (threadIdx.x < s)
            #pragma unroll
            for (int e = 0; e < NEXP; e++)
                red[threadIdx.x*NEXP + e] += red[(threadIdx.x+s)*NEXP + e];
        __syncthreads();
    }
    if (threadIdx.x == 0) {
        int i0 = indices[t*2+0], i1 = indices[t*2+1];
        float v0 = values[t*2+0] + red[i0] + bias[i0];
        float v1 = values[t*2+1] + red[i1] + bias[i1];
        float m = fmaxf(v0, v1);
        float e0 = __expf(v0 - m), e1 = __expf(v1 - m);
        float inv = 1.f / (e0 + e1);
        scores[t*2+0] = e0 * inv;
        scores[t*2+1] = e1 * inv;
    }
}

// ---------------- routing build ----------------
__global__ void route_init(int* counts) { if (threadIdx.x < NEXP) counts[threadIdx.x] = 0; }
__global__ void route_count(const int* __restrict__ indices, int* counts) {
    int i = blockIdx.x * blockDim.x + threadIdx.x;
    if (i < TT*TOPK) atomicAdd(&counts[indices[i]], 1);
}
__global__ void route_scan(const int* __restrict__ counts, int* offsets, int* cursor) {
    if (threadIdx.x == 0) {
        int off = 0;
        for (int e = 0; e < NEXP; e++) { offsets[e] = off; cursor[e] = off; off += counts[e]; }
        offsets[NEXP] = off;
    }
}
__global__ void route_scatter(const int* __restrict__ indices, int* cursor,
                              int* __restrict__ perm, int* __restrict__ slotpos) {
    int i = blockIdx.x * blockDim.x + threadIdx.x;
    if (i < TT*TOPK) {
        int e = indices[i];
        int p = atomicAdd(&cursor[e], 1);
        perm[p] = i >> 1;
        slotpos[i] = p;
    }
}

// =============== expert up (tf32): g = silu(x@W1) * (x@W2), gathered A ====
__global__ __launch_bounds__(256) void expert_up_tf32(
        const float* __restrict__ xffn, const float* __restrict__ experts,
        const int* __restrict__ counts, const int* __restrict__ offsets,
        const int* __restrict__ perm, float* __restrict__ g_out) {
    const int e = blockIdx.z;
    const int M = counts[e];
    const int row0 = blockIdx.y * 64;
    if (row0 >= M) return;
    const int off = offsets[e];
    const float* B1 = experts + (size_t)e * DD * EDIM;
    const float* B2 = experts + ((size_t)NEXP + e) * DD * EDIM;
    const int col0 = blockIdx.x * 64;

    __shared__ unsigned As[64][36];
    __shared__ unsigned B1s[32][72];
    __shared__ unsigned B2s[32][72];

    const int tid = threadIdx.x;
    const int lane = tid & 31, w = tid >> 5;
    const int g = lane >> 2, tg = lane & 3;
    const int wm = (w & 1) * 32, wn = (w >> 1) * 16;
    const int ar = tid >> 3, ac = (tid & 7) * 4;
    const int bkr = tid >> 4, bnc = (tid & 15) * 4;

    const float* Ap[2]; bool va[2];
    #pragma unroll
    for (int p = 0; p < 2; p++) {
        int r = row0 + p*32 + ar;
        va[p] = r < M;
        int tok = va[p] ? perm[off + r] : 0;
        Ap[p] = xffn + (size_t)tok * DD + ac;
    }
    const float* B1p[2]; const float* B2p[2];
    #pragma unroll
    for (int p = 0; p < 2; p++) {
        B1p[p] = B1 + (size_t)(p*16 + bkr) * EDIM + col0 + bnc;
        B2p[p] = B2 + (size_t)(p*16 + bkr) * EDIM + col0 + bnc;
    }

    #pragma unroll
    for (int p = 0; p < 2; p++) {
        float4 v = va[p] ? *(const float4*)(Ap[p]) : make_float4(0,0,0,0);
        As[p*32+ar][ac+0]=f2tf32(v.x); As[p*32+ar][ac+1]=f2tf32(v.y);
        As[p*32+ar][ac+2]=f2tf32(v.z); As[p*32+ar][ac+3]=f2tf32(v.w);
    }
    #pragma unroll
    for (int p = 0; p < 2; p++) {
        float4 v1 = *(const float4*)(B1p[p]);
        float4 v2 = *(const float4*)(B2p[p]);
        B1s[p*16+bkr][bnc+0]=f2tf32(v1.x); B1s[p*16+bkr][bnc+1]=f2tf32(v1.y);
        B1s[p*16+bkr][bnc+2]=f2tf32(v1.z); B1s[p*16+bkr][bnc+3]=f2tf32(v1.w);
        B2s[p*16+bkr][bnc+0]=f2tf32(v2.x); B2s[p*16+bkr][bnc+1]=f2tf32(v2.y);
        B2s[p*16+bkr][bnc+2]=f2tf32(v2.z); B2s[p*16+bkr][bnc+3]=f2tf32(v2.w);
    }
    __syncthreads();

    float acc1[2][2][4] = {}, acc2[2][2][4] = {};
    float4 pa[2], pb1[2], pb2[2];
    for (int k0 = 0; k0 < DD; k0 += 32) {
        bool nxt = (k0 + 32) < DD;
        if (nxt) {
            #pragma unroll
            for (int p = 0; p < 2; p++)
                pa[p] = va[p] ? *(const float4*)(Ap[p] + k0 + 32) : make_float4(0,0,0,0);
            #pragma unroll
            for (int p = 0; p < 2; p++) {
                pb1[p] = *(const float4*)(B1p[p] + (size_t)(k0 + 32) * EDIM);
                pb2[p] = *(const float4*)(B2p[p] + (size_t)(k0 + 32) * EDIM);
            }
        }
        #pragma unroll
        for (int ks = 0; ks < 4; ks++) {
            const int kb = ks*8;
            unsigned af[2][4], bf1[2][2], bf2[2][2];
            #pragma unroll
            for (int i = 0; i < 2; i++) {
                af[i][0] = As[wm+i*16+g  ][kb+tg];
                af[i][1] = As[wm+i*16+8+g][kb+tg];
                af[i][2] = As[wm+i*16+g  ][kb+tg+4];
                af[i][3] = As[wm+i*16+8+g][kb+tg+4];
            }
            #pragma unroll
            for (int j = 0; j < 2; j++) {
                bf1[j][0] = B1s[kb+tg  ][wn+j*8+g];
                bf1[j][1] = B1s[kb+tg+4][wn+j*8+g];
                bf2[j][0] = B2s[kb+tg  ][wn+j*8+g];
                bf2[j][1] = B2s[kb+tg+4][wn+j*8+g];
            }
            #pragma unroll
            for (int i = 0; i < 2; i++)
                #pragma unroll
                for (int j = 0; j < 2; j++) {
                    mma8(acc1[i][j], af[i], bf1[j]);
                    mma8(acc2[i][j], af[i], bf2[j]);
                }
        }
        __syncthreads();
        if (nxt) {
            #pragma unroll
            for (int p = 0; p < 2; p++) {
                As[p*32+ar][ac+0]=f2tf32(pa[p].x); As[p*32+ar][ac+1]=f2tf32(pa[p].y);
                As[p*32+ar][ac+2]=f2tf32(pa[p].z); As[p*32+ar][ac+3]=f2tf32(pa[p].w);
            }
            #pragma unroll
            for (int p = 0; p < 2; p++) {
                B1s[p*16+bkr][bnc+0]=f2tf32(pb1[p].x); B1s[p*16+bkr][bnc+1]=f2tf32(pb1[p].y);
                B1s[p*16+bkr][bnc+2]=f2tf32(pb1[p].z); B1s[p*16+bkr][bnc+3]=f2tf32(pb1[p].w);
                B2s[p*16+bkr][bnc+0]=f2tf32(pb2[p].x); B2s[p*16+bkr][bnc+1]=f2tf32(pb2[p].y);
                B2s[p*16+bkr][bnc+2]=f2tf32(pb2[p].z); B2s[p*16+bkr][bnc+3]=f2tf32(pb2[p].w);
            }
            __syncthreads();
        }
    }

    #pragma unroll
    for (int i = 0; i < 2; i++) {
        #pragma unroll
        for (int j = 0; j < 2; j++) {
            int r0 = row0 + wm + i*16 + g;
            int cc = col0 + wn + j*8 + tg*2;
            #pragma unroll
            for (int half = 0; half < 2; half++) {
                int r = r0 + half*8;
                if (r < M) {
                    float h1a = acc1[i][j][half*2+0], h2a = acc2[i][j][half*2+0];
                    float h1b = acc1[i][j][half*2+1], h2b = acc2[i][j][half*2+1];
                    float sa = 1.f / (1.f + __expf(-h1a));
                    float sb = 1.f / (1.f + __expf(-h1b));
                    size_t x = (size_t)(off + r) * EDIM + cc;
                    g_out[x]   = h1a * sa * h2a;
                    g_out[x+1] = h1b * sb * h2b;
                }
            }
        }
    }
}

// =============== expert down (tf32 NT): yp = g @ W3^T, per-expert slabs ===
__global__ __launch_bounds__(256) void expert_down_tf32(
        const float* __restrict__ gbuf, const float* __restrict__ experts,
        const int* __restrict__ counts, const int* __restrict__ offsets,
        float* __restrict__ yp) {
    const int e = blockIdx.z;
    const int M = counts[e];
    const int row0 = blockIdx.y * 128;
    if (row0 >= M) return;
    const int off = offsets[e];
    __shared__ SmemNT s;
    gemm_nt_body(s,
                 gbuf + (size_t)off * EDIM,
                 experts + (2*(size_t)NEXP + e) * DD * EDIM,
                 nullptr,
                 yp + (size_t)off * DD,
                 M, DD, EDIM, row0, blockIdx.x * 128);
}

// ---------------- combine experts (scores * yp) * coeff -------------------
__global__ void combine_kernel(const float* __restrict__ yp, const float* __restrict__ scores,
                               const int* __restrict__ slotpos, const float* __restrict__ coeff,
                               float* __restrict__ ycomb) {
    int t = blockIdx.x;
    float s0 = scores[t*2+0], s1 = scores[t*2+1];
    int p0 = slotpos[t*2+0], p1 = slotpos[t*2+1];
    const float* r0 = yp + (size_t)p0 * DD;
    const float* r1 = yp + (size_t)p1 * DD;
    #pragma unroll
    for (int i = 0; i < 4; i++) {
        int d = threadIdx.x + i*256;
        ycomb[(size_t)t*DD + d] = (s0*r0[d] + s1*r1[d]) * coeff[d];
    }
}

// ---------------- final: out = ycomb + rmsnorm(ysh)*w + x_ffn_input ------
__global__ void final_kernel(const float* __restrict__ ycomb, const float* __restrict__ ysh,
                             const float* __restrict__ shw, const float* __restrict__ xfi,
                             float* __restrict__ out) {
    int t = blockIdx.x;
    const float* yr = ysh + (size_t)t * DD;
    float v[4]; float s = 0.f;
    #pragma unroll
    for (int i = 0; i < 4; i++) { v[i] = yr[threadIdx.x + i*256]; s += v[i]*v[i]; }
    __shared__ float red[8];
    #pragma unroll
    for (int off = 16; off > 0; off >>= 1) s += __shfl_xor_sync(0xffffffffu, s, off);
    if ((threadIdx.x & 31) == 0) red[threadIdx.x >> 5] = s;
    __syncthreads();
    if (threadIdx.x == 0) {
        float tot = 0.f;
        #pragma unroll
        for (int i = 0; i < 8; i++) tot += red[i];
        red[0] = tot;
    }
    __syncthreads();
    float sc = rsqrtf(red[0] / (float)DD + 1e-5f);
    #pragma unroll
    for (int i = 0; i < 4; i++) {
        int d = threadIdx.x + i*256;
        size_t idx = (size_t)t*DD + d;
        out[idx] = ycomb[idx] + v[i]*sc*shw[d] + xfi[idx];
    }
}

// ---------------- launch ----------------
extern "C" void kernel_launch(void* const* d_in, const int* in_sizes, int n_in,
                              void* d_out, int out_size) {
    const float* x_input     = (const float*)d_in[0];
    const int*   indices     = (const int*)  d_in[1];
    const float* values      = (const float*)d_in[2];
    const float* attn_w      = (const float*)d_in[3];
    const float* attn_o_w    = (const float*)d_in[4];
    const float* attn_norm_w = (const float*)d_in[5];
    const float* ffn_norm_w  = (const float*)d_in[6];
    const float* ffn_experts = (const float*)d_in[7];
    const float* main_keys   = (const float*)d_in[8];
    const float* main_bias   = (const float*)d_in[9];
    const float* out_coeff   = (const float*)d_in[10];
    const float* ffn_up_w    = (const float*)d_in[11];
    const float* ffn_down_w  = (const float*)d_in[12];
    const float* shared_nw   = (const float*)d_in[13];
    float* out = (float*)d_out;

    float* bufF = nullptr; int* bufI = nullptr;
    cudaGetSymbolAddress((void**)&bufF, g_bufF);
    cudaGetSymbolAddress((void**)&bufI, g_bufI);

    float* xn   = bufF + OFF_XN;
    float* qkv  = bufF + OFF_QKV;
    float* ao   = bufF + OFF_AO;
    float* xfi  = bufF + OFF_XFI;
    float* xfn  = bufF + OFF_XFN;
    float* sc   = bufF + OFF_SC;
    float* gbuf = bufF + OFF_G;
    float* yp   = bufF + OFF_YP;
    float* yc   = bufF + OFF_YC;
    float* gt   = bufF + OFF_GT;
    float* ys   = bufF + OFF_YS;

    int* cnt  = bufI + IOFF_CNT;
    int* offs = bufI + IOFF_OFFS;
    int* cur  = bufI + IOFF_CUR;
    int* perm = bufI + IOFF_PERM;
    int* slot = bufI + IOFF_SLOT;

    cudaFuncSetAttribute(attn_kernel, cudaFuncAttributeMaxDynamicSharedMemorySize, ATTN_SMEM);

    // 1. attention pre-norm
    rmsnorm_kernel<<<TT, 256>>>(x_input, attn_norm_w, xn);
    // 2. QKV (tf32 tensor, 128x128 tiles)
    gemm_tf32_nt<<<dim3(QKV3/128, TT/128), 256>>>(xn, attn_w, nullptr, qkv, TT, QKV3, DD);
    // 3. RoPE on q,k
    rope_kernel<<<(2*TT*HH*32 + 255)/256, 256>>>(qkv);
    // 4. attention (tf32 tensor, cp.async K/V pipeline)
    attn_kernel<<<dim3(TT/128, HH), 256, ATTN_SMEM>>>(qkv, ao);
    // 5. O proj + residual (tf32)
    gemm_tf32_nt<<<dim3(DD/128, TT/128), 256>>>(ao, attn_o_w, x_input, xfi, TT, DD, DD);
    // 6. ffn pre-norm
    rmsnorm_kernel<<<TT, 256>>>(xfi, ffn_norm_w, xfn);
    // 7. router scores
    router_kernel<<<TT, 128>>>(xfn, main_keys, main_bias, indices, values, sc);
    // 8. routing permutation
    route_init<<<1, 32>>>(cnt);
    route_count<<<(TT*TOPK + 255)/256, 256>>>(indices, cnt);
    route_scan<<<1, 32>>>(cnt, offs, cur);
    route_scatter<<<(TT*TOPK + 255)/256, 256>>>(indices, cur, perm, slot);
    // 9. expert up (tf32 dual GEMM + SiLU)
    expert_up_tf32<<<dim3(EDIM/64, (TT*TOPK)/64, NEXP), 256>>>(xfn, ffn_experts, cnt, offs, perm, gbuf);
    // 10. expert down (tf32, 128x128 tiles)
    expert_down_tf32<<<dim3(DD/128, (TT*TOPK)/128, NEXP), 256>>>(gbuf, ffn_experts, cnt, offs, yp);
    // 11. combine
    combine_kernel<<<TT, 256>>>(yp, sc, slot, out_coeff, yc);
    // 12. shared expert up + gate (fused dual-B tf32)
    shared_up_gate_tf32<<<dim3(DSH/64, TT/128), 256>>>(xfn, ffn_up_w, gt);
    // 13. shared expert down (tf32)
    gemm_tf32_nt<<<dim3(DD/128, TT/128), 256>>>(gt, ffn_down_w, nullptr, ys, TT, DD, DSH);
    // 14. final combine
    final_kernel<<<TT, 256>>>(yc, ys, shared_nw, xfi, out);
}

// round 15
// speedup vs baseline: 1.1656x; 1.0507x over previous
#include <cuda_runtime.h>
#include <cuda_bf16.h>
#include <math.h>

#define TT    2048   // tokens (B*S)
#define DD    1024   // model dim
#define HH    16     // heads
#define HDIM  64     // head dim
#define NEXP  16     // experts
#define TOPK  2
#define EDIM  512    // expert dim
#define DSH   2048   // shared expert dim
#define QKV3  3072

// ---------------- scratch (device globals; no allocations) ----------------
constexpr size_t SZ_XN  = (size_t)TT * DD;
constexpr size_t OFF_XN  = 0;
constexpr size_t OFF_QKV = OFF_XN  + SZ_XN;
constexpr size_t OFF_AO  = OFF_QKV + (size_t)TT * QKV3;
constexpr size_t OFF_XFI = OFF_AO  + SZ_XN;
constexpr size_t OFF_XFN = OFF_XFI + SZ_XN;
constexpr size_t OFF_SC  = OFF_XFN + SZ_XN;
constexpr size_t OFF_G   = OFF_SC  + (size_t)TT * TOPK;
constexpr size_t OFF_YP  = OFF_G   + (size_t)TT * TOPK * EDIM;
constexpr size_t OFF_YC  = OFF_YP  + (size_t)TT * TOPK * DD;
constexpr size_t OFF_GT  = OFF_YC  + SZ_XN;
constexpr size_t OFF_YS  = OFF_GT  + (size_t)TT * DSH;
constexpr size_t TOTF    = OFF_YS  + SZ_XN;

__device__ float g_bufF[TOTF];

constexpr int IOFF_CNT  = 0;
constexpr int IOFF_OFFS = 16;
constexpr int IOFF_CUR  = 33;
constexpr int IOFF_PERM = 64;
constexpr int IOFF_SLOT = 64 + TT*TOPK;
constexpr int TOTI      = 64 + 2*TT*TOPK;
__device__ int g_bufI[TOTI];

// ---------------- tf32 mma helpers ----------------
__device__ __forceinline__ unsigned f2tf32(float x) {
    unsigned u; asm("cvt.rna.tf32.f32 %0, %1;" : "=r"(u) : "f"(x)); return u;
}
__device__ __forceinline__ void mma8(float* c, const unsigned* a, const unsigned* b) {
    asm volatile("mma.sync.aligned.m16n8k8.row.col.f32.tf32.tf32.f32 "
        "{%0,%1,%2,%3},{%4,%5,%6,%7},{%8,%9},{%0,%1,%2,%3};"
        : "+f"(c[0]), "+f"(c[1]), "+f"(c[2]), "+f"(c[3])
        : "r"(a[0]), "r"(a[1]), "r"(a[2]), "r"(a[3]), "r"(b[0]), "r"(b[1]));
}
// 16B cp.async with zero-fill when invalid
__device__ __forceinline__ void cpa16(float* dst, const float* src, bool v) {
    unsigned d = (unsigned)__cvta_generic_to_shared(dst);
    int sz = v ? 16 : 0;
    asm volatile("cp.async.cg.shared.global [%0], [%1], 16, %2;" :: "r"(d), "l"(src), "r"(sz));
}
#define CPA_COMMIT() asm volatile("cp.async.commit_group;")
#define CPA_WAIT1()  asm volatile("cp.async.wait_group 1;")
#define CPA_WAIT0()  asm volatile("cp.async.wait_group 0;")

// ---------------- rmsnorm ----------------
__global__ void rmsnorm_kernel(const float* __restrict__ x, const float* __restrict__ w,
                               float* __restrict__ o) {
    int t = blockIdx.x;
    const float* xr = x + (size_t)t * DD;
    float v[4]; float s = 0.f;
    #pragma unroll
    for (int i = 0; i < 4; i++) { v[i] = xr[threadIdx.x + i*256]; s += v[i]*v[i]; }
    __shared__ float red[8];
    #pragma unroll
    for (int off = 16; off > 0; off >>= 1) s += __shfl_xor_sync(0xffffffffu, s, off);
    if ((threadIdx.x & 31) == 0) red[threadIdx.x >> 5] = s;
    __syncthreads();
    if (threadIdx.x == 0) {
        float tot = 0.f;
        #pragma unroll
        for (int i = 0; i < 8; i++) tot += red[i];
        red[0] = tot;
    }
    __syncthreads();
    float sc = rsqrtf(red[0] / (float)DD + 1e-5f);
    #pragma unroll
    for (int i = 0; i < 4; i++) {
        int d = threadIdx.x + i*256;
        o[(size_t)t*DD + d] = v[i] * sc * w[d];
    }
}

// =============== tf32 NT GEMM: C[M,N] = A[M,K] @ B[N,K]^T (+R) ===========
// BM=128 BN=128 BK=32, 256 threads (8 warps: 2 along M x 4 along N,
// each warp computes a 64x32 tile). Register-prefetch double buffering.
struct SmemNT {
    unsigned As[128][36];
    unsigned Bs[128][36];
};

__device__ __forceinline__ void gemm_nt_body(
        SmemNT& s, const float* __restrict__ A, const float* __restrict__ B,
        const float* __restrict__ R, float* __restrict__ C,
        int M, int N, int K, int row0, int col0) {
    const int tid = threadIdx.x;
    const int lane = tid & 31, w = tid >> 5;
    const int g = lane >> 2, tg = lane & 3;
    const int wm = (w & 1) * 64, wn = (w >> 1) * 32;
    const int ar = tid >> 3, ac = (tid & 7) * 4;

    const float* Ap[4]; bool va[4];
    #pragma unroll
    for (int p = 0; p < 4; p++) {
        int r = row0 + p*32 + ar;
        va[p] = r < M;
        Ap[p] = A + (size_t)(va[p] ? r : 0) * K + ac;
    }
    const float* Bp[4];
    #pragma unroll
    for (int p = 0; p < 4; p++)
        Bp[p] = B + (size_t)(col0 + p*32 + ar) * K + ac;

    #pragma unroll
    for (int p = 0; p < 4; p++) {
        float4 v = va[p] ? *(const float4*)(Ap[p]) : make_float4(0,0,0,0);
        s.As[p*32+ar][ac+0]=f2tf32(v.x); s.As[p*32+ar][ac+1]=f2tf32(v.y);
        s.As[p*32+ar][ac+2]=f2tf32(v.z); s.As[p*32+ar][ac+3]=f2tf32(v.w);
        float4 b = *(const float4*)(Bp[p]);
        s.Bs[p*32+ar][ac+0]=f2tf32(b.x); s.Bs[p*32+ar][ac+1]=f2tf32(b.y);
        s.Bs[p*32+ar][ac+2]=f2tf32(b.z); s.Bs[p*32+ar][ac+3]=f2tf32(b.w);
    }
    __syncthreads();

    float acc[4][4][4] = {};
    float4 pa[4], pb[4];
    for (int k0 = 0; k0 < K; k0 += 32) {
        bool nxt = (k0 + 32) < K;
        if (nxt) {
            #pragma unroll
            for (int p = 0; p < 4; p++) {
                pa[p] = va[p] ? *(const float4*)(Ap[p] + k0 + 32) : make_float4(0,0,0,0);
                pb[p] = *(const float4*)(Bp[p] + k0 + 32);
            }
        }
        #pragma unroll
        for (int ks = 0; ks < 4; ks++) {
            const int kb = ks*8;
            unsigned af[4][4], bf[4][2];
            #pragma unroll
            for (int i = 0; i < 4; i++) {
                af[i][0] = s.As[wm+i*16+g  ][kb+tg];
                af[i][1] = s.As[wm+i*16+8+g][kb+tg];
                af[i][2] = s.As[wm+i*16+g  ][kb+tg+4];
                af[i][3] = s.As[wm+i*16+8+g][kb+tg+4];
            }
            #pragma unroll
            for (int j = 0; j < 4; j++) {
                bf[j][0] = s.Bs[wn+j*8+g][kb+tg];
                bf[j][1] = s.Bs[wn+j*8+g][kb+tg+4];
            }
            #pragma unroll
            for (int i = 0; i < 4; i++)
                #pragma unroll
                for (int j = 0; j < 4; j++)
                    mma8(acc[i][j], af[i], bf[j]);
        }
        __syncthreads();
        if (nxt) {
            #pragma unroll
            for (int p = 0; p < 4; p++) {
                s.As[p*32+ar][ac+0]=f2tf32(pa[p].x); s.As[p*32+ar][ac+1]=f2tf32(pa[p].y);
                s.As[p*32+ar][ac+2]=f2tf32(pa[p].z); s.As[p*32+ar][ac+3]=f2tf32(pa[p].w);
                s.Bs[p*32+ar][ac+0]=f2tf32(pb[p].x); s.Bs[p*32+ar][ac+1]=f2tf32(pb[p].y);
                s.Bs[p*32+ar][ac+2]=f2tf32(pb[p].z); s.Bs[p*32+ar][ac+3]=f2tf32(pb[p].w);
            }
            __syncthreads();
        }
    }

    #pragma unroll
    for (int i = 0; i < 4; i++) {
        #pragma unroll
        for (int j = 0; j < 4; j++) {
            int r0 = row0 + wm + i*16 + g;
            int cc = col0 + wn + j*8 + tg*2;
            if (r0 < M) {
                size_t x = (size_t)r0*N + cc;
                float v0 = acc[i][j][0], v1 = acc[i][j][1];
                if (R) { v0 += R[x]; v1 += R[x+1]; }
                C[x] = v0; C[x+1] = v1;
            }
            int r1 = r0 + 8;
            if (r1 < M) {
                size_t x = (size_t)r1*N + cc;
                float v2 = acc[i][j][2], v3 = acc[i][j][3];
                if (R) { v2 += R[x]; v3 += R[x+1]; }
                C[x] = v2; C[x+1] = v3;
            }
        }
    }
}

__global__ __launch_bounds__(256) void gemm_tf32_nt(
        const float* __restrict__ A, const float* __restrict__ B,
        const float* __restrict__ R, float* __restrict__ C, int M, int N, int K) {
    __shared__ SmemNT s;
    gemm_nt_body(s, A, B, R, C, M, N, K, blockIdx.y * 128, blockIdx.x * 128);
}

// =============== shared expert up + SiLU gate (dual-B tf32 NT) ============
// gt[T, DSH] = silu(x@B[0:DSH]^T) * (x@B[DSH:2DSH]^T). BM=128 BN=64 BK=32.
__global__ __launch_bounds__(256) void shared_up_gate_tf32(
        const float* __restrict__ A, const float* __restrict__ B,
        float* __restrict__ gt) {
    __shared__ unsigned As[128][36];
    __shared__ unsigned B1s[64][36];
    __shared__ unsigned B2s[64][36];
    const int row0 = blockIdx.y * 128, col0 = blockIdx.x * 64;
    const int tid = threadIdx.x;
    const int lane = tid & 31, w = tid >> 5;
    const int g = lane >> 2, tg = lane & 3;
    const int wm = (w & 3) * 32, wn = (w >> 2) * 32;
    const int ar = tid >> 3, ac = (tid & 7) * 4;

    const float* Ap[4];
    #pragma unroll
    for (int p = 0; p < 4; p++)
        Ap[p] = A + (size_t)(row0 + p*32 + ar) * DD + ac;
    const float* B1p[2]; const float* B2p[2];
    #pragma unroll
    for (int p = 0; p < 2; p++) {
        B1p[p] = B + (size_t)(col0 + p*32 + ar) * DD + ac;
        B2p[p] = B + (size_t)(DSH + col0 + p*32 + ar) * DD + ac;
    }

    #pragma unroll
    for (int p = 0; p < 4; p++) {
        float4 v = *(const float4*)(Ap[p]);
        As[p*32+ar][ac+0]=f2tf32(v.x); As[p*32+ar][ac+1]=f2tf32(v.y);
        As[p*32+ar][ac+2]=f2tf32(v.z); As[p*32+ar][ac+3]=f2tf32(v.w);
    }
    #pragma unroll
    for (int p = 0; p < 2; p++) {
        float4 v1 = *(const float4*)(B1p[p]);
        float4 v2 = *(const float4*)(B2p[p]);
        B1s[p*32+ar][ac+0]=f2tf32(v1.x); B1s[p*32+ar][ac+1]=f2tf32(v1.y);
        B1s[p*32+ar][ac+2]=f2tf32(v1.z); B1s[p*32+ar][ac+3]=f2tf32(v1.w);
        B2s[p*32+ar][ac+0]=f2tf32(v2.x); B2s[p*32+ar][ac+1]=f2tf32(v2.y);
        B2s[p*32+ar][ac+2]=f2tf32(v2.z); B2s[p*32+ar][ac+3]=f2tf32(v2.w);
    }
    __syncthreads();

    float acc1[2][4][4] = {}, acc2[2][4][4] = {};
    float4 pa[4], pb1[2], pb2[2];
    for (int k0 = 0; k0 < DD; k0 += 32) {
        bool nxt = (k0 + 32) < DD;
        if (nxt) {
            #pragma unroll
            for (int p = 0; p < 4; p++) pa[p] = *(const float4*)(Ap[p] + k0 + 32);
            #pragma unroll
            for (int p = 0; p < 2; p++) {
                pb1[p] = *(const float4*)(B1p[p] + k0 + 32);
                pb2[p] = *(const float4*)(B2p[p] + k0 + 32);
            }
        }
        #pragma unroll
        for (int ks = 0; ks < 4; ks++) {
            const int kb = ks*8;
            unsigned af[2][4], bf1[4][2], bf2[4][2];
            #pragma unroll
            for (int i = 0; i < 2; i++) {
                af[i][0] = As[wm+i*16+g  ][kb+tg];
                af[i][1] = As[wm+i*16+8+g][kb+tg];
                af[i][2] = As[wm+i*16+g  ][kb+tg+4];
                af[i][3] = As[wm+i*16+8+g][kb+tg+4];
            }
            #pragma unroll
            for (int j = 0; j < 4; j++) {
                bf1[j][0] = B1s[wn+j*8+g][kb+tg];
                bf1[j][1] = B1s[wn+j*8+g][kb+tg+4];
                bf2[j][0] = B2s[wn+j*8+g][kb+tg];
                bf2[j][1] = B2s[wn+j*8+g][kb+tg+4];
            }
            #pragma unroll
            for (int i = 0; i < 2; i++)
                #pragma unroll
                for (int j = 0; j < 4; j++) {
                    mma8(acc1[i][j], af[i], bf1[j]);
                    mma8(acc2[i][j], af[i], bf2[j]);
                }
        }
        __syncthreads();
        if (nxt) {
            #pragma unroll
            for (int p = 0; p < 4; p++) {
                As[p*32+ar][ac+0]=f2tf32(pa[p].x); As[p*32+ar][ac+1]=f2tf32(pa[p].y);
                As[p*32+ar][ac+2]=f2tf32(pa[p].z); As[p*32+ar][ac+3]=f2tf32(pa[p].w);
            }
            #pragma unroll
            for (int p = 0; p < 2; p++) {
                B1s[p*32+ar][ac+0]=f2tf32(pb1[p].x); B1s[p*32+ar][ac+1]=f2tf32(pb1[p].y);
                B1s[p*32+ar][ac+2]=f2tf32(pb1[p].z); B1s[p*32+ar][ac+3]=f2tf32(pb1[p].w);
                B2s[p*32+ar][ac+0]=f2tf32(pb2[p].x); B2s[p*32+ar][ac+1]=f2tf32(pb2[p].y);
                B2s[p*32+ar][ac+2]=f2tf32(pb2[p].z); B2s[p*32+ar][ac+3]=f2tf32(pb2[p].w);
            }
            __syncthreads();
        }
    }

    #pragma unroll
    for (int i = 0; i < 2; i++) {
        #pragma unroll
        for (int j = 0; j < 4; j++) {
            int r0 = row0 + wm + i*16 + g;
            int cc = col0 + wn + j*8 + tg*2;
            #pragma unroll
            for (int half = 0; half < 2; half++) {
                int r = r0 + half*8;
                float h1a = acc1[i][j][half*2+0], h2a = acc2[i][j][half*2+0];
                float h1b = acc1[i][j][half*2+1], h2b = acc2[i][j][half*2+1];
                float sa = 1.f / (1.f + __expf(-h1a));
                float sb = 1.f / (1.f + __expf(-h1b));
                size_t x = (size_t)r * DSH + cc;
                gt[x]   = h1a * sa * h2a;
                gt[x+1] = h1b * sb * h2b;
            }
        }
    }
}

// ---------------- RoPE (in-place on q,k within qkv buffer) ----------------
__global__ void rope_kernel(float* __restrict__ qkv) {
    int idx = blockIdx.x * blockDim.x + threadIdx.x;
    const int total = 2 * TT * HH * 32;
    if (idx >= total) return;
    int which = idx / (TT * HH * 32);
    int rem   = idx % (TT * HH * 32);
    int t = rem / (HH * 32);
    int r2 = rem % (HH * 32);
    int h = r2 >> 5, i = r2 & 31;
    size_t base = (size_t)t * QKV3 + (size_t)which * DD + h * HDIM;
    float invf = (float)exp(-9.210340371976184 * ((double)i / 32.0));
    float fr = (float)t * invf;
    float c = (float)cos((double)fr);
    float s = (float)sin((double)fr);
    float x1 = qkv[base + i];
    float x2 = qkv[base + 32 + i];
    qkv[base + i]      =  x1 * c + x2 * s;
    qkv[base + 32 + i] = -x1 * s + x2 * c;
}

// =============== flash attention v4: 128q, cp.async K/V double buffer =====
// 128q x 64k tiles, 256 threads = 8 warps, warp w owns q rows [16w,16w+16).
// __launch_bounds__(256,2) caps regs at 128 -> 2 CTAs/SM.
#define KSTR 68   // K tile stride (words): QK b-frag loads conflict-free
#define VSTR 72   // V tile stride (words): PV b-frag loads conflict-free
constexpr int ATTN_STAGE = 64*KSTR + 64*VSTR;            // words per stage
constexpr int ATTN_SMEM  = 2 * ATTN_STAGE * (int)sizeof(float);  // 71680 B

__global__ __launch_bounds__(256, 2) void attn_kernel(const float* __restrict__ qkv,
                                                      float* __restrict__ o) {
    extern __shared__ float smf[];

    const int qb = gridDim.x - 1 - blockIdx.x;   // heavy blocks first
    const int h = blockIdx.y;
    const int tid = threadIdx.x;
    const int lane = tid & 31, w = tid >> 5;
    const int g = lane >> 2, tg = lane & 3;
    const bool odd = tg & 1;
    const int s0 = tg >> 1, s1 = 2 + (tg >> 1);

    { // stage Q tile [128][64] raw fp32 (stride KSTR; 8704 words < 2*ATTN_STAGE)
        int qi = tid >> 1, d0 = (tid & 1) * 32;
        const float* src = qkv + (size_t)(qb*128 + qi) * QKV3 + h * HDIM + d0;
        #pragma unroll
        for (int c = 0; c < 32; c += 4) {
            float4 v = *(const float4*)(src + c);
            smf[qi*KSTR + d0+c+0] = v.x; smf[qi*KSTR + d0+c+1] = v.y;
            smf[qi*KSTR + d0+c+2] = v.z; smf[qi*KSTR + d0+c+3] = v.w;
        }
    }
    __syncthreads();
    unsigned aq[8][4];
    { // Q fragments to registers (RNA-converted once)
        int r0 = 16*w + g;
        #pragma unroll
        for (int kk = 0; kk < 8; kk++) {
            aq[kk][0] = f2tf32(smf[(r0  )*KSTR + 8*kk + tg]);
            aq[kk][1] = f2tf32(smf[(r0+8)*KSTR + 8*kk + tg]);
            aq[kk][2] = f2tf32(smf[(r0  )*KSTR + 8*kk + tg + 4]);
            aq[kk][3] = f2tf32(smf[(r0+8)*KSTR + 8*kk + tg + 4]);
        }
    }
    __syncthreads();

    const int kbmax = 2*qb + 1;
    const int lki = tid >> 2, ld0 = (tid & 3) * 16;   // K/V loader mapping

    { // preload stage 0 (kb = 0)
        float* Ks = smf;
        float* Vs = smf + 64*KSTR;
        const float* kp = qkv + (size_t)lki * QKV3 + DD   + h*HDIM + ld0;
        const float* vp = qkv + (size_t)lki * QKV3 + 2*DD + h*HDIM + ld0;
        #pragma unroll
        for (int c = 0; c < 16; c += 4) {
            cpa16(Ks + lki*KSTR + ld0 + c, kp + c, true);
            cpa16(Vs + lki*VSTR + ld0 + c, vp + c, true);
        }
        CPA_COMMIT();
    }

    float m0 = -INFINITY, m1 = -INFINITY, l0 = 0.f, l1 = 0.f;
    float acco[8][4] = {};
    const int qg0 = qb*128 + 16*w + g;
    const int qg1 = qg0 + 8;

    for (int kb = 0; kb <= kbmax; kb++) {
        const int st = kb & 1;
        const float* Ks = smf + st * ATTN_STAGE;
        const float* Vs = Ks + 64*KSTR;
        if (kb < kbmax) { // prefetch kb+1 into other stage
            float* Kn = smf + (st^1) * ATTN_STAGE;
            float* Vn = Kn + 64*KSTR;
            const float* kp = qkv + (size_t)((kb+1)*64 + lki) * QKV3 + DD   + h*HDIM + ld0;
            const float* vp = qkv + (size_t)((kb+1)*64 + lki) * QKV3 + 2*DD + h*HDIM + ld0;
            #pragma unroll
            for (int c = 0; c < 16; c += 4) {
                cpa16(Kn + lki*KSTR + ld0 + c, kp + c, true);
                cpa16(Vn + lki*VSTR + ld0 + c, vp + c, true);
            }
            CPA_COMMIT();
            CPA_WAIT1();
        } else {
            CPA_WAIT0();
        }
        __syncthreads();

        // S = Q @ K^T : warp tile 16 rows x 64 cols
        float sf[8][4] = {};
        #pragma unroll
        for (int kk = 0; kk < 8; kk++) {
            #pragma unroll
            for (int j = 0; j < 8; j++) {
                unsigned b[2] = { __float_as_uint(Ks[(8*j+g)*KSTR + 8*kk + tg]),
                                  __float_as_uint(Ks[(8*j+g)*KSTR + 8*kk + tg + 4]) };
                mma8(sf[j], aq[kk], b);
            }
        }
        // scale + causal mask + register softmax
        float vmax0 = -1e30f, vmax1 = -1e30f;
        #pragma unroll
        for (int j = 0; j < 8; j++) {
            int kg = kb*64 + 8*j + 2*tg;
            sf[j][0] = (kg   > qg0) ? -1e30f : sf[j][0]*0.125f;
            sf[j][1] = (kg+1 > qg0) ? -1e30f : sf[j][1]*0.125f;
            sf[j][2] = (kg   > qg1) ? -1e30f : sf[j][2]*0.125f;
            sf[j][3] = (kg+1 > qg1) ? -1e30f : sf[j][3]*0.125f;
            vmax0 = fmaxf(vmax0, fmaxf(sf[j][0], sf[j][1]));
            vmax1 = fmaxf(vmax1, fmaxf(sf[j][2], sf[j][3]));
        }
        vmax0 = fmaxf(vmax0, __shfl_xor_sync(0xffffffffu, vmax0, 1));
        vmax0 = fmaxf(vmax0, __shfl_xor_sync(0xffffffffu, vmax0, 2));
        vmax1 = fmaxf(vmax1, __shfl_xor_sync(0xffffffffu, vmax1, 1));
        vmax1 = fmaxf(vmax1, __shfl_xor_sync(0xffffffffu, vmax1, 2));
        float mn0 = fmaxf(m0, vmax0), mn1 = fmaxf(m1, vmax1);
        float al0 = __expf(m0 - mn0), al1 = __expf(m1 - mn1);
        float ps0 = 0.f, ps1 = 0.f;
        #pragma unroll
        for (int j = 0; j < 8; j++) {
            sf[j][0] = __expf(sf[j][0] - mn0); ps0 += sf[j][0];
            sf[j][1] = __expf(sf[j][1] - mn0); ps0 += sf[j][1];
            sf[j][2] = __expf(sf[j][2] - mn1); ps1 += sf[j][2];
            sf[j][3] = __expf(sf[j][3] - mn1); ps1 += sf[j][3];
        }
        ps0 += __shfl_xor_sync(0xffffffffu, ps0, 1);
        ps0 += __shfl_xor_sync(0xffffffffu, ps0, 2);
        ps1 += __shfl_xor_sync(0xffffffffu, ps1, 1);
        ps1 += __shfl_xor_sync(0xffffffffu, ps1, 2);
        l0 = l0*al0 + ps0; l1 = l1*al1 + ps1;
        m0 = mn0; m1 = mn1;
        #pragma unroll
        for (int jd = 0; jd < 8; jd++) {
            acco[jd][0] *= al0; acco[jd][1] *= al0;
            acco[jd][2] *= al1; acco[jd][3] *= al1;
        }
        // O += P @ V : A-frags built from C-frags via quad shuffles
        #pragma unroll
        for (int j = 0; j < 8; j++) {
            float q00 = __shfl_sync(0xffffffffu, sf[j][0], s0, 4);
            float q01 = __shfl_sync(0xffffffffu, sf[j][1], s0, 4);
            float q10 = __shfl_sync(0xffffffffu, sf[j][2], s0, 4);
            float q11 = __shfl_sync(0xffffffffu, sf[j][3], s0, 4);
            float r00 = __shfl_sync(0xffffffffu, sf[j][0], s1, 4);
            float r01 = __shfl_sync(0xffffffffu, sf[j][1], s1, 4);
            float r10 = __shfl_sync(0xffffffffu, sf[j][2], s1, 4);
            float r11 = __shfl_sync(0xffffffffu, sf[j][3], s1, 4);
            unsigned a[4];
            a[0] = f2tf32(odd ? q01 : q00);
            a[1] = f2tf32(odd ? q11 : q10);
            a[2] = f2tf32(odd ? r01 : r00);
            a[3] = f2tf32(odd ? r11 : r10);
            #pragma unroll
            for (int jd = 0; jd < 8; jd++) {
                unsigned b[2] = { __float_as_uint(Vs[(8*j+tg  )*VSTR + 8*jd + g]),
                                  __float_as_uint(Vs[(8*j+tg+4)*VSTR + 8*jd + g]) };
                mma8(acco[jd], a, b);
            }
        }
        __syncthreads();
    }

    float i0 = 1.f / l0, i1 = 1.f / l1;
    #pragma unroll
    for (int jd = 0; jd < 8; jd++) {
        int col = h*HDIM + 8*jd + 2*tg;
        o[(size_t)qg0*DD + col  ] = acco[jd][0]*i0;
        o[(size_t)qg0*DD + col+1] = acco[jd][1]*i0;
        o[(size_t)qg1*DD + col  ] = acco[jd][2]*i1;
        o[(size_t)qg1*DD + col+1] = acco[jd][3]*i1;
    }
}

// ---------------- router ----------------
__global__ void router_kernel(const float* __restrict__ xffn, const float* __restrict__ mk,
                              const float* __restrict__ bias, const int* __restrict__ indices,
                              const float* __restrict__ values, float* __restrict__ scores) {
    int t = blockIdx.x;
    __shared__ float red[128 * NEXP];
    float partial[NEXP];
    #pragma unroll
    for (int e = 0; e < NEXP; e++) partial[e] = 0.f;
    for (int d = threadIdx.x; d < DD; d += 128) {
        float xv = xffn[(size_t)t*DD + d];
        const float* mrow = mk + (size_t)d * NEXP;
        #pragma unroll
        for (int e = 0; e < NEXP; e++) partial[e] += xv * mrow[e];
    }
    #pragma unroll
    for (int e = 0; e < NEXP; e++) red[threadIdx.x*NEXP + e] = partial[e];
    __syncthreads();
    for (int s = 64; s >= 1; s >>= 1) {
        if (threadIdx.x < s)
            #pragma unroll
            for (int e = 0; e < NEXP; e++)
                red[threadIdx.x*NEXP + e] += red[(threadIdx.x+s)*NEXP + e];
        __syncthreads();
    }
    if (threadIdx.x == 0) {
        int i0 = indices[t*2+0], i1 = indices[t*2+1];
        float v0 = values[t*2+0] + red[i0] + bias[i0];
        float v1 = values[t*2+1] + red[i1] + bias[i1];
        float m = fmaxf(v0, v1);
        float e0 = __expf(v0 - m), e1 = __expf(v1 - m);
        float inv = 1.f / (e0 + e1);
        scores[t*2+0] = e0 * inv;
        scores[t*2+1] = e1 * inv;
    }
}

// ---------------- routing build ----------------
__global__ void route_init(int* counts) { if (threadIdx.x < NEXP) counts[threadIdx.x] = 0; }
__global__ void route_count(const int* __restrict__ indices, int* counts) {
    int i = blockIdx.x * blockDim.x + threadIdx.x;
    if (i < TT*TOPK) atomicAdd(&counts[indices[i]], 1);
}
__global__ void route_scan(const int* __restrict__ counts, int* offsets, int* cursor) {
    if (threadIdx.x == 0) {
        int off = 0;
        for (int e = 0; e < NEXP; e++) { offsets[e] = off; cursor[e] = off; off += counts[e]; }
        offsets[NEXP] = off;
    }
}
__global__ void route_scatter(const int* __restrict__ indices, int* cursor,
                              int* __restrict__ perm, int* __restrict__ slotpos) {
    int i = blockIdx.x * blockDim.x + threadIdx.x;
    if (i < TT*TOPK) {
        int e = indices[i];
        int p = atomicAdd(&cursor[e], 1);
        perm[p] = i >> 1;
        slotpos[i] = p;
    }
}

// =============== expert up (tf32): g = silu(x@W1) * (x@W2), gathered A ====
__global__ __launch_bounds__(256) void expert_up_tf32(
        const float* __restrict__ xffn, const float* __restrict__ experts,
        const int* __restrict__ counts, const int* __restrict__ offsets,
        const int* __restrict__ perm, float* __restrict__ g_out) {
    const int e = blockIdx.z;
    const int M = counts[e];
    const int row0 = blockIdx.y * 64;
    if (row0 >= M) return;
    const int off = offsets[e];
    const float* B1 = experts + (size_t)e * DD * EDIM;
    const float* B2 = experts + ((size_t)NEXP + e) * DD * EDIM;
    const int col0 = blockIdx.x * 64;

    __shared__ unsigned As[64][36];
    __shared__ unsigned B1s[32][72];
    __shared__ unsigned B2s[32][72];

    const int tid = threadIdx.x;
    const int lane = tid & 31, w = tid >> 5;
    const int g = lane >> 2, tg = lane & 3;
    const int wm = (w & 1) * 32, wn = (w >> 1) * 16;
    const int ar = tid >> 3, ac = (tid & 7) * 4;
    const int bkr = tid >> 4, bnc = (tid & 15) * 4;

    const float* Ap[2]; bool va[2];
    #pragma unroll
    for (int p = 0; p < 2; p++) {
        int r = row0 + p*32 + ar;
        va[p] = r < M;
        int tok = va[p] ? perm[off + r] : 0;
        Ap[p] = xffn + (size_t)tok * DD + ac;
    }
    const float* B1p[2]; const float* B2p[2];
    #pragma unroll
    for (int p = 0; p < 2; p++) {
        B1p[p] = B1 + (size_t)(p*16 + bkr) * EDIM + col0 + bnc;
        B2p[p] = B2 + (size_t)(p*16 + bkr) * EDIM + col0 + bnc;
    }

    #pragma unroll
    for (int p = 0; p < 2; p++) {
        float4 v = va[p] ? *(const float4*)(Ap[p]) : make_float4(0,0,0,0);
        As[p*32+ar][ac+0]=f2tf32(v.x); As[p*32+ar][ac+1]=f2tf32(v.y);
        As[p*32+ar][ac+2]=f2tf32(v.z); As[p*32+ar][ac+3]=f2tf32(v.w);
    }
    #pragma unroll
    for (int p = 0; p < 2; p++) {
        float4 v1 = *(const float4*)(B1p[p]);
        float4 v2 = *(const float4*)(B2p[p]);
        B1s[p*16+bkr][bnc+0]=f2tf32(v1.x); B1s[p*16+bkr][bnc+1]=f2tf32(v1.y);
        B1s[p*16+bkr][bnc+2]=f2tf32(v1.z); B1s[p*16+bkr][bnc+3]=f2tf32(v1.w);
        B2s[p*16+bkr][bnc+0]=f2tf32(v2.x); B2s[p*16+bkr][bnc+1]=f2tf32(v2.y);
        B2s[p*16+bkr][bnc+2]=f2tf32(v2.z); B2s[p*16+bkr][bnc+3]=f2tf32(v2.w);
    }
    __syncthreads();

    float acc1[2][2][4] = {}, acc2[2][2][4] = {};
    float4 pa[2], pb1[2], pb2[2];
    for (int k0 = 0; k0 < DD; k0 += 32) {
        bool nxt = (k0 + 32) < DD;
        if (nxt) {
            #pragma unroll
            for (int p = 0; p < 2; p++)
                pa[p] = va[p] ? *(const float4*)(Ap[p] + k0 + 32) : make_float4(0,0,0,0);
            #pragma unroll
            for (int p = 0; p < 2; p++) {
                pb1[p] = *(const float4*)(B1p[p] + (size_t)(k0 + 32) * EDIM);
                pb2[p] = *(const float4*)(B2p[p] + (size_t)(k0 + 32) * EDIM);
            }
        }
        #pragma unroll
        for (int ks = 0; ks < 4; ks++) {
            const int kb = ks*8;
            unsigned af[2][4], bf1[2][2], bf2[2][2];
            #pragma unroll
            for (int i = 0; i < 2; i++) {
                af[i][0] = As[wm+i*16+g  ][kb+tg];
                af[i][1] = As[wm+i*16+8+g][kb+tg];
                af[i][2] = As[wm+i*16+g  ][kb+tg+4];
                af[i][3] = As[wm+i*16+8+g][kb+tg+4];
            }
            #pragma unroll
            for (int j = 0; j < 2; j++) {
                bf1[j][0] = B1s[kb+tg  ][wn+j*8+g];
                bf1[j][1] = B1s[kb+tg+4][wn+j*8+g];
                bf2[j][0] = B2s[kb+tg  ][wn+j*8+g];
                bf2[j][1] = B2s[kb+tg+4][wn+j*8+g];
            }
            #pragma unroll
            for (int i = 0; i < 2; i++)
                #pragma unroll
                for (int j = 0; j < 2; j++) {
                    mma8(acc1[i][j], af[i], bf1[j]);
                    mma8(acc2[i][j], af[i], bf2[j]);
                }
        }
        __syncthreads();
        if (nxt) {
            #pragma unroll
            for (int p = 0; p < 2; p++) {
                As[p*32+ar][ac+0]=f2tf32(pa[p].x); As[p*32+ar][ac+1]=f2tf32(pa[p].y);
                As[p*32+ar][ac+2]=f2tf32(pa[p].z); As[p*32+ar][ac+3]=f2tf32(pa[p].w);
            }
            #pragma unroll
            for (int p = 0; p < 2; p++) {
                B1s[p*16+bkr][bnc+0]=f2tf32(pb1[p].x); B1s[p*16+bkr][bnc+1]=f2tf32(pb1[p].y);
                B1s[p*16+bkr][bnc+2]=f2tf32(pb1[p].z); B1s[p*16+bkr][bnc+3]=f2tf32(pb1[p].w);
                B2s[p*16+bkr][bnc+0]=f2tf32(pb2[p].x); B2s[p*16+bkr][bnc+1]=f2tf32(pb2[p].y);
                B2s[p*16+bkr][bnc+2]=f2tf32(pb2[p].z); B2s[p*16+bkr][bnc+3]=f2tf32(pb2[p].w);
            }
            __syncthreads();
        }
    }

    #pragma unroll
    for (int i = 0; i < 2; i++) {
        #pragma unroll
        for (int j = 0; j < 2; j++) {
            int r0 = row0 + wm + i*16 + g;
            int cc = col0 + wn + j*8 + tg*2;
            #pragma unroll
            for (int half = 0; half < 2; half++) {
                int r = r0 + half*8;
                if (r < M) {
                    float h1a = acc1[i][j][half*2+0], h2a = acc2[i][j][half*2+0];
                    float h1b = acc1[i][j][half*2+1], h2b = acc2[i][j][half*2+1];
                    float sa = 1.f / (1.f + __expf(-h1a));
                    float sb = 1.f / (1.f + __expf(-h1b));
                    size_t x = (size_t)(off + r) * EDIM + cc;
                    g_out[x]   = h1a * sa * h2a;
                    g_out[x+1] = h1b * sb * h2b;
                }
            }
        }
    }
}

// =============== expert down (tf32 NT): yp = g @ W3^T, per-expert slabs ===
__global__ __launch_bounds__(256) void expert_down_tf32(
        const float* __restrict__ gbuf, const float* __restrict__ experts,
        const int* __restrict__ counts, const int* __restrict__ offsets,
        float* __restrict__ yp) {
    const int e = blockIdx.z;
    const int M = counts[e];
    const int row0 = blockIdx.y * 128;
    if (row0 >= M) return;
    const int off = offsets[e];
    __shared__ SmemNT s;
    gemm_nt_body(s,
                 gbuf + (size_t)off * EDIM,
                 experts + (2*(size_t)NEXP + e) * DD * EDIM,
                 nullptr,
                 yp + (size_t)off * DD,
                 M, DD, EDIM, row0, blockIdx.x * 128);
}

// ---------------- combine experts (scores * yp) * coeff -------------------
__global__ void combine_kernel(const float* __restrict__ yp, const float* __restrict__ scores,
                               const int* __restrict__ slotpos, const float* __restrict__ coeff,
                               float* __restrict__ ycomb) {
    int t = blockIdx.x;
    float s0 = scores[t*2+0], s1 = scores[t*2+1];
    int p0 = slotpos[t*2+0], p1 = slotpos[t*2+1];
    const float* r0 = yp + (size_t)p0 * DD;
    const float* r1 = yp + (size_t)p1 * DD;
    #pragma unroll
    for (int i = 0; i < 4; i++) {
        int d = threadIdx.x + i*256;
        ycomb[(size_t)t*DD + d] = (s0*r0[d] + s1*r1[d]) * coeff[d];
    }
}

// ---------------- final: out = ycomb + rmsnorm(ysh)*w + x_ffn_input ------
__global__ void final_kernel(const float* __restrict__ ycomb, const float* __restrict__ ysh,
                             const float* __restrict__ shw, const float* __restrict__ xfi,
                             float* __restrict__ out) {
    int t = blockIdx.x;
    const float* yr = ysh + (size_t)t * DD;
    float v[4]; float s = 0.f;
    #pragma unroll
    for (int i = 0; i < 4; i++) { v[i] = yr[threadIdx.x + i*256]; s += v[i]*v[i]; }
    __shared__ float red[8];
    #pragma unroll
    for (int off = 16; off > 0; off >>= 1) s += __shfl_xor_sync(0xffffffffu, s, off);
    if ((threadIdx.x & 31) == 0) red[threadIdx.x >> 5] = s;
    __syncthreads();
    if (threadIdx.x == 0) {
        float tot = 0.f;
        #pragma unroll
        for (int i = 0; i < 8; i++) tot += red[i];
        red[0] = tot;
    }
    __syncthreads();
    float sc = rsqrtf(red[0] / (float)DD + 1e-5f);
    #pragma unroll
    for (int i = 0; i < 4; i++) {
        int d = threadIdx.x + i*256;
        size_t idx = (size_t)t*DD + d;
        out[idx] = ycomb[idx] + v[i]*sc*shw[d] + xfi[idx];
    }
}

// ---------------- launch ----------------
extern "C" void kernel_launch(void* const* d_in, const int* in_sizes, int n_in,
                              void* d_out, int out_size) {
    const float* x_input     = (const float*)d_in[0];
    const int*   indices     = (const int*)  d_in[1];
    const float* values      = (const float*)d_in[2];
    const float* attn_w      = (const float*)d_in[3];
    const float* attn_o_w    = (const float*)d_in[4];
    const float* attn_norm_w = (const float*)d_in[5];
    const float* ffn_norm_w  = (const float*)d_in[6];
    const float* ffn_experts = (const float*)d_in[7];
    const float* main_keys   = (const float*)d_in[8];
    const float* main_bias   = (const float*)d_in[9];
    const float* out_coeff   = (const float*)d_in[10];
    const float* ffn_up_w    = (const float*)d_in[11];
    const float* ffn_down_w  = (const float*)d_in[12];
    const float* shared_nw   = (const float*)d_in[13];
    float* out = (float*)d_out;

    float* bufF = nullptr; int* bufI = nullptr;
    cudaGetSymbolAddress((void**)&bufF, g_bufF);
    cudaGetSymbolAddress((void**)&bufI, g_bufI);

    float* xn   = bufF + OFF_XN;
    float* qkv  = bufF + OFF_QKV;
    float* ao   = bufF + OFF_AO;
    float* xfi  = bufF + OFF_XFI;
    float* xfn  = bufF + OFF_XFN;
    float* sc   = bufF + OFF_SC;
    float* gbuf = bufF + OFF_G;
    float* yp   = bufF + OFF_YP;
    float* yc   = bufF + OFF_YC;
    float* gt   = bufF + OFF_GT;
    float* ys   = bufF + OFF_YS;

    int* cnt  = bufI + IOFF_CNT;
    int* offs = bufI + IOFF_OFFS;
    int* cur  = bufI + IOFF_CUR;
    int* perm = bufI + IOFF_PERM;
    int* slot = bufI + IOFF_SLOT;

    cudaFuncSetAttribute(attn_kernel, cudaFuncAttributeMaxDynamicSharedMemorySize, ATTN_SMEM);

    // fork/join resources — created AND destroyed within this call so no
    // device-side stream/event memory outlives the run (R13 leaked 2 MB here).
    cudaStream_t s_r, s_s;
    cudaEvent_t ev_fork, ev_r, ev_s;
    cudaStreamCreateWithFlags(&s_r, cudaStreamNonBlocking);
    cudaStreamCreateWithFlags(&s_s, cudaStreamNonBlocking);
    cudaEventCreateWithFlags(&ev_fork, cudaEventDisableTiming);
    cudaEventCreateWithFlags(&ev_r,    cudaEventDisableTiming);
    cudaEventCreateWithFlags(&ev_s,    cudaEventDisableTiming);

    // ---- serial prefix (default stream) ----
    // 1. attention pre-norm
    rmsnorm_kernel<<<TT, 256>>>(x_input, attn_norm_w, xn);
    // 2. QKV (tf32 tensor, 128x128 tiles)
    gemm_tf32_nt<<<dim3(QKV3/128, TT/128), 256>>>(xn, attn_w, nullptr, qkv, TT, QKV3, DD);
    // 3. RoPE on q,k
    rope_kernel<<<(2*TT*HH*32 + 255)/256, 256>>>(qkv);
    // 4. attention (tf32 tensor, cp.async K/V pipeline, 2 CTAs/SM)
    attn_kernel<<<dim3(TT/128, HH), 256, ATTN_SMEM>>>(qkv, ao);
    // 5. O proj + residual (tf32)
    gemm_tf32_nt<<<dim3(DD/128, TT/128), 256>>>(ao, attn_o_w, x_input, xfi, TT, DD, DD);
    // 6. ffn pre-norm
    rmsnorm_kernel<<<TT, 256>>>(xfi, ffn_norm_w, xfn);

    // ---- fork: routed experts (s_r) || shared expert (s_s) ----
    cudaEventRecord(ev_fork, 0);
    cudaStreamWaitEvent(s_r, ev_fork, 0);
    cudaStreamWaitEvent(s_s, ev_fork, 0);

    // routed chain on s_r
    router_kernel<<<TT, 128, 0, s_r>>>(xfn, main_keys, main_bias, indices, values, sc);
    route_init<<<1, 32, 0, s_r>>>(cnt);
    route_count<<<(TT*TOPK + 255)/256, 256, 0, s_r>>>(indices, cnt);
    route_scan<<<1, 32, 0, s_r>>>(cnt, offs, cur);
    route_scatter<<<(TT*TOPK + 255)/256, 256, 0, s_r>>>(indices, cur, perm, slot);
    expert_up_tf32<<<dim3(EDIM/64, (TT*TOPK)/64, NEXP), 256, 0, s_r>>>(xfn, ffn_experts, cnt, offs, perm, gbuf);
    expert_down_tf32<<<dim3(DD/128, (TT*TOPK)/128, NEXP), 256, 0, s_r>>>(gbuf, ffn_experts, cnt, offs, yp);
    combine_kernel<<<TT, 256, 0, s_r>>>(yp, sc, slot, out_coeff, yc);
    cudaEventRecord(ev_r, s_r);

    // shared chain on s_s
    shared_up_gate_tf32<<<dim3(DSH/64, TT/128), 256, 0, s_s>>>(xfn, ffn_up_w, gt);
    gemm_tf32_nt<<<dim3(DD/128, TT/128), 256, 0, s_s>>>(gt, ffn_down_w, nullptr, ys, TT, DD, DSH);
    cudaEventRecord(ev_s, s_s);

    // ---- join on default stream ----
    cudaStreamWaitEvent(0, ev_r, 0);
    cudaStreamWaitEvent(0, ev_s, 0);
    // final combine
    final_kernel<<<TT, 256>>>(yc, ys, shared_nw, xfi, out);

    // ---- release fork/join resources (side streams already joined) ----
    cudaEventDestroy(ev_fork);
    cudaEventDestroy(ev_r);
    cudaEventDestroy(ev_s);
    cudaStreamDestroy(s_r);
    cudaStreamDestroy(s_s);
}

// round 16
// speedup vs baseline: 1.2537x; 1.0755x over previous
#include <cuda_runtime.h>
#include <cuda_bf16.h>
#include <math.h>

#define TT    2048   // tokens (B*S)
#define DD    1024   // model dim
#define HH    16     // heads
#define HDIM  64     // head dim
#define NEXP  16     // experts
#define TOPK  2
#define EDIM  512    // expert dim
#define DSH   2048   // shared expert dim
#define QKV3  3072

// ---------------- scratch (device globals; no allocations) ----------------
constexpr size_t SZ_XN  = (size_t)TT * DD;
constexpr size_t OFF_XN  = 0;
constexpr size_t OFF_QKV = OFF_XN  + SZ_XN;
constexpr size_t OFF_AO  = OFF_QKV + (size_t)TT * QKV3;
constexpr size_t OFF_XFI = OFF_AO  + SZ_XN;
constexpr size_t OFF_XFN = OFF_XFI + SZ_XN;
constexpr size_t OFF_SC  = OFF_XFN + SZ_XN;
constexpr size_t OFF_G   = OFF_SC  + (size_t)TT * TOPK;
constexpr size_t OFF_YP  = OFF_G   + (size_t)TT * TOPK * EDIM;
constexpr size_t OFF_GT  = OFF_YP  + (size_t)TT * TOPK * DD;
constexpr size_t OFF_YS  = OFF_GT  + (size_t)TT * DSH;
constexpr size_t OFF_PAC = OFF_YS  + SZ_XN;                    // split-K partial acc [16][HH][128][64]
constexpr size_t OFF_ML  = OFF_PAC + (size_t)16*HH*128*64;     // split-K (m,l) [16][HH][128][2]
constexpr size_t TOTF    = OFF_ML  + (size_t)16*HH*128*2;

__device__ float g_bufF[TOTF];

constexpr int IOFF_CNT  = 0;
constexpr int IOFF_OFFS = 16;
constexpr int IOFF_CUR  = 33;
constexpr int IOFF_PERM = 64;
constexpr int IOFF_SLOT = 64 + TT*TOPK;
constexpr int TOTI      = 64 + 2*TT*TOPK;
__device__ int g_bufI[TOTI];

// ---------------- tf32 mma helpers ----------------
__device__ __forceinline__ unsigned f2tf32(float x) {
    unsigned u; asm("cvt.rna.tf32.f32 %0, %1;" : "=r"(u) : "f"(x)); return u;
}
__device__ __forceinline__ void mma8(float* c, const unsigned* a, const unsigned* b) {
    asm volatile("mma.sync.aligned.m16n8k8.row.col.f32.tf32.tf32.f32 "
        "{%0,%1,%2,%3},{%4,%5,%6,%7},{%8,%9},{%0,%1,%2,%3};"
        : "+f"(c[0]), "+f"(c[1]), "+f"(c[2]), "+f"(c[3])
        : "r"(a[0]), "r"(a[1]), "r"(a[2]), "r"(a[3]), "r"(b[0]), "r"(b[1]));
}
// 16B cp.async with zero-fill when invalid
__device__ __forceinline__ void cpa16(float* dst, const float* src, bool v) {
    unsigned d = (unsigned)__cvta_generic_to_shared(dst);
    int sz = v ? 16 : 0;
    asm volatile("cp.async.cg.shared.global [%0], [%1], 16, %2;" :: "r"(d), "l"(src), "r"(sz));
}
#define CPA_COMMIT() asm volatile("cp.async.commit_group;")
#define CPA_WAIT1()  asm volatile("cp.async.wait_group 1;")
#define CPA_WAIT0()  asm volatile("cp.async.wait_group 0;")

// ---------------- rmsnorm ----------------
__global__ void rmsnorm_kernel(const float* __restrict__ x, const float* __restrict__ w,
                               float* __restrict__ o) {
    int t = blockIdx.x;
    const float* xr = x + (size_t)t * DD;
    float v[4]; float s = 0.f;
    #pragma unroll
    for (int i = 0; i < 4; i++) { v[i] = xr[threadIdx.x + i*256]; s += v[i]*v[i]; }
    __shared__ float red[8];
    #pragma unroll
    for (int off = 16; off > 0; off >>= 1) s += __shfl_xor_sync(0xffffffffu, s, off);
    if ((threadIdx.x & 31) == 0) red[threadIdx.x >> 5] = s;
    __syncthreads();
    if (threadIdx.x == 0) {
        float tot = 0.f;
        #pragma unroll
        for (int i = 0; i < 8; i++) tot += red[i];
        red[0] = tot;
    }
    __syncthreads();
    float sc = rsqrtf(red[0] / (float)DD + 1e-5f);
    #pragma unroll
    for (int i = 0; i < 4; i++) {
        int d = threadIdx.x + i*256;
        o[(size_t)t*DD + d] = v[i] * sc * w[d];
    }
}

// =============== tf32 NT GEMM: C[M,N] = A[M,K] @ B[N,K]^T (+R) ===========
// BM=128 BN=128 BK=32, 256 threads (8 warps: 2 along M x 4 along N,
// each warp computes a 64x32 tile). Register-prefetch double buffering.
struct SmemNT {
    unsigned As[128][36];
    unsigned Bs[128][36];
};

__device__ __forceinline__ void gemm_nt_body(
        SmemNT& s, const float* __restrict__ A, const float* __restrict__ B,
        const float* __restrict__ R, float* __restrict__ C,
        int M, int N, int K, int row0, int col0) {
    const int tid = threadIdx.x;
    const int lane = tid & 31, w = tid >> 5;
    const int g = lane >> 2, tg = lane & 3;
    const int wm = (w & 1) * 64, wn = (w >> 1) * 32;
    const int ar = tid >> 3, ac = (tid & 7) * 4;

    const float* Ap[4]; bool va[4];
    #pragma unroll
    for (int p = 0; p < 4; p++) {
        int r = row0 + p*32 + ar;
        va[p] = r < M;
        Ap[p] = A + (size_t)(va[p] ? r : 0) * K + ac;
    }
    const float* Bp[4];
    #pragma unroll
    for (int p = 0; p < 4; p++)
        Bp[p] = B + (size_t)(col0 + p*32 + ar) * K + ac;

    #pragma unroll
    for (int p = 0; p < 4; p++) {
        float4 v = va[p] ? *(const float4*)(Ap[p]) : make_float4(0,0,0,0);
        s.As[p*32+ar][ac+0]=f2tf32(v.x); s.As[p*32+ar][ac+1]=f2tf32(v.y);
        s.As[p*32+ar][ac+2]=f2tf32(v.z); s.As[p*32+ar][ac+3]=f2tf32(v.w);
        float4 b = *(const float4*)(Bp[p]);
        s.Bs[p*32+ar][ac+0]=f2tf32(b.x); s.Bs[p*32+ar][ac+1]=f2tf32(b.y);
        s.Bs[p*32+ar][ac+2]=f2tf32(b.z); s.Bs[p*32+ar][ac+3]=f2tf32(b.w);
    }
    __syncthreads();

    float acc[4][4][4] = {};
    float4 pa[4], pb[4];
    for (int k0 = 0; k0 < K; k0 += 32) {
        bool nxt = (k0 + 32) < K;
        if (nxt) {
            #pragma unroll
            for (int p = 0; p < 4; p++) {
                pa[p] = va[p] ? *(const float4*)(Ap[p] + k0 + 32) : make_float4(0,0,0,0);
                pb[p] = *(const float4*)(Bp[p] + k0 + 32);
            }
        }
        #pragma unroll
        for (int ks = 0; ks < 4; ks++) {
            const int kb = ks*8;
            unsigned af[4][4], bf[4][2];
            #pragma unroll
            for (int i = 0; i < 4; i++) {
                af[i][0] = s.As[wm+i*16+g  ][kb+tg];
                af[i][1] = s.As[wm+i*16+8+g][kb+tg];
                af[i][2] = s.As[wm+i*16+g  ][kb+tg+4];
                af[i][3] = s.As[wm+i*16+8+g][kb+tg+4];
            }
            #pragma unroll
            for (int j = 0; j < 4; j++) {
                bf[j][0] = s.Bs[wn+j*8+g][kb+tg];
                bf[j][1] = s.Bs[wn+j*8+g][kb+tg+4];
            }
            #pragma unroll
            for (int i = 0; i < 4; i++)
                #pragma unroll
                for (int j = 0; j < 4; j++)
                    mma8(acc[i][j], af[i], bf[j]);
        }
        __syncthreads();
        if (nxt) {
            #pragma unroll
            for (int p = 0; p < 4; p++) {
                s.As[p*32+ar][ac+0]=f2tf32(pa[p].x); s.As[p*32+ar][ac+1]=f2tf32(pa[p].y);
                s.As[p*32+ar][ac+2]=f2tf32(pa[p].z); s.As[p*32+ar][ac+3]=f2tf32(pa[p].w);
                s.Bs[p*32+ar][ac+0]=f2tf32(pb[p].x); s.Bs[p*32+ar][ac+1]=f2tf32(pb[p].y);
                s.Bs[p*32+ar][ac+2]=f2tf32(pb[p].z); s.Bs[p*32+ar][ac+3]=f2tf32(pb[p].w);
            }
            __syncthreads();
        }
    }

    #pragma unroll
    for (int i = 0; i < 4; i++) {
        #pragma unroll
        for (int j = 0; j < 4; j++) {
            int r0 = row0 + wm + i*16 + g;
            int cc = col0 + wn + j*8 + tg*2;
            if (r0 < M) {
                size_t x = (size_t)r0*N + cc;
                float v0 = acc[i][j][0], v1 = acc[i][j][1];
                if (R) { v0 += R[x]; v1 += R[x+1]; }
                C[x] = v0; C[x+1] = v1;
            }
            int r1 = r0 + 8;
            if (r1 < M) {
                size_t x = (size_t)r1*N + cc;
                float v2 = acc[i][j][2], v3 = acc[i][j][3];
                if (R) { v2 += R[x]; v3 += R[x+1]; }
                C[x] = v2; C[x+1] = v3;
            }
        }
    }
}

__global__ __launch_bounds__(256) void gemm_tf32_nt(
        const float* __restrict__ A, const float* __restrict__ B,
        const float* __restrict__ R, float* __restrict__ C, int M, int N, int K) {
    __shared__ SmemNT s;
    gemm_nt_body(s, A, B, R, C, M, N, K, blockIdx.y * 128, blockIdx.x * 128);
}

// =============== shared expert up + SiLU gate (dual-B tf32 NT) ============
__global__ __launch_bounds__(256) void shared_up_gate_tf32(
        const float* __restrict__ A, const float* __restrict__ B,
        float* __restrict__ gt) {
    __shared__ unsigned As[128][36];
    __shared__ unsigned B1s[64][36];
    __shared__ unsigned B2s[64][36];
    const int row0 = blockIdx.y * 128, col0 = blockIdx.x * 64;
    const int tid = threadIdx.x;
    const int lane = tid & 31, w = tid >> 5;
    const int g = lane >> 2, tg = lane & 3;
    const int wm = (w & 3) * 32, wn = (w >> 2) * 32;
    const int ar = tid >> 3, ac = (tid & 7) * 4;

    const float* Ap[4];
    #pragma unroll
    for (int p = 0; p < 4; p++)
        Ap[p] = A + (size_t)(row0 + p*32 + ar) * DD + ac;
    const float* B1p[2]; const float* B2p[2];
    #pragma unroll
    for (int p = 0; p < 2; p++) {
        B1p[p] = B + (size_t)(col0 + p*32 + ar) * DD + ac;
        B2p[p] = B + (size_t)(DSH + col0 + p*32 + ar) * DD + ac;
    }

    #pragma unroll
    for (int p = 0; p < 4; p++) {
        float4 v = *(const float4*)(Ap[p]);
        As[p*32+ar][ac+0]=f2tf32(v.x); As[p*32+ar][ac+1]=f2tf32(v.y);
        As[p*32+ar][ac+2]=f2tf32(v.z); As[p*32+ar][ac+3]=f2tf32(v.w);
    }
    #pragma unroll
    for (int p = 0; p < 2; p++) {
        float4 v1 = *(const float4*)(B1p[p]);
        float4 v2 = *(const float4*)(B2p[p]);
        B1s[p*32+ar][ac+0]=f2tf32(v1.x); B1s[p*32+ar][ac+1]=f2tf32(v1.y);
        B1s[p*32+ar][ac+2]=f2tf32(v1.z); B1s[p*32+ar][ac+3]=f2tf32(v1.w);
        B2s[p*32+ar][ac+0]=f2tf32(v2.x); B2s[p*32+ar][ac+1]=f2tf32(v2.y);
        B2s[p*32+ar][ac+2]=f2tf32(v2.z); B2s[p*32+ar][ac+3]=f2tf32(v2.w);
    }
    __syncthreads();

    float acc1[2][4][4] = {}, acc2[2][4][4] = {};
    float4 pa[4], pb1[2], pb2[2];
    for (int k0 = 0; k0 < DD; k0 += 32) {
        bool nxt = (k0 + 32) < DD;
        if (nxt) {
            #pragma unroll
            for (int p = 0; p < 4; p++) pa[p] = *(const float4*)(Ap[p] + k0 + 32);
            #pragma unroll
            for (int p = 0; p < 2; p++) {
                pb1[p] = *(const float4*)(B1p[p] + k0 + 32);
                pb2[p] = *(const float4*)(B2p[p] + k0 + 32);
            }
        }
        #pragma unroll
        for (int ks = 0; ks < 4; ks++) {
            const int kb = ks*8;
            unsigned af[2][4], bf1[4][2], bf2[4][2];
            #pragma unroll
            for (int i = 0; i < 2; i++) {
                af[i][0] = As[wm+i*16+g  ][kb+tg];
                af[i][1] = As[wm+i*16+8+g][kb+tg];
                af[i][2] = As[wm+i*16+g  ][kb+tg+4];
                af[i][3] = As[wm+i*16+8+g][kb+tg+4];
            }
            #pragma unroll
            for (int j = 0; j < 4; j++) {
                bf1[j][0] = B1s[wn+j*8+g][kb+tg];
                bf1[j][1] = B1s[wn+j*8+g][kb+tg+4];
                bf2[j][0] = B2s[wn+j*8+g][kb+tg];
                bf2[j][1] = B2s[wn+j*8+g][kb+tg+4];
            }
            #pragma unroll
            for (int i = 0; i < 2; i++)
                #pragma unroll
                for (int j = 0; j < 4; j++) {
                    mma8(acc1[i][j], af[i], bf1[j]);
                    mma8(acc2[i][j], af[i], bf2[j]);
                }
        }
        __syncthreads();
        if (nxt) {
            #pragma unroll
            for (int p = 0; p < 4; p++) {
                As[p*32+ar][ac+0]=f2tf32(pa[p].x); As[p*32+ar][ac+1]=f2tf32(pa[p].y);
                As[p*32+ar][ac+2]=f2tf32(pa[p].z); As[p*32+ar][ac+3]=f2tf32(pa[p].w);
            }
            #pragma unroll
            for (int p = 0; p < 2; p++) {
                B1s[p*32+ar][ac+0]=f2tf32(pb1[p].x); B1s[p*32+ar][ac+1]=f2tf32(pb1[p].y);
                B1s[p*32+ar][ac+2]=f2tf32(pb1[p].z); B1s[p*32+ar][ac+3]=f2tf32(pb1[p].w);
                B2s[p*32+ar][ac+0]=f2tf32(pb2[p].x); B2s[p*32+ar][ac+1]=f2tf32(pb2[p].y);
                B2s[p*32+ar][ac+2]=f2tf32(pb2[p].z); B2s[p*32+ar][ac+3]=f2tf32(pb2[p].w);
            }
            __syncthreads();
        }
    }

    #pragma unroll
    for (int i = 0; i < 2; i++) {
        #pragma unroll
        for (int j = 0; j < 4; j++) {
            int r0 = row0 + wm + i*16 + g;
            int cc = col0 + wn + j*8 + tg*2;
            #pragma unroll
            for (int half = 0; half < 2; half++) {
                int r = r0 + half*8;
                float h1a = acc1[i][j][half*2+0], h2a = acc2[i][j][half*2+0];
                float h1b = acc1[i][j][half*2+1], h2b = acc2[i][j][half*2+1];
                float sa = 1.f / (1.f + __expf(-h1a));
                float sb = 1.f / (1.f + __expf(-h1b));
                size_t x = (size_t)r * DSH + cc;
                gt[x]   = h1a * sa * h2a;
                gt[x+1] = h1b * sb * h2b;
            }
        }
    }
}

// ---------------- RoPE (in-place on q,k within qkv buffer) ----------------
__global__ void rope_kernel(float* __restrict__ qkv) {
    int idx = blockIdx.x * blockDim.x + threadIdx.x;
    const int total = 2 * TT * HH * 32;
    if (idx >= total) return;
    int which = idx / (TT * HH * 32);
    int rem   = idx % (TT * HH * 32);
    int t = rem / (HH * 32);
    int r2 = rem % (HH * 32);
    int h = r2 >> 5, i = r2 & 31;
    size_t base = (size_t)t * QKV3 + (size_t)which * DD + h * HDIM;
    float invf = (float)exp(-9.210340371976184 * ((double)i / 32.0));
    float fr = (float)t * invf;
    float c = (float)cos((double)fr);
    float s = (float)sin((double)fr);
    float x1 = qkv[base + i];
    float x2 = qkv[base + 32 + i];
    qkv[base + i]      =  x1 * c + x2 * s;
    qkv[base + 32 + i] = -x1 * s + x2 * c;
}

// =============== flash attention v5: split-K heavy blocks ================
// Work units: qb<8 unsplit; qb>=8 split into two equal K-halves emitting
// unnormalized acc + (m,l); merge kernel combines exactly.
// 24 units/head, max 16 k-tiles each (vs 32 unsplit worst-case).
#define KSTR 68
#define VSTR 72
constexpr int ATTN_STAGE = 64*KSTR + 64*VSTR;
constexpr int ATTN_SMEM  = 2 * ATTN_STAGE * (int)sizeof(float);  // 71680 B

// {qb, kb0, kb1, su}; su = -1 unsplit, else (qb-8)*2+half. Sorted heavy-first.
__device__ __constant__ int4 c_units[24] = {
    {15,  0, 15, 14}, {15, 16, 31, 15}, { 7,  0, 15, -1},
    {14,  0, 14, 12}, {14, 15, 29, 13}, {13,  0, 13, 10},
    {13, 14, 27, 11}, { 6,  0, 13, -1}, {12,  0, 12,  8},
    {12, 13, 25,  9}, {11,  0, 11,  6}, {11, 12, 23,  7},
    { 5,  0, 11, -1}, {10,  0, 10,  4}, {10, 11, 21,  5},
    { 9,  0,  9,  2}, { 9, 10, 19,  3}, { 4,  0,  9, -1},
    { 8,  0,  8,  0}, { 8,  9, 17,  1}, { 3,  0,  7, -1},
    { 2,  0,  5, -1}, { 1,  0,  3, -1}, { 0,  0,  1, -1}
};

__global__ __launch_bounds__(256, 2) void attn_kernel(const float* __restrict__ qkv,
                                                      float* __restrict__ o,
                                                      float* __restrict__ pacc,
                                                      float* __restrict__ pml) {
    extern __shared__ float smf[];

    const int4 u = c_units[blockIdx.y];
    const int qb = u.x, kb0 = u.y, kb1 = u.z, su = u.w;
    const int h = blockIdx.x;                 // heads fastest -> heavy units first
    const int tid = threadIdx.x;
    const int lane = tid & 31, w = tid >> 5;
    const int g = lane >> 2, tg = lane & 3;
    const bool odd = tg & 1;
    const int s0 = tg >> 1, s1 = 2 + (tg >> 1);

    { // stage Q tile [128][64] raw fp32
        int qi = tid >> 1, d0 = (tid & 1) * 32;
        const float* src = qkv + (size_t)(qb*128 + qi) * QKV3 + h * HDIM + d0;
        #pragma unroll
        for (int c = 0; c < 32; c += 4) {
            float4 v = *(const float4*)(src + c);
            smf[qi*KSTR + d0+c+0] = v.x; smf[qi*KSTR + d0+c+1] = v.y;
            smf[qi*KSTR + d0+c+2] = v.z; smf[qi*KSTR + d0+c+3] = v.w;
        }
    }
    __syncthreads();
    unsigned aq[8][4];
    {
        int r0 = 16*w + g;
        #pragma unroll
        for (int kk = 0; kk < 8; kk++) {
            aq[kk][0] = f2tf32(smf[(r0  )*KSTR + 8*kk + tg]);
            aq[kk][1] = f2tf32(smf[(r0+8)*KSTR + 8*kk + tg]);
            aq[kk][2] = f2tf32(smf[(r0  )*KSTR + 8*kk + tg + 4]);
            aq[kk][3] = f2tf32(smf[(r0+8)*KSTR + 8*kk + tg + 4]);
        }
    }
    __syncthreads();

    const int lki = tid >> 2, ld0 = (tid & 3) * 16;

    { // preload stage 0 (kb = kb0)
        float* Ks = smf;
        float* Vs = smf + 64*KSTR;
        const float* kp = qkv + (size_t)(kb0*64 + lki) * QKV3 + DD   + h*HDIM + ld0;
        const float* vp = qkv + (size_t)(kb0*64 + lki) * QKV3 + 2*DD + h*HDIM + ld0;
        #pragma unroll
        for (int c = 0; c < 16; c += 4) {
            cpa16(Ks + lki*KSTR + ld0 + c, kp + c, true);
            cpa16(Vs + lki*VSTR + ld0 + c, vp + c, true);
        }
        CPA_COMMIT();
    }

    float m0 = -INFINITY, m1 = -INFINITY, l0 = 0.f, l1 = 0.f;
    float acco[8][4] = {};
    const int qg0 = qb*128 + 16*w + g;
    const int qg1 = qg0 + 8;

    for (int kb = kb0; kb <= kb1; kb++) {
        const int st = (kb - kb0) & 1;
        const float* Ks = smf + st * ATTN_STAGE;
        const float* Vs = Ks + 64*KSTR;
        if (kb < kb1) {
            float* Kn = smf + (st^1) * ATTN_STAGE;
            float* Vn = Kn + 64*KSTR;
            const float* kp = qkv + (size_t)((kb+1)*64 + lki) * QKV3 + DD   + h*HDIM + ld0;
            const float* vp = qkv + (size_t)((kb+1)*64 + lki) * QKV3 + 2*DD + h*HDIM + ld0;
            #pragma unroll
            for (int c = 0; c < 16; c += 4) {
                cpa16(Kn + lki*KSTR + ld0 + c, kp + c, true);
                cpa16(Vn + lki*VSTR + ld0 + c, vp + c, true);
            }
            CPA_COMMIT();
            CPA_WAIT1();
        } else {
            CPA_WAIT0();
        }
        __syncthreads();

        // S = Q @ K^T
        float sf[8][4] = {};
        #pragma unroll
        for (int kk = 0; kk < 8; kk++) {
            #pragma unroll
            for (int j = 0; j < 8; j++) {
                unsigned b[2] = { __float_as_uint(Ks[(8*j+g)*KSTR + 8*kk + tg]),
                                  __float_as_uint(Ks[(8*j+g)*KSTR + 8*kk + tg + 4]) };
                mma8(sf[j], aq[kk], b);
            }
        }
        // scale + causal mask + register softmax
        float vmax0 = -1e30f, vmax1 = -1e30f;
        #pragma unroll
        for (int j = 0; j < 8; j++) {
            int kg = kb*64 + 8*j + 2*tg;
            sf[j][0] = (kg   > qg0) ? -1e30f : sf[j][0]*0.125f;
            sf[j][1] = (kg+1 > qg0) ? -1e30f : sf[j][1]*0.125f;
            sf[j][2] = (kg   > qg1) ? -1e30f : sf[j][2]*0.125f;
            sf[j][3] = (kg+1 > qg1) ? -1e30f : sf[j][3]*0.125f;
            vmax0 = fmaxf(vmax0, fmaxf(sf[j][0], sf[j][1]));
            vmax1 = fmaxf(vmax1, fmaxf(sf[j][2], sf[j][3]));
        }
        vmax0 = fmaxf(vmax0, __shfl_xor_sync(0xffffffffu, vmax0, 1));
        vmax0 = fmaxf(vmax0, __shfl_xor_sync(0xffffffffu, vmax0, 2));
        vmax1 = fmaxf(vmax1, __shfl_xor_sync(0xffffffffu, vmax1, 1));
        vmax1 = fmaxf(vmax1, __shfl_xor_sync(0xffffffffu, vmax1, 2));
        float mn0 = fmaxf(m0, vmax0), mn1 = fmaxf(m1, vmax1);
        float al0 = __expf(m0 - mn0), al1 = __expf(m1 - mn1);
        float ps0 = 0.f, ps1 = 0.f;
        #pragma unroll
        for (int j = 0; j < 8; j++) {
            sf[j][0] = __expf(sf[j][0] - mn0); ps0 += sf[j][0];
            sf[j][1] = __expf(sf[j][1] - mn0); ps0 += sf[j][1];
            sf[j][2] = __expf(sf[j][2] - mn1); ps1 += sf[j][2];
            sf[j][3] = __expf(sf[j][3] - mn1); ps1 += sf[j][3];
        }
        ps0 += __shfl_xor_sync(0xffffffffu, ps0, 1);
        ps0 += __shfl_xor_sync(0xffffffffu, ps0, 2);
        ps1 += __shfl_xor_sync(0xffffffffu, ps1, 1);
        ps1 += __shfl_xor_sync(0xffffffffu, ps1, 2);
        l0 = l0*al0 + ps0; l1 = l1*al1 + ps1;
        m0 = mn0; m1 = mn1;
        #pragma unroll
        for (int jd = 0; jd < 8; jd++) {
            acco[jd][0] *= al0; acco[jd][1] *= al0;
            acco[jd][2] *= al1; acco[jd][3] *= al1;
        }
        // O += P @ V
        #pragma unroll
        for (int j = 0; j < 8; j++) {
            float q00 = __shfl_sync(0xffffffffu, sf[j][0], s0, 4);
            float q01 = __shfl_sync(0xffffffffu, sf[j][1], s0, 4);
            float q10 = __shfl_sync(0xffffffffu, sf[j][2], s0, 4);
            float q11 = __shfl_sync(0xffffffffu, sf[j][3], s0, 4);
            float r00 = __shfl_sync(0xffffffffu, sf[j][0], s1, 4);
            float r01 = __shfl_sync(0xffffffffu, sf[j][1], s1, 4);
            float r10 = __shfl_sync(0xffffffffu, sf[j][2], s1, 4);
            float r11 = __shfl_sync(0xffffffffu, sf[j][3], s1, 4);
            unsigned a[4];
            a[0] = f2tf32(odd ? q01 : q00);
            a[1] = f2tf32(odd ? q11 : q10);
            a[2] = f2tf32(odd ? r01 : r00);
            a[3] = f2tf32(odd ? r11 : r10);
            #pragma unroll
            for (int jd = 0; jd < 8; jd++) {
                unsigned b[2] = { __float_as_uint(Vs[(8*j+tg  )*VSTR + 8*jd + g]),
                                  __float_as_uint(Vs[(8*j+tg+4)*VSTR + 8*jd + g]) };
                mma8(acco[jd], a, b);
            }
        }
        __syncthreads();
    }

    if (su < 0) { // unsplit: normalize and write
        float i0 = 1.f / l0, i1 = 1.f / l1;
        #pragma unroll
        for (int jd = 0; jd < 8; jd++) {
            int col = h*HDIM + 8*jd + 2*tg;
            o[(size_t)qg0*DD + col  ] = acco[jd][0]*i0;
            o[(size_t)qg0*DD + col+1] = acco[jd][1]*i0;
            o[(size_t)qg1*DD + col  ] = acco[jd][2]*i1;
            o[(size_t)qg1*DD + col+1] = acco[jd][3]*i1;
        }
    } else { // split half: write unnormalized acc + (m,l)
        float* pa = pacc + ((size_t)su*HH + h) * 128 * 64;
        int r0 = 16*w + g, r1 = r0 + 8;
        #pragma unroll
        for (int jd = 0; jd < 8; jd++) {
            int col = 8*jd + 2*tg;
            pa[(size_t)r0*64 + col  ] = acco[jd][0];
            pa[(size_t)r0*64 + col+1] = acco[jd][1];
            pa[(size_t)r1*64 + col  ] = acco[jd][2];
            pa[(size_t)r1*64 + col+1] = acco[jd][3];
        }
        if (tg == 0) {
            float* ml = pml + ((size_t)su*HH + h) * 128 * 2;
            ml[r0*2+0] = m0; ml[r0*2+1] = l0;
            ml[r1*2+0] = m1; ml[r1*2+1] = l1;
        }
    }
}

// merge split halves: o = (eA*accA + eB*accB) / (eA*lA + eB*lB)
__global__ void attn_merge(const float* __restrict__ pacc, const float* __restrict__ pml,
                           float* __restrict__ o) {
    const int sp = blockIdx.x;          // 0..7 -> qb = 8+sp
    const int h  = blockIdx.y;
    const int suA = sp*2, suB = suA+1;
    const int qb = 8 + sp;
    const int r  = threadIdx.x >> 1;    // 0..127
    const int c0 = (threadIdx.x & 1) * 32;
    const float* mlA = pml + ((size_t)suA*HH + h) * 128 * 2;
    const float* mlB = pml + ((size_t)suB*HH + h) * 128 * 2;
    float mA = mlA[r*2+0], lA = mlA[r*2+1];
    float mB = mlB[r*2+0], lB = mlB[r*2+1];
    float mm = fmaxf(mA, mB);
    float eA = __expf(mA - mm), eB = __expf(mB - mm);
    float inv = 1.f / (eA*lA + eB*lB);
    const float* pA = pacc + ((size_t)suA*HH + h) * 128 * 64 + (size_t)r * 64;
    const float* pB = pacc + ((size_t)suB*HH + h) * 128 * 64 + (size_t)r * 64;
    float* orow = o + (size_t)(qb*128 + r) * DD + h * HDIM;
    #pragma unroll
    for (int c = 0; c < 32; c += 4) {
        float4 a = *(const float4*)(pA + c0 + c);
        float4 b = *(const float4*)(pB + c0 + c);
        float4 v;
        v.x = (eA*a.x + eB*b.x) * inv;
        v.y = (eA*a.y + eB*b.y) * inv;
        v.z = (eA*a.z + eB*b.z) * inv;
        v.w = (eA*a.w + eB*b.w) * inv;
        *(float4*)(orow + c0 + c) = v;
    }
}

// ---------------- router ----------------
__global__ void router_kernel(const float* __restrict__ xffn, const float* __restrict__ mk,
                              const float* __restrict__ bias, const int* __restrict__ indices,
                              const float* __restrict__ values, float* __restrict__ scores) {
    int t = blockIdx.x;
    __shared__ float red[128 * NEXP];
    float partial[NEXP];
    #pragma unroll
    for (int e = 0; e < NEXP; e++) partial[e] = 0.f;
    for (int d = threadIdx.x; d < DD; d += 128) {
        float xv = xffn[(size_t)t*DD + d];
        const float* mrow = mk + (size_t)d * NEXP;
        #pragma unroll
        for (int e = 0; e < NEXP; e++) partial[e] += xv * mrow[e];
    }
    #pragma unroll
    for (int e = 0; e < NEXP; e++) red[threadIdx.x*NEXP + e] = partial[e];
    __syncthreads();
    for (int s = 64; s >= 1; s >>= 1) {
        if (threadIdx.x < s)
            #pragma unroll
            for (int e = 0; e < NEXP; e++)
                red[threadIdx.x*NEXP + e] += red[(threadIdx.x+s)*NEXP + e];
        __syncthreads();
    }
    if (threadIdx.x == 0) {
        int i0 = indices[t*2+0], i1 = indices[t*2+1];
        float v0 = values[t*2+0] + red[i0] + bias[i0];
        float v1 = values[t*2+1] + red[i1] + bias[i1];
        float m = fmaxf(v0, v1);
        float e0 = __expf(v0 - m), e1 = __expf(v1 - m);
        float inv = 1.f / (e0 + e1);
        scores[t*2+0] = e0 * inv;
        scores[t*2+1] = e1 * inv;
    }
}

// ---------------- routing build ----------------
__global__ void route_init(int* counts) { if (threadIdx.x < NEXP) counts[threadIdx.x] = 0; }
__global__ void route_count(const int* __restrict__ indices, int* counts) {
    int i = blockIdx.x * blockDim.x + threadIdx.x;
    if (i < TT*TOPK) atomicAdd(&counts[indices[i]], 1);
}
__global__ void route_scan(const int* __restrict__ counts, int* offsets, int* cursor) {
    if (threadIdx.x == 0) {
        int off = 0;
        for (int e = 0; e < NEXP; e++) { offsets[e] = off; cursor[e] = off; off += counts[e]; }
        offsets[NEXP] = off;
    }
}
__global__ void route_scatter(const int* __restrict__ indices, int* cursor,
                              int* __restrict__ perm, int* __restrict__ slotpos) {
    int i = blockIdx.x * blockDim.x + threadIdx.x;
    if (i < TT*TOPK) {
        int e = indices[i];
        int p = atomicAdd(&cursor[e], 1);
        perm[p] = i >> 1;
        slotpos[i] = p;
    }
}

// =============== expert up (tf32): g = silu(x@W1) * (x@W2), gathered A ====
__global__ __launch_bounds__(256) void expert_up_tf32(
        const float* __restrict__ xffn, const float* __restrict__ experts,
        const int* __restrict__ counts, const int* __restrict__ offsets,
        const int* __restrict__ perm, float* __restrict__ g_out) {
    const int e = blockIdx.z;
    const int M = counts[e];
    const int row0 = blockIdx.y * 64;
    if (row0 >= M) return;
    const int off = offsets[e];
    const float* B1 = experts + (size_t)e * DD * EDIM;
    const float* B2 = experts + ((size_t)NEXP + e) * DD * EDIM;
    const int col0 = blockIdx.x * 64;

    __shared__ unsigned As[64][36];
    __shared__ unsigned B1s[32][72];
    __shared__ unsigned B2s[32][72];

    const int tid = threadIdx.x;
    const int lane = tid & 31, w = tid >> 5;
    const int g = lane >> 2, tg = lane & 3;
    const int wm = (w & 1) * 32, wn = (w >> 1) * 16;
    const int ar = tid >> 3, ac = (tid & 7) * 4;
    const int bkr = tid >> 4, bnc = (tid & 15) * 4;

    const float* Ap[2]; bool va[2];
    #pragma unroll
    for (int p = 0; p < 2; p++) {
        int r = row0 + p*32 + ar;
        va[p] = r < M;
        int tok = va[p] ? perm[off + r] : 0;
        Ap[p] = xffn + (size_t)tok * DD + ac;
    }
    const float* B1p[2]; const float* B2p[2];
    #pragma unroll
    for (int p = 0; p < 2; p++) {
        B1p[p] = B1 + (size_t)(p*16 + bkr) * EDIM + col0 + bnc;
        B2p[p] = B2 + (size_t)(p*16 + bkr) * EDIM + col0 + bnc;
    }

    #pragma unroll
    for (int p = 0; p < 2; p++) {
        float4 v = va[p] ? *(const float4*)(Ap[p]) : make_float4(0,0,0,0);
        As[p*32+ar][ac+0]=f2tf32(v.x); As[p*32+ar][ac+1]=f2tf32(v.y);
        As[p*32+ar][ac+2]=f2tf32(v.z); As[p*32+ar][ac+3]=f2tf32(v.w);
    }
    #pragma unroll
    for (int p = 0; p < 2; p++) {
        float4 v1 = *(const float4*)(B1p[p]);
        float4 v2 = *(const float4*)(B2p[p]);
        B1s[p*16+bkr][bnc+0]=f2tf32(v1.x); B1s[p*16+bkr][bnc+1]=f2tf32(v1.y);
        B1s[p*16+bkr][bnc+2]=f2tf32(v1.z); B1s[p*16+bkr][bnc+3]=f2tf32(v1.w);
        B2s[p*16+bkr][bnc+0]=f2tf32(v2.x); B2s[p*16+bkr][bnc+1]=f2tf32(v2.y);
        B2s[p*16+bkr][bnc+2]=f2tf32(v2.z); B2s[p*16+bkr][bnc+3]=f2tf32(v2.w);
    }
    __syncthreads();

    float acc1[2][2][4] = {}, acc2[2][2][4] = {};
    float4 pa[2], pb1[2], pb2[2];
    for (int k0 = 0; k0 < DD; k0 += 32) {
        bool nxt = (k0 + 32) < DD;
        if (nxt) {
            #pragma unroll
            for (int p = 0; p < 2; p++)
                pa[p] = va[p] ? *(const float4*)(Ap[p] + k0 + 32) : make_float4(0,0,0,0);
            #pragma unroll
            for (int p = 0; p < 2; p++) {
                pb1[p] = *(const float4*)(B1p[p] + (size_t)(k0 + 32) * EDIM);
                pb2[p] = *(const float4*)(B2p[p] + (size_t)(k0 + 32) * EDIM);
            }
        }
        #pragma unroll
        for (int ks = 0; ks < 4; ks++) {
            const int kb = ks*8;
            unsigned af[2][4], bf1[2][2], bf2[2][2];
            #pragma unroll
            for (int i = 0; i < 2; i++) {
                af[i][0] = As[wm+i*16+g  ][kb+tg];
                af[i][1] = As[wm+i*16+8+g][kb+tg];
                af[i][2] = As[wm+i*16+g  ][kb+tg+4];
                af[i][3] = As[wm+i*16+8+g][kb+tg+4];
            }
            #pragma unroll
            for (int j = 0; j < 2; j++) {
                bf1[j][0] = B1s[kb+tg  ][wn+j*8+g];
                bf1[j][1] = B1s[kb+tg+4][wn+j*8+g];
                bf2[j][0] = B2s[kb+tg  ][wn+j*8+g];
                bf2[j][1] = B2s[kb+tg+4][wn+j*8+g];
            }
            #pragma unroll
            for (int i = 0; i < 2; i++)
                #pragma unroll
                for (int j = 0; j < 2; j++) {
                    mma8(acc1[i][j], af[i], bf1[j]);
                    mma8(acc2[i][j], af[i], bf2[j]);
                }
        }
        __syncthreads();
        if (nxt) {
            #pragma unroll
            for (int p = 0; p < 2; p++) {
                As[p*32+ar][ac+0]=f2tf32(pa[p].x); As[p*32+ar][ac+1]=f2tf32(pa[p].y);
                As[p*32+ar][ac+2]=f2tf32(pa[p].z); As[p*32+ar][ac+3]=f2tf32(pa[p].w);
            }
            #pragma unroll
            for (int p = 0; p < 2; p++) {
                B1s[p*16+bkr][bnc+0]=f2tf32(pb1[p].x); B1s[p*16+bkr][bnc+1]=f2tf32(pb1[p].y);
                B1s[p*16+bkr][bnc+2]=f2tf32(pb1[p].z); B1s[p*16+bkr][bnc+3]=f2tf32(pb1[p].w);
                B2s[p*16+bkr][bnc+0]=f2tf32(pb2[p].x); B2s[p*16+bkr][bnc+1]=f2tf32(pb2[p].y);
                B2s[p*16+bkr][bnc+2]=f2tf32(pb2[p].z); B2s[p*16+bkr][bnc+3]=f2tf32(pb2[p].w);
            }
            __syncthreads();
        }
    }

    #pragma unroll
    for (int i = 0; i < 2; i++) {
        #pragma unroll
        for (int j = 0; j < 2; j++) {
            int r0 = row0 + wm + i*16 + g;
            int cc = col0 + wn + j*8 + tg*2;
            #pragma unroll
            for (int half = 0; half < 2; half++) {
                int r = r0 + half*8;
                if (r < M) {
                    float h1a = acc1[i][j][half*2+0], h2a = acc2[i][j][half*2+0];
                    float h1b = acc1[i][j][half*2+1], h2b = acc2[i][j][half*2+1];
                    float sa = 1.f / (1.f + __expf(-h1a));
                    float sb = 1.f / (1.f + __expf(-h1b));
                    size_t x = (size_t)(off + r) * EDIM + cc;
                    g_out[x]   = h1a * sa * h2a;
                    g_out[x+1] = h1b * sb * h2b;
                }
            }
        }
    }
}

// =============== expert down (tf32 NT): yp = g @ W3^T, per-expert slabs ===
__global__ __launch_bounds__(256) void expert_down_tf32(
        const float* __restrict__ gbuf, const float* __restrict__ experts,
        const int* __restrict__ counts, const int* __restrict__ offsets,
        float* __restrict__ yp) {
    const int e = blockIdx.z;
    const int M = counts[e];
    const int row0 = blockIdx.y * 128;
    if (row0 >= M) return;
    const int off = offsets[e];
    __shared__ SmemNT s;
    gemm_nt_body(s,
                 gbuf + (size_t)off * EDIM,
                 experts + (2*(size_t)NEXP + e) * DD * EDIM,
                 nullptr,
                 yp + (size_t)off * DD,
                 M, DD, EDIM, row0, blockIdx.x * 128);
}

// ---- final: out = (s0*yp[p0]+s1*yp[p1])*coeff + rmsnorm(ysh)*w + xfi ----
__global__ void final_kernel(const float* __restrict__ yp, const float* __restrict__ scores,
                             const int* __restrict__ slotpos, const float* __restrict__ coeff,
                             const float* __restrict__ ysh, const float* __restrict__ shw,
                             const float* __restrict__ xfi, float* __restrict__ out) {
    int t = blockIdx.x;
    const float* yr = ysh + (size_t)t * DD;
    float v[4]; float s = 0.f;
    #pragma unroll
    for (int i = 0; i < 4; i++) { v[i] = yr[threadIdx.x + i*256]; s += v[i]*v[i]; }
    __shared__ float red[8];
    #pragma unroll
    for (int off = 16; off > 0; off >>= 1) s += __shfl_xor_sync(0xffffffffu, s, off);
    if ((threadIdx.x & 31) == 0) red[threadIdx.x >> 5] = s;
    __syncthreads();
    if (threadIdx.x == 0) {
        float tot = 0.f;
        #pragma unroll
        for (int i = 0; i < 8; i++) tot += red[i];
        red[0] = tot;
    }
    __syncthreads();
    float sc = rsqrtf(red[0] / (float)DD + 1e-5f);
    float s0 = scores[t*2+0], s1 = scores[t*2+1];
    int p0 = slotpos[t*2+0], p1 = slotpos[t*2+1];
    const float* r0 = yp + (size_t)p0 * DD;
    const float* r1 = yp + (size_t)p1 * DD;
    #pragma unroll
    for (int i = 0; i < 4; i++) {
        int d = threadIdx.x + i*256;
        size_t idx = (size_t)t*DD + d;
        out[idx] = (s0*r0[d] + s1*r1[d]) * coeff[d] + v[i]*sc*shw[d] + xfi[idx];
    }
}

// ---------------- launch ----------------
extern "C" void kernel_launch(void* const* d_in, const int* in_sizes, int n_in,
                              void* d_out, int out_size) {
    const float* x_input     = (const float*)d_in[0];
    const int*   indices     = (const int*)  d_in[1];
    const float* values      = (const float*)d_in[2];
    const float* attn_w      = (const float*)d_in[3];
    const float* attn_o_w    = (const float*)d_in[4];
    const float* attn_norm_w = (const float*)d_in[5];
    const float* ffn_norm_w  = (const float*)d_in[6];
    const float* ffn_experts = (const float*)d_in[7];
    const float* main_keys   = (const float*)d_in[8];
    const float* main_bias   = (const float*)d_in[9];
    const float* out_coeff   = (const float*)d_in[10];
    const float* ffn_up_w    = (const float*)d_in[11];
    const float* ffn_down_w  = (const float*)d_in[12];
    const float* shared_nw   = (const float*)d_in[13];
    float* out = (float*)d_out;

    float* bufF = nullptr; int* bufI = nullptr;
    cudaGetSymbolAddress((void**)&bufF, g_bufF);
    cudaGetSymbolAddress((void**)&bufI, g_bufI);

    float* xn   = bufF + OFF_XN;
    float* qkv  = bufF + OFF_QKV;
    float* ao   = bufF + OFF_AO;
    float* xfi  = bufF + OFF_XFI;
    float* xfn  = bufF + OFF_XFN;
    float* sc   = bufF + OFF_SC;
    float* gbuf = bufF + OFF_G;
    float* yp   = bufF + OFF_YP;
    float* gt   = bufF + OFF_GT;
    float* ys   = bufF + OFF_YS;
    float* pac  = bufF + OFF_PAC;
    float* pml  = bufF + OFF_ML;

    int* cnt  = bufI + IOFF_CNT;
    int* offs = bufI + IOFF_OFFS;
    int* cur  = bufI + IOFF_CUR;
    int* perm = bufI + IOFF_PERM;
    int* slot = bufI + IOFF_SLOT;

    cudaFuncSetAttribute(attn_kernel, cudaFuncAttributeMaxDynamicSharedMemorySize, ATTN_SMEM);

    // fork/join resources — created AND destroyed within this call
    cudaStream_t s_r, s_s;
    cudaEvent_t ev_fork, ev_r, ev_s;
    cudaStreamCreateWithFlags(&s_r, cudaStreamNonBlocking);
    cudaStreamCreateWithFlags(&s_s, cudaStreamNonBlocking);
    cudaEventCreateWithFlags(&ev_fork, cudaEventDisableTiming);
    cudaEventCreateWithFlags(&ev_r,    cudaEventDisableTiming);
    cudaEventCreateWithFlags(&ev_s,    cudaEventDisableTiming);

    // ---- serial prefix (default stream) ----
    rmsnorm_kernel<<<TT, 256>>>(x_input, attn_norm_w, xn);
    gemm_tf32_nt<<<dim3(QKV3/128, TT/128), 256>>>(xn, attn_w, nullptr, qkv, TT, QKV3, DD);
    rope_kernel<<<(2*TT*HH*32 + 255)/256, 256>>>(qkv);
    // attention: 24 split-K work units per head (heads fastest -> heavy first)
    attn_kernel<<<dim3(HH, 24), 256, ATTN_SMEM>>>(qkv, ao, pac, pml);
    attn_merge<<<dim3(8, HH), 256>>>(pac, pml, ao);
    gemm_tf32_nt<<<dim3(DD/128, TT/128), 256>>>(ao, attn_o_w, x_input, xfi, TT, DD, DD);
    rmsnorm_kernel<<<TT, 256>>>(xfi, ffn_norm_w, xfn);

    // ---- fork: routed experts (s_r) || shared expert (s_s) ----
    cudaEventRecord(ev_fork, 0);
    cudaStreamWaitEvent(s_r, ev_fork, 0);
    cudaStreamWaitEvent(s_s, ev_fork, 0);

    // routed chain on s_r
    router_kernel<<<TT, 128, 0, s_r>>>(xfn, main_keys, main_bias, indices, values, sc);
    route_init<<<1, 32, 0, s_r>>>(cnt);
    route_count<<<(TT*TOPK + 255)/256, 256, 0, s_r>>>(indices, cnt);
    route_scan<<<1, 32, 0, s_r>>>(cnt, offs, cur);
    route_scatter<<<(TT*TOPK + 255)/256, 256, 0, s_r>>>(indices, cur, perm, slot);
    expert_up_tf32<<<dim3(EDIM/64, (TT*TOPK)/64, NEXP), 256, 0, s_r>>>(xfn, ffn_experts, cnt, offs, perm, gbuf);
    expert_down_tf32<<<dim3(DD/128, (TT*TOPK)/128, NEXP), 256, 0, s_r>>>(gbuf, ffn_experts, cnt, offs, yp);
    cudaEventRecord(ev_r, s_r);

    // shared chain on s_s
    shared_up_gate_tf32<<<dim3(DSH/64, TT/128), 256, 0, s_s>>>(xfn, ffn_up_w, gt);
    gemm_tf32_nt<<<dim3(DD/128, TT/128), 256, 0, s_s>>>(gt, ffn_down_w, nullptr, ys, TT, DD, DSH);
    cudaEventRecord(ev_s, s_s);

    // ---- join on default stream ----
    cudaStreamWaitEvent(0, ev_r, 0);
    cudaStreamWaitEvent(0, ev_s, 0);
    // fused combine + shared-norm + residual
    final_kernel<<<TT, 256>>>(yp, sc, slot, out_coeff, ys, shared_nw, xfi, out);

    // ---- release fork/join resources (side streams already joined) ----
    cudaEventDestroy(ev_fork);
    cudaEventDestroy(ev_r);
    cudaEventDestroy(ev_s);
    cudaStreamDestroy(s_r);
    cudaStreamDestroy(s_s);
}

// round 17
// speedup vs baseline: 1.2956x; 1.0335x over previous
#include <cuda_runtime.h>
#include <cuda_bf16.h>
#include <math.h>

#define TT    2048   // tokens (B*S)
#define DD    1024   // model dim
#define HH    16     // heads
#define HDIM  64     // head dim
#define NEXP  16     // experts
#define TOPK  2
#define EDIM  512    // expert dim
#define DSH   2048   // shared expert dim
#define QKV3  3072

// ---------------- scratch (device globals; no allocations) ----------------
constexpr size_t SZ_XN  = (size_t)TT * DD;
constexpr size_t OFF_XN  = 0;
constexpr size_t OFF_QKV = OFF_XN  + SZ_XN;
constexpr size_t OFF_AO  = OFF_QKV + (size_t)TT * QKV3;
constexpr size_t OFF_XFI = OFF_AO  + SZ_XN;
constexpr size_t OFF_XFN = OFF_XFI + SZ_XN;
constexpr size_t OFF_SC  = OFF_XFN + SZ_XN;
constexpr size_t OFF_G   = OFF_SC  + (size_t)TT * TOPK;
constexpr size_t OFF_YP  = OFF_G   + (size_t)TT * TOPK * EDIM;
constexpr size_t OFF_GT  = OFF_YP  + (size_t)TT * TOPK * DD;
constexpr size_t OFF_YS  = OFF_GT  + (size_t)TT * DSH;
constexpr size_t OFF_PAC = OFF_YS  + SZ_XN;                    // split-K partial acc [16][HH][128][64]
constexpr size_t OFF_ML  = OFF_PAC + (size_t)16*HH*128*64;     // split-K (m,l) [16][HH][128][2]
constexpr size_t TOTF    = OFF_ML  + (size_t)16*HH*128*2;

__device__ float g_bufF[TOTF];

constexpr int IOFF_CNT  = 0;
constexpr int IOFF_OFFS = 16;
constexpr int IOFF_CUR  = 33;
constexpr int IOFF_PERM = 64;
constexpr int IOFF_SLOT = 64 + TT*TOPK;
constexpr int TOTI      = 64 + 2*TT*TOPK;
__device__ int g_bufI[TOTI];

// ---------------- tf32 mma helpers ----------------
__device__ __forceinline__ unsigned f2tf32(float x) {
    unsigned u; asm("cvt.rna.tf32.f32 %0, %1;" : "=r"(u) : "f"(x)); return u;
}
__device__ __forceinline__ void mma8(float* c, const unsigned* a, const unsigned* b) {
    asm volatile("mma.sync.aligned.m16n8k8.row.col.f32.tf32.tf32.f32 "
        "{%0,%1,%2,%3},{%4,%5,%6,%7},{%8,%9},{%0,%1,%2,%3};"
        : "+f"(c[0]), "+f"(c[1]), "+f"(c[2]), "+f"(c[3])
        : "r"(a[0]), "r"(a[1]), "r"(a[2]), "r"(a[3]), "r"(b[0]), "r"(b[1]));
}
// 16B cp.async with zero-fill when invalid
__device__ __forceinline__ void cpa16(float* dst, const float* src, bool v) {
    unsigned d = (unsigned)__cvta_generic_to_shared(dst);
    int sz = v ? 16 : 0;
    asm volatile("cp.async.cg.shared.global [%0], [%1], 16, %2;" :: "r"(d), "l"(src), "r"(sz));
}
#define CPA_COMMIT() asm volatile("cp.async.commit_group;")
#define CPA_WAIT1()  asm volatile("cp.async.wait_group 1;")
#define CPA_WAIT0()  asm volatile("cp.async.wait_group 0;")

// ---------------- rmsnorm ----------------
__global__ void rmsnorm_kernel(const float* __restrict__ x, const float* __restrict__ w,
                               float* __restrict__ o) {
    int t = blockIdx.x;
    const float* xr = x + (size_t)t * DD;
    float v[4]; float s = 0.f;
    #pragma unroll
    for (int i = 0; i < 4; i++) { v[i] = xr[threadIdx.x + i*256]; s += v[i]*v[i]; }
    __shared__ float red[8];
    #pragma unroll
    for (int off = 16; off > 0; off >>= 1) s += __shfl_xor_sync(0xffffffffu, s, off);
    if ((threadIdx.x & 31) == 0) red[threadIdx.x >> 5] = s;
    __syncthreads();
    if (threadIdx.x == 0) {
        float tot = 0.f;
        #pragma unroll
        for (int i = 0; i < 8; i++) tot += red[i];
        red[0] = tot;
    }
    __syncthreads();
    float sc = rsqrtf(red[0] / (float)DD + 1e-5f);
    #pragma unroll
    for (int i = 0; i < 4; i++) {
        int d = threadIdx.x + i*256;
        o[(size_t)t*DD + d] = v[i] * sc * w[d];
    }
}

// =============== tf32 NT GEMM: C[M,N] = A[M,K] @ B[N,K]^T (+R) ===========
// BM=128 BN=128 BK=32, 256 threads (8 warps: 2 along M x 4 along N,
// each warp computes a 64x32 tile). Register-prefetch double buffering.
// __launch_bounds__(256,2) on callers caps regs at 128 -> 2 CTAs/SM.
struct SmemNT {
    unsigned As[128][36];
    unsigned Bs[128][36];
};

__device__ __forceinline__ void gemm_nt_body(
        SmemNT& s, const float* __restrict__ A, const float* __restrict__ B,
        const float* __restrict__ R, float* __restrict__ C,
        int M, int N, int K, int row0, int col0) {
    const int tid = threadIdx.x;
    const int lane = tid & 31, w = tid >> 5;
    const int g = lane >> 2, tg = lane & 3;
    const int wm = (w & 1) * 64, wn = (w >> 1) * 32;
    const int ar = tid >> 3, ac = (tid & 7) * 4;

    const float* Ap[4]; bool va[4];
    #pragma unroll
    for (int p = 0; p < 4; p++) {
        int r = row0 + p*32 + ar;
        va[p] = r < M;
        Ap[p] = A + (size_t)(va[p] ? r : 0) * K + ac;
    }
    const float* Bp[4];
    #pragma unroll
    for (int p = 0; p < 4; p++)
        Bp[p] = B + (size_t)(col0 + p*32 + ar) * K + ac;

    #pragma unroll
    for (int p = 0; p < 4; p++) {
        float4 v = va[p] ? *(const float4*)(Ap[p]) : make_float4(0,0,0,0);
        s.As[p*32+ar][ac+0]=f2tf32(v.x); s.As[p*32+ar][ac+1]=f2tf32(v.y);
        s.As[p*32+ar][ac+2]=f2tf32(v.z); s.As[p*32+ar][ac+3]=f2tf32(v.w);
        float4 b = *(const float4*)(Bp[p]);
        s.Bs[p*32+ar][ac+0]=f2tf32(b.x); s.Bs[p*32+ar][ac+1]=f2tf32(b.y);
        s.Bs[p*32+ar][ac+2]=f2tf32(b.z); s.Bs[p*32+ar][ac+3]=f2tf32(b.w);
    }
    __syncthreads();

    float acc[4][4][4] = {};
    float4 pa[4], pb[4];
    for (int k0 = 0; k0 < K; k0 += 32) {
        bool nxt = (k0 + 32) < K;
        if (nxt) {
            #pragma unroll
            for (int p = 0; p < 4; p++) {
                pa[p] = va[p] ? *(const float4*)(Ap[p] + k0 + 32) : make_float4(0,0,0,0);
                pb[p] = *(const float4*)(Bp[p] + k0 + 32);
            }
        }
        #pragma unroll
        for (int ks = 0; ks < 4; ks++) {
            const int kb = ks*8;
            unsigned af[4][4], bf[4][2];
            #pragma unroll
            for (int i = 0; i < 4; i++) {
                af[i][0] = s.As[wm+i*16+g  ][kb+tg];
                af[i][1] = s.As[wm+i*16+8+g][kb+tg];
                af[i][2] = s.As[wm+i*16+g  ][kb+tg+4];
                af[i][3] = s.As[wm+i*16+8+g][kb+tg+4];
            }
            #pragma unroll
            for (int j = 0; j < 4; j++) {
                bf[j][0] = s.Bs[wn+j*8+g][kb+tg];
                bf[j][1] = s.Bs[wn+j*8+g][kb+tg+4];
            }
            #pragma unroll
            for (int i = 0; i < 4; i++)
                #pragma unroll
                for (int j = 0; j < 4; j++)
                    mma8(acc[i][j], af[i], bf[j]);
        }
        __syncthreads();
        if (nxt) {
            #pragma unroll
            for (int p = 0; p < 4; p++) {
                s.As[p*32+ar][ac+0]=f2tf32(pa[p].x); s.As[p*32+ar][ac+1]=f2tf32(pa[p].y);
                s.As[p*32+ar][ac+2]=f2tf32(pa[p].z); s.As[p*32+ar][ac+3]=f2tf32(pa[p].w);
                s.Bs[p*32+ar][ac+0]=f2tf32(pb[p].x); s.Bs[p*32+ar][ac+1]=f2tf32(pb[p].y);
                s.Bs[p*32+ar][ac+2]=f2tf32(pb[p].z); s.Bs[p*32+ar][ac+3]=f2tf32(pb[p].w);
            }
            __syncthreads();
        }
    }

    #pragma unroll
    for (int i = 0; i < 4; i++) {
        #pragma unroll
        for (int j = 0; j < 4; j++) {
            int r0 = row0 + wm + i*16 + g;
            int cc = col0 + wn + j*8 + tg*2;
            if (r0 < M) {
                size_t x = (size_t)r0*N + cc;
                float v0 = acc[i][j][0], v1 = acc[i][j][1];
                if (R) { v0 += R[x]; v1 += R[x+1]; }
                C[x] = v0; C[x+1] = v1;
            }
            int r1 = r0 + 8;
            if (r1 < M) {
                size_t x = (size_t)r1*N + cc;
                float v2 = acc[i][j][2], v3 = acc[i][j][3];
                if (R) { v2 += R[x]; v3 += R[x+1]; }
                C[x] = v2; C[x+1] = v3;
            }
        }
    }
}

__global__ __launch_bounds__(256, 2) void gemm_tf32_nt(
        const float* __restrict__ A, const float* __restrict__ B,
        const float* __restrict__ R, float* __restrict__ C, int M, int N, int K) {
    __shared__ SmemNT s;
    gemm_nt_body(s, A, B, R, C, M, N, K, blockIdx.y * 128, blockIdx.x * 128);
}

// =============== shared expert up + SiLU gate (dual-B tf32 NT) ============
__global__ __launch_bounds__(256, 2) void shared_up_gate_tf32(
        const float* __restrict__ A, const float* __restrict__ B,
        float* __restrict__ gt) {
    __shared__ unsigned As[128][36];
    __shared__ unsigned B1s[64][36];
    __shared__ unsigned B2s[64][36];
    const int row0 = blockIdx.y * 128, col0 = blockIdx.x * 64;
    const int tid = threadIdx.x;
    const int lane = tid & 31, w = tid >> 5;
    const int g = lane >> 2, tg = lane & 3;
    const int wm = (w & 3) * 32, wn = (w >> 2) * 32;
    const int ar = tid >> 3, ac = (tid & 7) * 4;

    const float* Ap[4];
    #pragma unroll
    for (int p = 0; p < 4; p++)
        Ap[p] = A + (size_t)(row0 + p*32 + ar) * DD + ac;
    const float* B1p[2]; const float* B2p[2];
    #pragma unroll
    for (int p = 0; p < 2; p++) {
        B1p[p] = B + (size_t)(col0 + p*32 + ar) * DD + ac;
        B2p[p] = B + (size_t)(DSH + col0 + p*32 + ar) * DD + ac;
    }

    #pragma unroll
    for (int p = 0; p < 4; p++) {
        float4 v = *(const float4*)(Ap[p]);
        As[p*32+ar][ac+0]=f2tf32(v.x); As[p*32+ar][ac+1]=f2tf32(v.y);
        As[p*32+ar][ac+2]=f2tf32(v.z); As[p*32+ar][ac+3]=f2tf32(v.w);
    }
    #pragma unroll
    for (int p = 0; p < 2; p++) {
        float4 v1 = *(const float4*)(B1p[p]);
        float4 v2 = *(const float4*)(B2p[p]);
        B1s[p*32+ar][ac+0]=f2tf32(v1.x); B1s[p*32+ar][ac+1]=f2tf32(v1.y);
        B1s[p*32+ar][ac+2]=f2tf32(v1.z); B1s[p*32+ar][ac+3]=f2tf32(v1.w);
        B2s[p*32+ar][ac+0]=f2tf32(v2.x); B2s[p*32+ar][ac+1]=f2tf32(v2.y);
        B2s[p*32+ar][ac+2]=f2tf32(v2.z); B2s[p*32+ar][ac+3]=f2tf32(v2.w);
    }
    __syncthreads();

    float acc1[2][4][4] = {}, acc2[2][4][4] = {};
    float4 pa[4], pb1[2], pb2[2];
    for (int k0 = 0; k0 < DD; k0 += 32) {
        bool nxt = (k0 + 32) < DD;
        if (nxt) {
            #pragma unroll
            for (int p = 0; p < 4; p++) pa[p] = *(const float4*)(Ap[p] + k0 + 32);
            #pragma unroll
            for (int p = 0; p < 2; p++) {
                pb1[p] = *(const float4*)(B1p[p] + k0 + 32);
                pb2[p] = *(const float4*)(B2p[p] + k0 + 32);
            }
        }
        #pragma unroll
        for (int ks = 0; ks < 4; ks++) {
            const int kb = ks*8;
            unsigned af[2][4], bf1[4][2], bf2[4][2];
            #pragma unroll
            for (int i = 0; i < 2; i++) {
                af[i][0] = As[wm+i*16+g  ][kb+tg];
                af[i][1] = As[wm+i*16+8+g][kb+tg];
                af[i][2] = As[wm+i*16+g  ][kb+tg+4];
                af[i][3] = As[wm+i*16+8+g][kb+tg+4];
            }
            #pragma unroll
            for (int j = 0; j < 4; j++) {
                bf1[j][0] = B1s[wn+j*8+g][kb+tg];
                bf1[j][1] = B1s[wn+j*8+g][kb+tg+4];
                bf2[j][0] = B2s[wn+j*8+g][kb+tg];
                bf2[j][1] = B2s[wn+j*8+g][kb+tg+4];
            }
            #pragma unroll
            for (int i = 0; i < 2; i++)
                #pragma unroll
                for (int j = 0; j < 4; j++) {
                    mma8(acc1[i][j], af[i], bf1[j]);
                    mma8(acc2[i][j], af[i], bf2[j]);
                }
        }
        __syncthreads();
        if (nxt) {
            #pragma unroll
            for (int p = 0; p < 4; p++) {
                As[p*32+ar][ac+0]=f2tf32(pa[p].x); As[p*32+ar][ac+1]=f2tf32(pa[p].y);
                As[p*32+ar][ac+2]=f2tf32(pa[p].z); As[p*32+ar][ac+3]=f2tf32(pa[p].w);
            }
            #pragma unroll
            for (int p = 0; p < 2; p++) {
                B1s[p*32+ar][ac+0]=f2tf32(pb1[p].x); B1s[p*32+ar][ac+1]=f2tf32(pb1[p].y);
                B1s[p*32+ar][ac+2]=f2tf32(pb1[p].z); B1s[p*32+ar][ac+3]=f2tf32(pb1[p].w);
                B2s[p*32+ar][ac+0]=f2tf32(pb2[p].x); B2s[p*32+ar][ac+1]=f2tf32(pb2[p].y);
                B2s[p*32+ar][ac+2]=f2tf32(pb2[p].z); B2s[p*32+ar][ac+3]=f2tf32(pb2[p].w);
            }
            __syncthreads();
        }
    }

    #pragma unroll
    for (int i = 0; i < 2; i++) {
        #pragma unroll
        for (int j = 0; j < 4; j++) {
            int r0 = row0 + wm + i*16 + g;
            int cc = col0 + wn + j*8 + tg*2;
            #pragma unroll
            for (int half = 0; half < 2; half++) {
                int r = r0 + half*8;
                float h1a = acc1[i][j][half*2+0], h2a = acc2[i][j][half*2+0];
                float h1b = acc1[i][j][half*2+1], h2b = acc2[i][j][half*2+1];
                float sa = 1.f / (1.f + __expf(-h1a));
                float sb = 1.f / (1.f + __expf(-h1b));
                size_t x = (size_t)r * DSH + cc;
                gt[x]   = h1a * sa * h2a;
                gt[x+1] = h1b * sb * h2b;
            }
        }
    }
}

// ---------------- RoPE (in-place on q,k within qkv buffer) ----------------
__global__ void rope_kernel(float* __restrict__ qkv) {
    int idx = blockIdx.x * blockDim.x + threadIdx.x;
    const int total = 2 * TT * HH * 32;
    if (idx >= total) return;
    int which = idx / (TT * HH * 32);
    int rem   = idx % (TT * HH * 32);
    int t = rem / (HH * 32);
    int r2 = rem % (HH * 32);
    int h = r2 >> 5, i = r2 & 31;
    size_t base = (size_t)t * QKV3 + (size_t)which * DD + h * HDIM;
    float invf = (float)exp(-9.210340371976184 * ((double)i / 32.0));
    float fr = (float)t * invf;
    float c = (float)cos((double)fr);
    float s = (float)sin((double)fr);
    float x1 = qkv[base + i];
    float x2 = qkv[base + 32 + i];
    qkv[base + i]      =  x1 * c + x2 * s;
    qkv[base + 32 + i] = -x1 * s + x2 * c;
}

// =============== flash attention v5: split-K heavy blocks ================
#define KSTR 68
#define VSTR 72
constexpr int ATTN_STAGE = 64*KSTR + 64*VSTR;
constexpr int ATTN_SMEM  = 2 * ATTN_STAGE * (int)sizeof(float);  // 71680 B

// {qb, kb0, kb1, su}; su = -1 unsplit, else (qb-8)*2+half. Sorted heavy-first.
__device__ __constant__ int4 c_units[24] = {
    {15,  0, 15, 14}, {15, 16, 31, 15}, { 7,  0, 15, -1},
    {14,  0, 14, 12}, {14, 15, 29, 13}, {13,  0, 13, 10},
    {13, 14, 27, 11}, { 6,  0, 13, -1}, {12,  0, 12,  8},
    {12, 13, 25,  9}, {11,  0, 11,  6}, {11, 12, 23,  7},
    { 5,  0, 11, -1}, {10,  0, 10,  4}, {10, 11, 21,  5},
    { 9,  0,  9,  2}, { 9, 10, 19,  3}, { 4,  0,  9, -1},
    { 8,  0,  8,  0}, { 8,  9, 17,  1}, { 3,  0,  7, -1},
    { 2,  0,  5, -1}, { 1,  0,  3, -1}, { 0,  0,  1, -1}
};

__global__ __launch_bounds__(256, 2) void attn_kernel(const float* __restrict__ qkv,
                                                      float* __restrict__ o,
                                                      float* __restrict__ pacc,
                                                      float* __restrict__ pml) {
    extern __shared__ float smf[];

    const int4 u = c_units[blockIdx.y];
    const int qb = u.x, kb0 = u.y, kb1 = u.z, su = u.w;
    const int h = blockIdx.x;
    const int tid = threadIdx.x;
    const int lane = tid & 31, w = tid >> 5;
    const int g = lane >> 2, tg = lane & 3;
    const bool odd = tg & 1;
    const int s0 = tg >> 1, s1 = 2 + (tg >> 1);

    { // stage Q tile [128][64] raw fp32
        int qi = tid >> 1, d0 = (tid & 1) * 32;
        const float* src = qkv + (size_t)(qb*128 + qi) * QKV3 + h * HDIM + d0;
        #pragma unroll
        for (int c = 0; c < 32; c += 4) {
            float4 v = *(const float4*)(src + c);
            smf[qi*KSTR + d0+c+0] = v.x; smf[qi*KSTR + d0+c+1] = v.y;
            smf[qi*KSTR + d0+c+2] = v.z; smf[qi*KSTR + d0+c+3] = v.w;
        }
    }
    __syncthreads();
    unsigned aq[8][4];
    {
        int r0 = 16*w + g;
        #pragma unroll
        for (int kk = 0; kk < 8; kk++) {
            aq[kk][0] = f2tf32(smf[(r0  )*KSTR + 8*kk + tg]);
            aq[kk][1] = f2tf32(smf[(r0+8)*KSTR + 8*kk + tg]);
            aq[kk][2] = f2tf32(smf[(r0  )*KSTR + 8*kk + tg + 4]);
            aq[kk][3] = f2tf32(smf[(r0+8)*KSTR + 8*kk + tg + 4]);
        }
    }
    __syncthreads();

    const int lki = tid >> 2, ld0 = (tid & 3) * 16;

    { // preload stage 0 (kb = kb0)
        float* Ks = smf;
        float* Vs = smf + 64*KSTR;
        const float* kp = qkv + (size_t)(kb0*64 + lki) * QKV3 + DD   + h*HDIM + ld0;
        const float* vp = qkv + (size_t)(kb0*64 + lki) * QKV3 + 2*DD + h*HDIM + ld0;
        #pragma unroll
        for (int c = 0; c < 16; c += 4) {
            cpa16(Ks + lki*KSTR + ld0 + c, kp + c, true);
            cpa16(Vs + lki*VSTR + ld0 + c, vp + c, true);
        }
        CPA_COMMIT();
    }

    float m0 = -INFINITY, m1 = -INFINITY, l0 = 0.f, l1 = 0.f;
    float acco[8][4] = {};
    const int qg0 = qb*128 + 16*w + g;
    const int qg1 = qg0 + 8;

    for (int kb = kb0; kb <= kb1; kb++) {
        const int st = (kb - kb0) & 1;
        const float* Ks = smf + st * ATTN_STAGE;
        const float* Vs = Ks + 64*KSTR;
        if (kb < kb1) {
            float* Kn = smf + (st^1) * ATTN_STAGE;
            float* Vn = Kn + 64*KSTR;
            const float* kp = qkv + (size_t)((kb+1)*64 + lki) * QKV3 + DD   + h*HDIM + ld0;
            const float* vp = qkv + (size_t)((kb+1)*64 + lki) * QKV3 + 2*DD + h*HDIM + ld0;
            #pragma unroll
            for (int c = 0; c < 16; c += 4) {
                cpa16(Kn + lki*KSTR + ld0 + c, kp + c, true);
                cpa16(Vn + lki*VSTR + ld0 + c, vp + c, true);
            }
            CPA_COMMIT();
            CPA_WAIT1();
        } else {
            CPA_WAIT0();
        }
        __syncthreads();

        // S = Q @ K^T
        float sf[8][4] = {};
        #pragma unroll
        for (int kk = 0; kk < 8; kk++) {
            #pragma unroll
            for (int j = 0; j < 8; j++) {
                unsigned b[2] = { __float_as_uint(Ks[(8*j+g)*KSTR + 8*kk + tg]),
                                  __float_as_uint(Ks[(8*j+g)*KSTR + 8*kk + tg + 4]) };
                mma8(sf[j], aq[kk], b);
            }
        }
        // scale + causal mask + register softmax
        float vmax0 = -1e30f, vmax1 = -1e30f;
        #pragma unroll
        for (int j = 0; j < 8; j++) {
            int kg = kb*64 + 8*j + 2*tg;
            sf[j][0] = (kg   > qg0) ? -1e30f : sf[j][0]*0.125f;
            sf[j][1] = (kg+1 > qg0) ? -1e30f : sf[j][1]*0.125f;
            sf[j][2] = (kg   > qg1) ? -1e30f : sf[j][2]*0.125f;
            sf[j][3] = (kg+1 > qg1) ? -1e30f : sf[j][3]*0.125f;
            vmax0 = fmaxf(vmax0, fmaxf(sf[j][0], sf[j][1]));
            vmax1 = fmaxf(vmax1, fmaxf(sf[j][2], sf[j][3]));
        }
        vmax0 = fmaxf(vmax0, __shfl_xor_sync(0xffffffffu, vmax0, 1));
        vmax0 = fmaxf(vmax0, __shfl_xor_sync(0xffffffffu, vmax0, 2));
        vmax1 = fmaxf(vmax1, __shfl_xor_sync(0xffffffffu, vmax1, 1));
        vmax1 = fmaxf(vmax1, __shfl_xor_sync(0xffffffffu, vmax1, 2));
        float mn0 = fmaxf(m0, vmax0), mn1 = fmaxf(m1, vmax1);
        float al0 = __expf(m0 - mn0), al1 = __expf(m1 - mn1);
        float ps0 = 0.f, ps1 = 0.f;
        #pragma unroll
        for (int j = 0; j < 8; j++) {
            sf[j][0] = __expf(sf[j][0] - mn0); ps0 += sf[j][0];
            sf[j][1] = __expf(sf[j][1] - mn0); ps0 += sf[j][1];
            sf[j][2] = __expf(sf[j][2] - mn1); ps1 += sf[j][2];
            sf[j][3] = __expf(sf[j][3] - mn1); ps1 += sf[j][3];
        }
        ps0 += __shfl_xor_sync(0xffffffffu, ps0, 1);
        ps0 += __shfl_xor_sync(0xffffffffu, ps0, 2);
        ps1 += __shfl_xor_sync(0xffffffffu, ps1, 1);
        ps1 += __shfl_xor_sync(0xffffffffu, ps1, 2);
        l0 = l0*al0 + ps0; l1 = l1*al1 + ps1;
        m0 = mn0; m1 = mn1;
        #pragma unroll
        for (int jd = 0; jd < 8; jd++) {
            acco[jd][0] *= al0; acco[jd][1] *= al0;
            acco[jd][2] *= al1; acco[jd][3] *= al1;
        }
        // O += P @ V
        #pragma unroll
        for (int j = 0; j < 8; j++) {
            float q00 = __shfl_sync(0xffffffffu, sf[j][0], s0, 4);
            float q01 = __shfl_sync(0xffffffffu, sf[j][1], s0, 4);
            float q10 = __shfl_sync(0xffffffffu, sf[j][2], s0, 4);
            float q11 = __shfl_sync(0xffffffffu, sf[j][3], s0, 4);
            float r00 = __shfl_sync(0xffffffffu, sf[j][0], s1, 4);
            float r01 = __shfl_sync(0xffffffffu, sf[j][1], s1, 4);
            float r10 = __shfl_sync(0xffffffffu, sf[j][2], s1, 4);
            float r11 = __shfl_sync(0xffffffffu, sf[j][3], s1, 4);
            unsigned a[4];
            a[0] = f2tf32(odd ? q01 : q00);
            a[1] = f2tf32(odd ? q11 : q10);
            a[2] = f2tf32(odd ? r01 : r00);
            a[3] = f2tf32(odd ? r11 : r10);
            #pragma unroll
            for (int jd = 0; jd < 8; jd++) {
                unsigned b[2] = { __float_as_uint(Vs[(8*j+tg  )*VSTR + 8*jd + g]),
                                  __float_as_uint(Vs[(8*j+tg+4)*VSTR + 8*jd + g]) };
                mma8(acco[jd], a, b);
            }
        }
        __syncthreads();
    }

    if (su < 0) { // unsplit: normalize and write
        float i0 = 1.f / l0, i1 = 1.f / l1;
        #pragma unroll
        for (int jd = 0; jd < 8; jd++) {
            int col = h*HDIM + 8*jd + 2*tg;
            o[(size_t)qg0*DD + col  ] = acco[jd][0]*i0;
            o[(size_t)qg0*DD + col+1] = acco[jd][1]*i0;
            o[(size_t)qg1*DD + col  ] = acco[jd][2]*i1;
            o[(size_t)qg1*DD + col+1] = acco[jd][3]*i1;
        }
    } else { // split half: write unnormalized acc + (m,l)
        float* pa = pacc + ((size_t)su*HH + h) * 128 * 64;
        int r0 = 16*w + g, r1 = r0 + 8;
        #pragma unroll
        for (int jd = 0; jd < 8; jd++) {
            int col = 8*jd + 2*tg;
            pa[(size_t)r0*64 + col  ] = acco[jd][0];
            pa[(size_t)r0*64 + col+1] = acco[jd][1];
            pa[(size_t)r1*64 + col  ] = acco[jd][2];
            pa[(size_t)r1*64 + col+1] = acco[jd][3];
        }
        if (tg == 0) {
            float* ml = pml + ((size_t)su*HH + h) * 128 * 2;
            ml[r0*2+0] = m0; ml[r0*2+1] = l0;
            ml[r1*2+0] = m1; ml[r1*2+1] = l1;
        }
    }
}

// merge split halves: o = (eA*accA + eB*accB) / (eA*lA + eB*lB)
__global__ void attn_merge(const float* __restrict__ pacc, const float* __restrict__ pml,
                           float* __restrict__ o) {
    const int sp = blockIdx.x;          // 0..7 -> qb = 8+sp
    const int h  = blockIdx.y;
    const int suA = sp*2, suB = suA+1;
    const int qb = 8 + sp;
    const int r  = threadIdx.x >> 1;    // 0..127
    const int c0 = (threadIdx.x & 1) * 32;
    const float* mlA = pml + ((size_t)suA*HH + h) * 128 * 2;
    const float* mlB = pml + ((size_t)suB*HH + h) * 128 * 2;
    float mA = mlA[r*2+0], lA = mlA[r*2+1];
    float mB = mlB[r*2+0], lB = mlB[r*2+1];
    float mm = fmaxf(mA, mB);
    float eA = __expf(mA - mm), eB = __expf(mB - mm);
    float inv = 1.f / (eA*lA + eB*lB);
    const float* pA = pacc + ((size_t)suA*HH + h) * 128 * 64 + (size_t)r * 64;
    const float* pB = pacc + ((size_t)suB*HH + h) * 128 * 64 + (size_t)r * 64;
    float* orow = o + (size_t)(qb*128 + r) * DD + h * HDIM;
    #pragma unroll
    for (int c = 0; c < 32; c += 4) {
        float4 a = *(const float4*)(pA + c0 + c);
        float4 b = *(const float4*)(pB + c0 + c);
        float4 v;
        v.x = (eA*a.x + eB*b.x) * inv;
        v.y = (eA*a.y + eB*b.y) * inv;
        v.z = (eA*a.z + eB*b.z) * inv;
        v.w = (eA*a.w + eB*b.w) * inv;
        *(float4*)(orow + c0 + c) = v;
    }
}

// ---------------- router ----------------
__global__ void router_kernel(const float* __restrict__ xffn, const float* __restrict__ mk,
                              const float* __restrict__ bias, const int* __restrict__ indices,
                              const float* __restrict__ values, float* __restrict__ scores) {
    int t = blockIdx.x;
    __shared__ float red[128 * NEXP];
    float partial[NEXP];
    #pragma unroll
    for (int e = 0; e < NEXP; e++) partial[e] = 0.f;
    for (int d = threadIdx.x; d < DD; d += 128) {
        float xv = xffn[(size_t)t*DD + d];
        const float* mrow = mk + (size_t)d * NEXP;
        #pragma unroll
        for (int e = 0; e < NEXP; e++) partial[e] += xv * mrow[e];
    }
    #pragma unroll
    for (int e = 0; e < NEXP; e++) red[threadIdx.x*NEXP + e] = partial[e];
    __syncthreads();
    for (int s = 64; s >= 1; s >>= 1) {
        if (threadIdx.x < s)
            #pragma unroll
            for (int e = 0; e < NEXP; e++)
                red[threadIdx.x*NEXP + e] += red[(threadIdx.x+s)*NEXP + e];
        __syncthreads();
    }
    if (threadIdx.x == 0) {
        int i0 = indices[t*2+0], i1 = indices[t*2+1];
        float v0 = values[t*2+0] + red[i0] + bias[i0];
        float v1 = values[t*2+1] + red[i1] + bias[i1];
        float m = fmaxf(v0, v1);
        float e0 = __expf(v0 - m), e1 = __expf(v1 - m);
        float inv = 1.f / (e0 + e1);
        scores[t*2+0] = e0 * inv;
        scores[t*2+1] = e1 * inv;
    }
}

// ---------------- routing build ----------------
__global__ void route_init(int* counts) { if (threadIdx.x < NEXP) counts[threadIdx.x] = 0; }
__global__ void route_count(const int* __restrict__ indices, int* counts) {
    int i = blockIdx.x * blockDim.x + threadIdx.x;
    if (i < TT*TOPK) atomicAdd(&counts[indices[i]], 1);
}
__global__ void route_scan(const int* __restrict__ counts, int* offsets, int* cursor) {
    if (threadIdx.x == 0) {
        int off = 0;
        for (int e = 0; e < NEXP; e++) { offsets[e] = off; cursor[e] = off; off += counts[e]; }
        offsets[NEXP] = off;
    }
}
__global__ void route_scatter(const int* __restrict__ indices, int* cursor,
                              int* __restrict__ perm, int* __restrict__ slotpos) {
    int i = blockIdx.x * blockDim.x + threadIdx.x;
    if (i < TT*TOPK) {
        int e = indices[i];
        int p = atomicAdd(&cursor[e], 1);
        perm[p] = i >> 1;
        slotpos[i] = p;
    }
}

// =============== expert up (tf32): g = silu(x@W1) * (x@W2), gathered A ====
__global__ __launch_bounds__(256, 2) void expert_up_tf32(
        const float* __restrict__ xffn, const float* __restrict__ experts,
        const int* __restrict__ counts, const int* __restrict__ offsets,
        const int* __restrict__ perm, float* __restrict__ g_out) {
    const int e = blockIdx.z;
    const int M = counts[e];
    const int row0 = blockIdx.y * 64;
    if (row0 >= M) return;
    const int off = offsets[e];
    const float* B1 = experts + (size_t)e * DD * EDIM;
    const float* B2 = experts + ((size_t)NEXP + e) * DD * EDIM;
    const int col0 = blockIdx.x * 64;

    __shared__ unsigned As[64][36];
    __shared__ unsigned B1s[32][72];
    __shared__ unsigned B2s[32][72];

    const int tid = threadIdx.x;
    const int lane = tid & 31, w = tid >> 5;
    const int g = lane >> 2, tg = lane & 3;
    const int wm = (w & 1) * 32, wn = (w >> 1) * 16;
    const int ar = tid >> 3, ac = (tid & 7) * 4;
    const int bkr = tid >> 4, bnc = (tid & 15) * 4;

    const float* Ap[2]; bool va[2];
    #pragma unroll
    for (int p = 0; p < 2; p++) {
        int r = row0 + p*32 + ar;
        va[p] = r < M;
        int tok = va[p] ? perm[off + r] : 0;
        Ap[p] = xffn + (size_t)tok * DD + ac;
    }
    const float* B1p[2]; const float* B2p[2];
    #pragma unroll
    for (int p = 0; p < 2; p++) {
        B1p[p] = B1 + (size_t)(p*16 + bkr) * EDIM + col0 + bnc;
        B2p[p] = B2 + (size_t)(p*16 + bkr) * EDIM + col0 + bnc;
    }

    #pragma unroll
    for (int p = 0; p < 2; p++) {
        float4 v = va[p] ? *(const float4*)(Ap[p]) : make_float4(0,0,0,0);
        As[p*32+ar][ac+0]=f2tf32(v.x); As[p*32+ar][ac+1]=f2tf32(v.y);
        As[p*32+ar][ac+2]=f2tf32(v.z); As[p*32+ar][ac+3]=f2tf32(v.w);
    }
    #pragma unroll
    for (int p = 0; p < 2; p++) {
        float4 v1 = *(const float4*)(B1p[p]);
        float4 v2 = *(const float4*)(B2p[p]);
        B1s[p*16+bkr][bnc+0]=f2tf32(v1.x); B1s[p*16+bkr][bnc+1]=f2tf32(v1.y);
        B1s[p*16+bkr][bnc+2]=f2tf32(v1.z); B1s[p*16+bkr][bnc+3]=f2tf32(v1.w);
        B2s[p*16+bkr][bnc+0]=f2tf32(v2.x); B2s[p*16+bkr][bnc+1]=f2tf32(v2.y);
        B2s[p*16+bkr][bnc+2]=f2tf32(v2.z); B2s[p*16+bkr][bnc+3]=f2tf32(v2.w);
    }
    __syncthreads();

    float acc1[2][2][4] = {}, acc2[2][2][4] = {};
    float4 pa[2], pb1[2], pb2[2];
    for (int k0 = 0; k0 < DD; k0 += 32) {
        bool nxt = (k0 + 32) < DD;
        if (nxt) {
            #pragma unroll
            for (int p = 0; p < 2; p++)
                pa[p] = va[p] ? *(const float4*)(Ap[p] + k0 + 32) : make_float4(0,0,0,0);
            #pragma unroll
            for (int p = 0; p < 2; p++) {
                pb1[p] = *(const float4*)(B1p[p] + (size_t)(k0 + 32) * EDIM);
                pb2[p] = *(const float4*)(B2p[p] + (size_t)(k0 + 32) * EDIM);
            }
        }
        #pragma unroll
        for (int ks = 0; ks < 4; ks++) {
            const int kb = ks*8;
            unsigned af[2][4], bf1[2][2], bf2[2][2];
            #pragma unroll
            for (int i = 0; i < 2; i++) {
                af[i][0] = As[wm+i*16+g  ][kb+tg];
                af[i][1] = As[wm+i*16+8+g][kb+tg];
                af[i][2] = As[wm+i*16+g  ][kb+tg+4];
                af[i][3] = As[wm+i*16+8+g][kb+tg+4];
            }
            #pragma unroll
            for (int j = 0; j < 2; j++) {
                bf1[j][0] = B1s[kb+tg  ][wn+j*8+g];
                bf1[j][1] = B1s[kb+tg+4][wn+j*8+g];
                bf2[j][0] = B2s[kb+tg  ][wn+j*8+g];
                bf2[j][1] = B2s[kb+tg+4][wn+j*8+g];
            }
            #pragma unroll
            for (int i = 0; i < 2; i++)
                #pragma unroll
                for (int j = 0; j < 2; j++) {
                    mma8(acc1[i][j], af[i], bf1[j]);
                    mma8(acc2[i][j], af[i], bf2[j]);
                }
        }
        __syncthreads();
        if (nxt) {
            #pragma unroll
            for (int p = 0; p < 2; p++) {
                As[p*32+ar][ac+0]=f2tf32(pa[p].x); As[p*32+ar][ac+1]=f2tf32(pa[p].y);
                As[p*32+ar][ac+2]=f2tf32(pa[p].z); As[p*32+ar][ac+3]=f2tf32(pa[p].w);
            }
            #pragma unroll
            for (int p = 0; p < 2; p++) {
                B1s[p*16+bkr][bnc+0]=f2tf32(pb1[p].x); B1s[p*16+bkr][bnc+1]=f2tf32(pb1[p].y);
                B1s[p*16+bkr][bnc+2]=f2tf32(pb1[p].z); B1s[p*16+bkr][bnc+3]=f2tf32(pb1[p].w);
                B2s[p*16+bkr][bnc+0]=f2tf32(pb2[p].x); B2s[p*16+bkr][bnc+1]=f2tf32(pb2[p].y);
                B2s[p*16+bkr][bnc+2]=f2tf32(pb2[p].z); B2s[p*16+bkr][bnc+3]=f2tf32(pb2[p].w);
            }
            __syncthreads();
        }
    }

    #pragma unroll
    for (int i = 0; i < 2; i++) {
        #pragma unroll
        for (int j = 0; j < 2; j++) {
            int r0 = row0 + wm + i*16 + g;
            int cc = col0 + wn + j*8 + tg*2;
            #pragma unroll
            for (int half = 0; half < 2; half++) {
                int r = r0 + half*8;
                if (r < M) {
                    float h1a = acc1[i][j][half*2+0], h2a = acc2[i][j][half*2+0];
                    float h1b = acc1[i][j][half*2+1], h2b = acc2[i][j][half*2+1];
                    float sa = 1.f / (1.f + __expf(-h1a));
                    float sb = 1.f / (1.f + __expf(-h1b));
                    size_t x = (size_t)(off + r) * EDIM + cc;
                    g_out[x]   = h1a * sa * h2a;
                    g_out[x+1] = h1b * sb * h2b;
                }
            }
        }
    }
}

// =============== expert down (tf32 NT): yp = g @ W3^T, per-expert slabs ===
__global__ __launch_bounds__(256, 2) void expert_down_tf32(
        const float* __restrict__ gbuf, const float* __restrict__ experts,
        const int* __restrict__ counts, const int* __restrict__ offsets,
        float* __restrict__ yp) {
    const int e = blockIdx.z;
    const int M = counts[e];
    const int row0 = blockIdx.y * 128;
    if (row0 >= M) return;
    const int off = offsets[e];
    __shared__ SmemNT s;
    gemm_nt_body(s,
                 gbuf + (size_t)off * EDIM,
                 experts + (2*(size_t)NEXP + e) * DD * EDIM,
                 nullptr,
                 yp + (size_t)off * DD,
                 M, DD, EDIM, row0, blockIdx.x * 128);
}

// ---- final: out = (s0*yp[p0]+s1*yp[p1])*coeff + rmsnorm(ysh)*w + xfi ----
__global__ void final_kernel(const float* __restrict__ yp, const float* __restrict__ scores,
                             const int* __restrict__ slotpos, const float* __restrict__ coeff,
                             const float* __restrict__ ysh, const float* __restrict__ shw,
                             const float* __restrict__ xfi, float* __restrict__ out) {
    int t = blockIdx.x;
    const float* yr = ysh + (size_t)t * DD;
    float v[4]; float s = 0.f;
    #pragma unroll
    for (int i = 0; i < 4; i++) { v[i] = yr[threadIdx.x + i*256]; s += v[i]*v[i]; }
    __shared__ float red[8];
    #pragma unroll
    for (int off = 16; off > 0; off >>= 1) s += __shfl_xor_sync(0xffffffffu, s, off);
    if ((threadIdx.x & 31) == 0) red[threadIdx.x >> 5] = s;
    __syncthreads();
    if (threadIdx.x == 0) {
        float tot = 0.f;
        #pragma unroll
        for (int i = 0; i < 8; i++) tot += red[i];
        red[0] = tot;
    }
    __syncthreads();
    float sc = rsqrtf(red[0] / (float)DD + 1e-5f);
    float s0 = scores[t*2+0], s1 = scores[t*2+1];
    int p0 = slotpos[t*2+0], p1 = slotpos[t*2+1];
    const float* r0 = yp + (size_t)p0 * DD;
    const float* r1 = yp + (size_t)p1 * DD;
    #pragma unroll
    for (int i = 0; i < 4; i++) {
        int d = threadIdx.x + i*256;
        size_t idx = (size_t)t*DD + d;
        out[idx] = (s0*r0[d] + s1*r1[d]) * coeff[d] + v[i]*sc*shw[d] + xfi[idx];
    }
}

// ---------------- launch ----------------
extern "C" void kernel_launch(void* const* d_in, const int* in_sizes, int n_in,
                              void* d_out, int out_size) {
    const float* x_input     = (const float*)d_in[0];
    const int*   indices     = (const int*)  d_in[1];
    const float* values      = (const float*)d_in[2];
    const float* attn_w      = (const float*)d_in[3];
    const float* attn_o_w    = (const float*)d_in[4];
    const float* attn_norm_w = (const float*)d_in[5];
    const float* ffn_norm_w  = (const float*)d_in[6];
    const float* ffn_experts = (const float*)d_in[7];
    const float* main_keys   = (const float*)d_in[8];
    const float* main_bias   = (const float*)d_in[9];
    const float* out_coeff   = (const float*)d_in[10];
    const float* ffn_up_w    = (const float*)d_in[11];
    const float* ffn_down_w  = (const float*)d_in[12];
    const float* shared_nw   = (const float*)d_in[13];
    float* out = (float*)d_out;

    float* bufF = nullptr; int* bufI = nullptr;
    cudaGetSymbolAddress((void**)&bufF, g_bufF);
    cudaGetSymbolAddress((void**)&bufI, g_bufI);

    float* xn   = bufF + OFF_XN;
    float* qkv  = bufF + OFF_QKV;
    float* ao   = bufF + OFF_AO;
    float* xfi  = bufF + OFF_XFI;
    float* xfn  = bufF + OFF_XFN;
    float* sc   = bufF + OFF_SC;
    float* gbuf = bufF + OFF_G;
    float* yp   = bufF + OFF_YP;
    float* gt   = bufF + OFF_GT;
    float* ys   = bufF + OFF_YS;
    float* pac  = bufF + OFF_PAC;
    float* pml  = bufF + OFF_ML;

    int* cnt  = bufI + IOFF_CNT;
    int* offs = bufI + IOFF_OFFS;
    int* cur  = bufI + IOFF_CUR;
    int* perm = bufI + IOFF_PERM;
    int* slot = bufI + IOFF_SLOT;

    cudaFuncSetAttribute(attn_kernel, cudaFuncAttributeMaxDynamicSharedMemorySize, ATTN_SMEM);

    // fork/join resources — created AND destroyed within this call
    cudaStream_t s_r, s_s;
    cudaEvent_t ev_fork, ev_r, ev_s;
    cudaStreamCreateWithFlags(&s_r, cudaStreamNonBlocking);
    cudaStreamCreateWithFlags(&s_s, cudaStreamNonBlocking);
    cudaEventCreateWithFlags(&ev_fork, cudaEventDisableTiming);
    cudaEventCreateWithFlags(&ev_r,    cudaEventDisableTiming);
    cudaEventCreateWithFlags(&ev_s,    cudaEventDisableTiming);

    // ---- routing permutation build on s_r: depends only on `indices`,
    //      overlaps the whole attention prefix ----
    route_init<<<1, 32, 0, s_r>>>(cnt);
    route_count<<<(TT*TOPK + 255)/256, 256, 0, s_r>>>(indices, cnt);
    route_scan<<<1, 32, 0, s_r>>>(cnt, offs, cur);
    route_scatter<<<(TT*TOPK + 255)/256, 256, 0, s_r>>>(indices, cur, perm, slot);

    // ---- serial prefix (default stream) ----
    rmsnorm_kernel<<<TT, 256>>>(x_input, attn_norm_w, xn);
    gemm_tf32_nt<<<dim3(QKV3/128, TT/128), 256>>>(xn, attn_w, nullptr, qkv, TT, QKV3, DD);
    rope_kernel<<<(2*TT*HH*32 + 255)/256, 256>>>(qkv);
    attn_kernel<<<dim3(HH, 24), 256, ATTN_SMEM>>>(qkv, ao, pac, pml);
    attn_merge<<<dim3(8, HH), 256>>>(pac, pml, ao);
    gemm_tf32_nt<<<dim3(DD/128, TT/128), 256>>>(ao, attn_o_w, x_input, xfi, TT, DD, DD);
    rmsnorm_kernel<<<TT, 256>>>(xfi, ffn_norm_w, xfn);

    // ---- fork: routed experts (s_r) || shared expert (s_s) ----
    cudaEventRecord(ev_fork, 0);
    cudaStreamWaitEvent(s_r, ev_fork, 0);
    cudaStreamWaitEvent(s_s, ev_fork, 0);

    // routed chain on s_r (perm/cnt already built above on this stream)
    router_kernel<<<TT, 128, 0, s_r>>>(xfn, main_keys, main_bias, indices, values, sc);
    expert_up_tf32<<<dim3(EDIM/64, (TT*TOPK)/64, NEXP), 256, 0, s_r>>>(xfn, ffn_experts, cnt, offs, perm, gbuf);
    expert_down_tf32<<<dim3(DD/128, (TT*TOPK)/128, NEXP), 256, 0, s_r>>>(gbuf, ffn_experts, cnt, offs, yp);
    cudaEventRecord(ev_r, s_r);

    // shared chain on s_s
    shared_up_gate_tf32<<<dim3(DSH/64, TT/128), 256, 0, s_s>>>(xfn, ffn_up_w, gt);
    gemm_tf32_nt<<<dim3(DD/128, TT/128), 256, 0, s_s>>>(gt, ffn_down_w, nullptr, ys, TT, DD, DSH);
    cudaEventRecord(ev_s, s_s);

    // ---- join on default stream ----
    cudaStreamWaitEvent(0, ev_r, 0);
    cudaStreamWaitEvent(0, ev_s, 0);
    // fused combine + shared-norm + residual
    final_kernel<<<TT, 256>>>(yp, sc, slot, out_coeff, ys, shared_nw, xfi, out);

    // ---- release fork/join resources (side streams already joined) ----
    cudaEventDestroy(ev_fork);
    cudaEventDestroy(ev_r);
    cudaEventDestroy(ev_s);
    cudaStreamDestroy(s_r);
    cudaStreamDestroy(s_s);
}